// round 1
// baseline (speedup 1.0000x reference)
#include <cuda_runtime.h>
#include <math.h>

// Problem constants (fixed shapes for BaseEncoder_68702296867023)
#define BB 16
#define SS 512
#define EE 512
#define HH 8
#define FFD 2048
#define LL 6
#define DH 64
#define TOK (BB*SS)              // 8192 tokens
#define NZ (BB*HH)               // 128 attention batches

// ---------------------------------------------------------------------------
// Scratch (device globals; no allocations allowed)
// ---------------------------------------------------------------------------
__device__ float g_x[TOK*EE];                 // activations           16 MB
__device__ float g_qkv[TOK*3*EE];             // qkv                   48 MB
__device__ float g_scores[NZ*SS*SS];          // attention scores     134 MB
__device__ float g_biasm[NZ*SS*SS];           // rel-dist bias + mask 134 MB
__device__ float g_ctx[TOK*EE];               // attention context     16 MB
__device__ float g_ff[TOK*FFD];               // FF hidden             64 MB
__device__ float g_y[TOK*EE];                 // residual branch       16 MB

// ---------------------------------------------------------------------------
// Generic tiled fp32 GEMM
//   C[z][m,n] = alpha * sum_k A[m,k] * B(op)[k,n]  (+ bias[n]) (+ addm[m,n]) (gelu)
//   B K-major (row n contiguous in k) when BKMAJ, else N-major.
//   Batch offset for pointer P: (z/zmod)*sPo + (z%zmod)*sPi
//   EPI: 0 = bias, 1 = bias+exact gelu, 2 = alpha*acc + addm
// ---------------------------------------------------------------------------
template<int BM,int BN,int BK,int TM,int TN,bool BKMAJ,int EPI>
__global__ void __launch_bounds__((BM/TM)*(BN/TN))
gemm_k(const float* __restrict__ A, const float* __restrict__ Bm,
       const float* __restrict__ bias, const float* __restrict__ addm,
       float* __restrict__ C,
       int K, int lda, int ldb, int ldc, float alpha, int zmod,
       long long sAo, long long sAi, long long sBo, long long sBi,
       long long sCo, long long sCi, long long sDo, long long sDi)
{
    constexpr int NT = (BM/TM)*(BN/TN);
    static_assert(BM*BK == 4*NT, "A tile load count");
    static_assert(BN*BK == 4*NT, "B tile load count");

    const int tid = threadIdx.x;
    const int z   = blockIdx.z;
    const int zo  = z / zmod;
    const int zi  = z % zmod;
    A  += (long long)zo*sAo + (long long)zi*sAi;
    Bm += (long long)zo*sBo + (long long)zi*sBi;
    C  += (long long)zo*sCo + (long long)zi*sCi;
    if (EPI == 2) addm += (long long)zo*sDo + (long long)zi*sDi;

    const int m0 = blockIdx.y * BM;
    const int n0 = blockIdx.x * BN;

    __shared__ float As[BK][BM+4];
    __shared__ float Bs[BK][BN+4];

    // A tile: K-major, one float4 along K per thread
    const int aRow = tid / (BK/4);
    const int aK   = (tid % (BK/4)) * 4;
    // B tile
    int bRow, bK;
    if (BKMAJ) { bRow = tid / (BK/4); bK = (tid % (BK/4)) * 4; }   // bRow = n
    else       { bK = tid / (BN/4);   bRow = (tid % (BN/4)) * 4; } // bRow = n, 4 along n

    const int tx = tid % (BN/TN);
    const int ty = tid / (BN/TN);

    float acc[TM][TN];
#pragma unroll
    for (int i = 0; i < TM; i++)
#pragma unroll
        for (int j = 0; j < TN; j++) acc[i][j] = 0.f;

    for (int k0 = 0; k0 < K; k0 += BK) {
        float4 av = *(const float4*)&A[(long long)(m0 + aRow)*lda + k0 + aK];
        As[aK+0][aRow] = av.x; As[aK+1][aRow] = av.y;
        As[aK+2][aRow] = av.z; As[aK+3][aRow] = av.w;
        if (BKMAJ) {
            float4 bv = *(const float4*)&Bm[(long long)(n0 + bRow)*ldb + k0 + bK];
            Bs[bK+0][bRow] = bv.x; Bs[bK+1][bRow] = bv.y;
            Bs[bK+2][bRow] = bv.z; Bs[bK+3][bRow] = bv.w;
        } else {
            float4 bv = *(const float4*)&Bm[(long long)(k0 + bK)*ldb + n0 + bRow];
            *(float4*)&Bs[bK][bRow] = bv;
        }
        __syncthreads();
#pragma unroll
        for (int kk = 0; kk < BK; kk++) {
            float a[TM], b[TN];
#pragma unroll
            for (int i = 0; i < TM; i++) a[i] = As[kk][ty*TM + i];
#pragma unroll
            for (int j = 0; j < TN; j++) b[j] = Bs[kk][tx*TN + j];
#pragma unroll
            for (int i = 0; i < TM; i++)
#pragma unroll
                for (int j = 0; j < TN; j++)
                    acc[i][j] = fmaf(a[i], b[j], acc[i][j]);
        }
        __syncthreads();
    }

#pragma unroll
    for (int i = 0; i < TM; i++) {
        const int row = m0 + ty*TM + i;
#pragma unroll
        for (int j = 0; j < TN; j++) {
            const int col = n0 + tx*TN + j;
            float v = acc[i][j] * alpha;
            if (EPI != 2 && bias) v += bias[col];
            if (EPI == 2) v += addm[(long long)row*ldc + col];
            if (EPI == 1) v = 0.5f * v * (1.f + erff(v * 0.70710678118654752f));
            C[(long long)row*ldc + col] = v;
        }
    }
}

// ---------------------------------------------------------------------------
// Embedding: x = tok_emb[seq] * sqrt(E)
// ---------------------------------------------------------------------------
__global__ void embed_k(const int* __restrict__ seq, const float* __restrict__ emb,
                        float* __restrict__ x)
{
    int i = blockIdx.x * blockDim.x + threadIdx.x;   // < TOK*EE
    int e = i & (EE-1);
    int t = i >> 9;
    x[i] = emb[seq[t]*EE + e] * 22.627416997969522f; // sqrt(512)
}

// ---------------------------------------------------------------------------
// Bias precompute: biasm[b,h,q,k] = dist_emb[squares[b,q,k], h] + (seq[b,k]==0 ? -1e9 : 0)
// ---------------------------------------------------------------------------
__global__ void bias_k(const int* __restrict__ squares, const int* __restrict__ seq,
                       const float* __restrict__ dist, float* __restrict__ bias)
{
    long long i = (long long)blockIdx.x * blockDim.x + threadIdx.x; // < NZ*SS*SS
    int k = (int)(i & (SS-1));
    long long r = i >> 9;
    int q = (int)(r & (SS-1)); r >>= 9;
    int h = (int)(r & (HH-1));
    int b = (int)(r >> 3);
    float m = (seq[b*SS + k] == 0) ? -1e9f : 0.f;
    bias[i] = dist[squares[((long long)(b*SS + q) << 9) + k]*HH + h] + m;
}

// ---------------------------------------------------------------------------
// Row softmax over 512 (one warp per row, 8 rows per block)
// ---------------------------------------------------------------------------
__global__ void softmax_k(float* __restrict__ sc)
{
    const int row  = blockIdx.x * 8 + threadIdx.y;
    const int lane = threadIdx.x;
    float* p = sc + (long long)row * SS;
    float v[16];
    float mx = -INFINITY;
#pragma unroll
    for (int i = 0; i < 16; i++) { v[i] = p[lane + i*32]; mx = fmaxf(mx, v[i]); }
#pragma unroll
    for (int o = 16; o > 0; o >>= 1) mx = fmaxf(mx, __shfl_xor_sync(0xffffffffu, mx, o));
    float s = 0.f;
#pragma unroll
    for (int i = 0; i < 16; i++) { v[i] = expf(v[i] - mx); s += v[i]; }
#pragma unroll
    for (int o = 16; o > 0; o >>= 1) s += __shfl_xor_sync(0xffffffffu, s, o);
    const float inv = 1.f / s;
#pragma unroll
    for (int i = 0; i < 16; i++) p[lane + i*32] = v[i] * inv;
}

// ---------------------------------------------------------------------------
// Residual + LayerNorm (in place on x): x = LN(x + y) * w + b, eps=1e-5, E=512
// ---------------------------------------------------------------------------
__device__ __forceinline__ void block_ln_stats(float v, float& mean, float& var)
{
    float s = v, q = v*v;
#pragma unroll
    for (int o = 16; o > 0; o >>= 1) {
        s += __shfl_xor_sync(0xffffffffu, s, o);
        q += __shfl_xor_sync(0xffffffffu, q, o);
    }
    __shared__ float shs[16], shq[16];
    const int wid = threadIdx.x >> 5, lane = threadIdx.x & 31;
    if (lane == 0) { shs[wid] = s; shq[wid] = q; }
    __syncthreads();
    if (threadIdx.x < 32) {
        float ss = (lane < 16) ? shs[lane] : 0.f;
        float qq = (lane < 16) ? shq[lane] : 0.f;
#pragma unroll
        for (int o = 8; o > 0; o >>= 1) {
            ss += __shfl_xor_sync(0xffffffffu, ss, o);
            qq += __shfl_xor_sync(0xffffffffu, qq, o);
        }
        if (lane == 0) { shs[0] = ss; shq[0] = qq; }
    }
    __syncthreads();
    mean = shs[0] * (1.f/EE);
    var  = shq[0] * (1.f/EE) - mean*mean;
}

__global__ void add_ln_k(float* __restrict__ x, const float* __restrict__ y,
                         const float* __restrict__ w, const float* __restrict__ b)
{
    const long long base = (long long)blockIdx.x * EE;
    const int t = threadIdx.x;
    float v = x[base + t] + y[base + t];
    float mean, var;
    block_ln_stats(v, mean, var);
    x[base + t] = (v - mean) * rsqrtf(var + 1e-5f) * w[t] + b[t];
}

// Final LN; writes transposed: out[(s*B + b)*E + e]
__global__ void ln_final_k(const float* __restrict__ x, const float* __restrict__ w,
                           const float* __restrict__ b, float* __restrict__ out)
{
    const int row = blockIdx.x;           // b*S + s
    const int bi = row >> 9, si = row & (SS-1);
    const int t = threadIdx.x;
    float v = x[(long long)row*EE + t];
    float mean, var;
    block_ln_stats(v, mean, var);
    out[((long long)si*BB + bi)*EE + t] = (v - mean) * rsqrtf(var + 1e-5f) * w[t] + b[t];
}

__global__ void mask_k(const int* __restrict__ seq, float* __restrict__ out)
{
    int i = blockIdx.x * blockDim.x + threadIdx.x; // < TOK
    out[i] = (seq[i] == 0) ? 1.f : 0.f;
}

// ---------------------------------------------------------------------------
extern "C" void kernel_launch(void* const* d_in, const int* in_sizes, int n_in,
                              void* d_out, int out_size)
{
    const int*   seq     = (const int*)  d_in[0];
    const int*   squares = (const int*)  d_in[1];
    const float* tok_emb = (const float*)d_in[2];
    const float* dist    = (const float*)d_in[3];
    const float* ipw     = (const float*)d_in[4];
    const float* ipb     = (const float*)d_in[5];
    const float* ow      = (const float*)d_in[6];
    const float* ob      = (const float*)d_in[7];
    const float* f1w     = (const float*)d_in[8];
    const float* f1b     = (const float*)d_in[9];
    const float* f2w     = (const float*)d_in[10];
    const float* f2b     = (const float*)d_in[11];
    const float* l1w     = (const float*)d_in[12];
    const float* l1b     = (const float*)d_in[13];
    const float* l2w     = (const float*)d_in[14];
    const float* l2b     = (const float*)d_in[15];
    const float* lfw     = (const float*)d_in[16];
    const float* lfb     = (const float*)d_in[17];
    float* out = (float*)d_out;

    float *x,*qkv,*sc,*bm,*ctx,*ff,*y;
    cudaGetSymbolAddress((void**)&x,   g_x);
    cudaGetSymbolAddress((void**)&qkv, g_qkv);
    cudaGetSymbolAddress((void**)&sc,  g_scores);
    cudaGetSymbolAddress((void**)&bm,  g_biasm);
    cudaGetSymbolAddress((void**)&ctx, g_ctx);
    cudaGetSymbolAddress((void**)&ff,  g_ff);
    cudaGetSymbolAddress((void**)&y,   g_y);

    const long long SSS = (long long)SS*SS;

    embed_k<<<(TOK*EE)/256, 256>>>(seq, tok_emb, x);
    bias_k<<<(int)(((long long)NZ*SSS)/256), 256>>>(squares, seq, dist, bm);

    for (int l = 0; l < LL; l++) {
        // qkv = x @ in_proj_w^T + b      [8192,1536] K=512
        gemm_k<128,128,8,8,8,true,0><<<dim3(12,64,1),256>>>(
            x, ipw + (long long)l*3*EE*EE, ipb + l*3*EE, nullptr, qkv,
            EE, EE, EE, 3*EE, 1.f, 1, 0,0, 0,0, 0,0, 0,0);

        // scores = 0.125 * Q K^T + biasm  per (b,h): [512,512] K=64
        gemm_k<128,128,8,8,8,true,2><<<dim3(4,4,NZ),256>>>(
            qkv, qkv + EE, nullptr, bm, sc,
            DH, 3*EE, 3*EE, SS, 0.125f, HH,
            (long long)SS*3*EE, DH,
            (long long)SS*3*EE, DH,
            HH*SSS, SSS,
            HH*SSS, SSS);

        softmax_k<<<NZ*SS/8, dim3(32,8)>>>(sc);

        // ctx = P @ V  per (b,h): [512,64] K=512, V is N-major
        gemm_k<64,64,16,4,4,false,0><<<dim3(1,8,NZ),256>>>(
            sc, qkv + 2*EE, nullptr, nullptr, ctx,
            SS, SS, 3*EE, EE, 1.f, HH,
            HH*SSS, SSS,
            (long long)SS*3*EE, DH,
            (long long)SS*EE, DH,
            0,0);

        // attn_out = ctx @ out_w^T + b   [8192,512] K=512
        gemm_k<128,128,8,8,8,true,0><<<dim3(4,64,1),256>>>(
            ctx, ow + (long long)l*EE*EE, ob + l*EE, nullptr, y,
            EE, EE, EE, EE, 1.f, 1, 0,0, 0,0, 0,0, 0,0);

        add_ln_k<<<TOK, EE>>>(x, y, l1w + l*EE, l1b + l*EE);

        // h = gelu(x @ ff1_w^T + b)      [8192,2048] K=512
        gemm_k<128,128,8,8,8,true,1><<<dim3(16,64,1),256>>>(
            x, f1w + (long long)l*FFD*EE, f1b + l*FFD, nullptr, ff,
            EE, EE, EE, FFD, 1.f, 1, 0,0, 0,0, 0,0, 0,0);

        // ff = h @ ff2_w^T + b           [8192,512] K=2048
        gemm_k<128,128,8,8,8,true,0><<<dim3(4,64,1),256>>>(
            ff, f2w + (long long)l*EE*FFD, f2b + l*EE, nullptr, y,
            FFD, FFD, FFD, EE, 1.f, 1, 0,0, 0,0, 0,0, 0,0);

        add_ln_k<<<TOK, EE>>>(x, y, l2w + l*EE, l2b + l*EE);
    }

    ln_final_k<<<TOK, EE>>>(x, lfw, lfb, out);

    if (out_size >= TOK*EE + TOK)
        mask_k<<<TOK/256, 256>>>(seq, out + (long long)TOK*EE);
}

// round 3
// speedup vs baseline: 2.4294x; 2.4294x over previous
#include <cuda_runtime.h>
#include <math.h>
#include <stdint.h>

// Fixed shapes for BaseEncoder_68702296867023
#define BB 16
#define SS 512
#define EE 512
#define HH 8
#define FFD 2048
#define LL 6
#define DH 64
#define TOK (BB*SS)              // 8192 tokens
#define NZ (BB*HH)               // 128 attention batches

// ---------------------------------------------------------------------------
// Scratch (device globals; no allocations allowed)
// ---------------------------------------------------------------------------
__device__ float g_x[TOK*EE];                 // activations           16 MB
__device__ float g_qkv[TOK*3*EE];             // qkv                   48 MB
__device__ float g_scores[NZ*SS*SS];          // attention scores     134 MB
__device__ float g_biasm[NZ*SS*SS];           // rel-dist bias + mask 134 MB
__device__ float g_ctx[TOK*EE];               // attention context     16 MB
__device__ float g_ff[TOK*FFD];               // FF hidden             64 MB
__device__ float g_y[TOK*EE];                 // residual branch       16 MB
__device__ float g_wr[18874368];              // tf32-rounded weights  75 MB

__device__ __forceinline__ float tf32r(float x)
{
    uint32_t u;
    asm("cvt.rna.tf32.f32 %0, %1;" : "=r"(u) : "f"(x));
    return __uint_as_float(u);
}

// ---------------------------------------------------------------------------
// tf32 tensor-core GEMM (mma.sync.m16n8k8), double-buffered smem.
//   C[z][m,n] = alpha * A[m,:] . B(op)[:,n]  (+bias) (+addm) (gelu) (round)
//   BKMAJ: B[n*ldb + k] (weights / K^T); else B[k*ldb + n] (V).
//   EPI: 0 = (+bias), 1 = (+bias, exact gelu), 2 = (*alpha + addm)
//   All mma inputs are assumed PRE-ROUNDED to tf32 values.
// ---------------------------------------------------------------------------
template<int BM,int BN,int BK,int WM,int WN,bool BKMAJ,int EPI,bool RND>
__global__ void __launch_bounds__(256)
mma_gemm(const float* __restrict__ A, const float* __restrict__ B,
         const float* __restrict__ bias, const float* __restrict__ addm,
         float* __restrict__ C, int K, int lda, int ldb, int ldc,
         float alpha, int zmod,
         long long sAo, long long sAi, long long sBo, long long sBi,
         long long sCo, long long sCi, long long sDo, long long sDi)
{
    constexpr int BKP = BK + 4;                 // pad → conflict-free frag reads
    constexpr int WX = BN / WN, WY = BM / WM;
    static_assert(WX * WY == 8, "8 warps / 256 threads");
    constexpr int FM = WM / 16, FN = WN / 8;
    constexpr int APASS = BM / 64;              // A loader passes (BK=16)
    constexpr int BPASS = BN / 64;
    static_assert(BK == 16, "loader assumes BK=16");
    static_assert(BKMAJ || (BK * BN == 4 * 256), "!BKMAJ loader: one f4/thread");

    __shared__ float As[2][BM][BKP];
    __shared__ float Bs[2][BN][BKP];

    const int tid = threadIdx.x;
    const int z = blockIdx.z, zo = z / zmod, zi = z % zmod;
    A += zo * sAo + zi * sAi;
    B += zo * sBo + zi * sBi;
    C += zo * sCo + zi * sCi;
    if (EPI == 2) addm += zo * sDo + zi * sDi;

    const int m0 = blockIdx.y * BM, n0 = blockIdx.x * BN;
    const int warp = tid >> 5, lane = tid & 31;
    const int wx = warp % WX, wy = warp / WX;
    const int wm0 = wy * WM, wn0 = wx * WN;
    const int g = lane >> 2, tg = lane & 3;

    // global loaders
    const int aRow = tid >> 2, aK = (tid & 3) * 4;      // f4 along K
    const int bkT = tid >> 4, bn4 = (tid & 15) * 4;     // !BKMAJ: f4 along N

    float4 ar[APASS];
    float4 br[BKMAJ ? BPASS : 1];

    float acc[FM][FN][4];
#pragma unroll
    for (int i = 0; i < FM; i++)
#pragma unroll
        for (int j = 0; j < FN; j++)
#pragma unroll
            for (int c = 0; c < 4; c++) acc[i][j][c] = 0.f;

    auto ldg = [&](int k0) {
#pragma unroll
        for (int p = 0; p < APASS; p++)
            ar[p] = *(const float4*)&A[(long long)(m0 + p*64 + aRow)*lda + k0 + aK];
        if (BKMAJ) {
#pragma unroll
            for (int p = 0; p < BPASS; p++)
                br[p] = *(const float4*)&B[(long long)(n0 + p*64 + aRow)*ldb + k0 + aK];
        } else {
            br[0] = *(const float4*)&B[(long long)(k0 + bkT)*ldb + n0 + bn4];
        }
    };
    auto sts = [&](int buf) {
#pragma unroll
        for (int p = 0; p < APASS; p++)
            *(float4*)&As[buf][p*64 + aRow][aK] = ar[p];
        if (BKMAJ) {
#pragma unroll
            for (int p = 0; p < BPASS; p++)
                *(float4*)&Bs[buf][p*64 + aRow][aK] = br[p];
        } else {
            Bs[buf][bn4+0][bkT] = br[0].x;
            Bs[buf][bn4+1][bkT] = br[0].y;
            Bs[buf][bn4+2][bkT] = br[0].z;
            Bs[buf][bn4+3][bkT] = br[0].w;
        }
    };
    auto compute = [&](int cur) {
#pragma unroll
        for (int ks = 0; ks < BK/8; ks++) {
            const int kb = ks * 8;
            float a[FM][4], b[FN][2];
#pragma unroll
            for (int i = 0; i < FM; i++) {
                a[i][0] = As[cur][wm0 + i*16 +     g][kb +     tg];
                a[i][1] = As[cur][wm0 + i*16 + 8 + g][kb +     tg];
                a[i][2] = As[cur][wm0 + i*16 +     g][kb + 4 + tg];
                a[i][3] = As[cur][wm0 + i*16 + 8 + g][kb + 4 + tg];
            }
#pragma unroll
            for (int j = 0; j < FN; j++) {
                b[j][0] = Bs[cur][wn0 + j*8 + g][kb +     tg];
                b[j][1] = Bs[cur][wn0 + j*8 + g][kb + 4 + tg];
            }
#pragma unroll
            for (int i = 0; i < FM; i++)
#pragma unroll
                for (int j = 0; j < FN; j++) {
                    asm volatile(
                        "mma.sync.aligned.m16n8k8.row.col.f32.tf32.tf32.f32 "
                        "{%0,%1,%2,%3},{%4,%5,%6,%7},{%8,%9},{%0,%1,%2,%3};\n"
                        : "+f"(acc[i][j][0]), "+f"(acc[i][j][1]),
                          "+f"(acc[i][j][2]), "+f"(acc[i][j][3])
                        : "r"(__float_as_uint(a[i][0])), "r"(__float_as_uint(a[i][1])),
                          "r"(__float_as_uint(a[i][2])), "r"(__float_as_uint(a[i][3])),
                          "r"(__float_as_uint(b[j][0])), "r"(__float_as_uint(b[j][1])));
                }
        }
    };

    const int nb = K / BK;
    ldg(0);
    sts(0);
    __syncthreads();
    for (int t = 0; t < nb; t++) {
        const int cur = t & 1;
        if (t + 1 < nb) ldg((t + 1) * BK);
        compute(cur);
        if (t + 1 < nb) {
            sts(cur ^ 1);
            __syncthreads();
        }
    }

    // epilogue
#pragma unroll
    for (int i = 0; i < FM; i++) {
#pragma unroll
        for (int j = 0; j < FN; j++) {
#pragma unroll
            for (int half = 0; half < 2; half++) {
                const int r = m0 + wm0 + i*16 + g + half*8;
                const int c = n0 + wn0 + j*8 + 2*tg;
                float2 v;
                v.x = acc[i][j][half*2 + 0] * alpha;
                v.y = acc[i][j][half*2 + 1] * alpha;
                if (EPI < 2 && bias) { v.x += bias[c]; v.y += bias[c+1]; }
                if (EPI == 2) {
                    float2 m = *(const float2*)&addm[(long long)r*ldc + c];
                    v.x += m.x; v.y += m.y;
                }
                if (EPI == 1) {
                    v.x = 0.5f * v.x * (1.f + erff(v.x * 0.70710678118654752f));
                    v.y = 0.5f * v.y * (1.f + erff(v.y * 0.70710678118654752f));
                }
                if (RND) { v.x = tf32r(v.x); v.y = tf32r(v.y); }
                *(float2*)&C[(long long)r*ldc + c] = v;
            }
        }
    }
}

// ---------------------------------------------------------------------------
// Round fp32 -> tf32 (weights, once per launch)
// ---------------------------------------------------------------------------
__global__ void roundw_k(const float* __restrict__ src, float* __restrict__ dst, int n)
{
    int i = blockIdx.x * blockDim.x + threadIdx.x;
    if (i < n) dst[i] = tf32r(src[i]);
}

// ---------------------------------------------------------------------------
// Embedding: x = round_tf32(tok_emb[seq] * sqrt(E))
// ---------------------------------------------------------------------------
__global__ void embed_k(const int* __restrict__ seq, const float* __restrict__ emb,
                        float* __restrict__ x)
{
    int i = blockIdx.x * blockDim.x + threadIdx.x;   // < TOK*EE
    int e = i & (EE-1);
    int t = i >> 9;
    x[i] = tf32r(emb[seq[t]*EE + e] * 22.627416997969522f); // sqrt(512)
}

// ---------------------------------------------------------------------------
// biasm[b,h,q,k] = dist_emb[squares[b,q,k], h] + (seq[b,k]==0 ? -1e9 : 0)
// ---------------------------------------------------------------------------
__global__ void bias_k(const int* __restrict__ squares, const int* __restrict__ seq,
                       const float* __restrict__ dist, float* __restrict__ bias)
{
    long long i = (long long)blockIdx.x * blockDim.x + threadIdx.x; // < NZ*SS*SS
    int k = (int)(i & (SS-1));
    long long r = i >> 9;
    int q = (int)(r & (SS-1)); r >>= 9;
    int h = (int)(r & (HH-1));
    int b = (int)(r >> 3);
    float m = (seq[b*SS + k] == 0) ? -1e9f : 0.f;
    bias[i] = dist[squares[((long long)(b*SS + q) << 9) + k]*HH + h] + m;
}

// ---------------------------------------------------------------------------
// Row softmax over 512 (one warp per row); output rounded to tf32 (feeds mma)
// ---------------------------------------------------------------------------
__global__ void softmax_k(float* __restrict__ sc)
{
    const int row  = blockIdx.x * 8 + threadIdx.y;
    const int lane = threadIdx.x;
    float* p = sc + (long long)row * SS;
    float v[16];
    float mx = -INFINITY;
#pragma unroll
    for (int i = 0; i < 16; i++) { v[i] = p[lane + i*32]; mx = fmaxf(mx, v[i]); }
#pragma unroll
    for (int o = 16; o > 0; o >>= 1) mx = fmaxf(mx, __shfl_xor_sync(0xffffffffu, mx, o));
    float s = 0.f;
#pragma unroll
    for (int i = 0; i < 16; i++) { v[i] = expf(v[i] - mx); s += v[i]; }
#pragma unroll
    for (int o = 16; o > 0; o >>= 1) s += __shfl_xor_sync(0xffffffffu, s, o);
    const float inv = 1.f / s;
#pragma unroll
    for (int i = 0; i < 16; i++) p[lane + i*32] = tf32r(v[i] * inv);
}

// ---------------------------------------------------------------------------
// Residual + LayerNorm
// ---------------------------------------------------------------------------
__device__ __forceinline__ void block_ln_stats(float v, float& mean, float& var)
{
    float s = v, q = v*v;
#pragma unroll
    for (int o = 16; o > 0; o >>= 1) {
        s += __shfl_xor_sync(0xffffffffu, s, o);
        q += __shfl_xor_sync(0xffffffffu, q, o);
    }
    __shared__ float shs[16], shq[16];
    const int wid = threadIdx.x >> 5, lane = threadIdx.x & 31;
    if (lane == 0) { shs[wid] = s; shq[wid] = q; }
    __syncthreads();
    if (threadIdx.x < 32) {
        float ss = (lane < 16) ? shs[lane] : 0.f;
        float qq = (lane < 16) ? shq[lane] : 0.f;
#pragma unroll
        for (int o = 8; o > 0; o >>= 1) {
            ss += __shfl_xor_sync(0xffffffffu, ss, o);
            qq += __shfl_xor_sync(0xffffffffu, qq, o);
        }
        if (lane == 0) { shs[0] = ss; shq[0] = qq; }
    }
    __syncthreads();
    mean = shs[0] * (1.f/EE);
    var  = shq[0] * (1.f/EE) - mean*mean;
}

__global__ void add_ln_k(float* __restrict__ x, const float* __restrict__ y,
                         const float* __restrict__ w, const float* __restrict__ b)
{
    const long long base = (long long)blockIdx.x * EE;
    const int t = threadIdx.x;
    float v = x[base + t] + y[base + t];
    float mean, var;
    block_ln_stats(v, mean, var);
    x[base + t] = tf32r((v - mean) * rsqrtf(var + 1e-5f) * w[t] + b[t]);
}

// Final LN; writes transposed: out[(s*B + b)*E + e] (full fp32, no rounding)
__global__ void ln_final_k(const float* __restrict__ x, const float* __restrict__ w,
                           const float* __restrict__ b, float* __restrict__ out)
{
    const int row = blockIdx.x;           // b*S + s
    const int bi = row >> 9, si = row & (SS-1);
    const int t = threadIdx.x;
    float v = x[(long long)row*EE + t];
    float mean, var;
    block_ln_stats(v, mean, var);
    out[((long long)si*BB + bi)*EE + t] = (v - mean) * rsqrtf(var + 1e-5f) * w[t] + b[t];
}

__global__ void mask_k(const int* __restrict__ seq, float* __restrict__ out)
{
    int i = blockIdx.x * blockDim.x + threadIdx.x; // < TOK
    out[i] = (seq[i] == 0) ? 1.f : 0.f;
}

// ---------------------------------------------------------------------------
extern "C" void kernel_launch(void* const* d_in, const int* in_sizes, int n_in,
                              void* d_out, int out_size)
{
    const int*   seq     = (const int*)  d_in[0];
    const int*   squares = (const int*)  d_in[1];
    const float* tok_emb = (const float*)d_in[2];
    const float* dist    = (const float*)d_in[3];
    const float* ipw     = (const float*)d_in[4];
    const float* ipb     = (const float*)d_in[5];
    const float* ow      = (const float*)d_in[6];
    const float* ob      = (const float*)d_in[7];
    const float* f1w     = (const float*)d_in[8];
    const float* f1b     = (const float*)d_in[9];
    const float* f2w     = (const float*)d_in[10];
    const float* f2b     = (const float*)d_in[11];
    const float* l1w     = (const float*)d_in[12];
    const float* l1b     = (const float*)d_in[13];
    const float* l2w     = (const float*)d_in[14];
    const float* l2b     = (const float*)d_in[15];
    const float* lfw     = (const float*)d_in[16];
    const float* lfb     = (const float*)d_in[17];
    float* out = (float*)d_out;

    float *x,*qkv,*sc,*bm,*ctx,*ff,*y,*wr;
    cudaGetSymbolAddress((void**)&x,   g_x);
    cudaGetSymbolAddress((void**)&qkv, g_qkv);
    cudaGetSymbolAddress((void**)&sc,  g_scores);
    cudaGetSymbolAddress((void**)&bm,  g_biasm);
    cudaGetSymbolAddress((void**)&ctx, g_ctx);
    cudaGetSymbolAddress((void**)&ff,  g_ff);
    cudaGetSymbolAddress((void**)&y,   g_y);
    cudaGetSymbolAddress((void**)&wr,  g_wr);

    const long long SSS = (long long)SS*SS;

    // tf32-rounded weight copies
    const int N_IP = LL*3*EE*EE;   // 4718592
    const int N_OW = LL*EE*EE;     // 1572864
    const int N_F1 = LL*FFD*EE;    // 6291456
    const int N_F2 = LL*EE*FFD;    // 6291456
    float* ipr = wr;
    float* owr = ipr + N_IP;
    float* f1r = owr + N_OW;
    float* f2r = f1r + N_F1;
    roundw_k<<<(N_IP+255)/256, 256>>>(ipw, ipr, N_IP);
    roundw_k<<<(N_OW+255)/256, 256>>>(ow,  owr, N_OW);
    roundw_k<<<(N_F1+255)/256, 256>>>(f1w, f1r, N_F1);
    roundw_k<<<(N_F2+255)/256, 256>>>(f2w, f2r, N_F2);

    embed_k<<<(TOK*EE)/256, 256>>>(seq, tok_emb, x);
    bias_k<<<(int)(((long long)NZ*SSS)/256), 256>>>(squares, seq, dist, bm);

    for (int l = 0; l < LL; l++) {
        // qkv = x @ in_proj_w^T + b      [8192,1536] K=512
        mma_gemm<128,128,16,64,32,true,0,true><<<dim3(12,64,1),256>>>(
            x, ipr + (long long)l*3*EE*EE, ipb + l*3*EE, nullptr, qkv,
            EE, EE, EE, 3*EE, 1.f, 1, 0,0, 0,0, 0,0, 0,0);

        // scores = 0.125 * Q K^T + biasm  per (b,h): [512,512] K=64
        mma_gemm<128,128,16,64,32,true,2,false><<<dim3(4,4,NZ),256>>>(
            qkv, qkv + EE, nullptr, bm, sc,
            DH, 3*EE, 3*EE, SS, 0.125f, HH,
            (long long)SS*3*EE, DH,
            (long long)SS*3*EE, DH,
            HH*SSS, SSS,
            HH*SSS, SSS);

        softmax_k<<<NZ*SS/8, dim3(32,8)>>>(sc);

        // ctx = P @ V  per (b,h): [512,64] K=512, V N-major
        mma_gemm<128,64,16,64,16,false,0,true><<<dim3(1,4,NZ),256>>>(
            sc, qkv + 2*EE, nullptr, nullptr, ctx,
            SS, SS, 3*EE, EE, 1.f, HH,
            HH*SSS, SSS,
            (long long)SS*3*EE, DH,
            (long long)SS*EE, DH,
            0,0);

        // attn_out = ctx @ out_w^T + b   [8192,512] K=512
        mma_gemm<128,128,16,64,32,true,0,false><<<dim3(4,64,1),256>>>(
            ctx, owr + (long long)l*EE*EE, ob + l*EE, nullptr, y,
            EE, EE, EE, EE, 1.f, 1, 0,0, 0,0, 0,0, 0,0);

        add_ln_k<<<TOK, EE>>>(x, y, l1w + l*EE, l1b + l*EE);

        // h = gelu(x @ ff1_w^T + b)      [8192,2048] K=512
        mma_gemm<128,128,16,64,32,true,1,true><<<dim3(16,64,1),256>>>(
            x, f1r + (long long)l*FFD*EE, f1b + l*FFD, nullptr, ff,
            EE, EE, EE, FFD, 1.f, 1, 0,0, 0,0, 0,0, 0,0);

        // ff = h @ ff2_w^T + b           [8192,512] K=2048
        mma_gemm<128,128,16,64,32,true,0,false><<<dim3(4,64,1),256>>>(
            ff, f2r + (long long)l*EE*FFD, f2b + l*EE, nullptr, y,
            FFD, FFD, FFD, EE, 1.f, 1, 0,0, 0,0, 0,0, 0,0);

        add_ln_k<<<TOK, EE>>>(x, y, l2w + l*EE, l2b + l*EE);
    }

    ln_final_k<<<TOK, EE>>>(x, lfw, lfb, out);

    if (out_size >= TOK*EE + TOK)
        mask_k<<<TOK/256, 256>>>(seq, out + (long long)TOK*EE);
}

// round 4
// speedup vs baseline: 2.9939x; 1.2324x over previous
#include <cuda_runtime.h>
#include <math.h>
#include <stdint.h>

// Fixed shapes for BaseEncoder_68702296867023
#define BB 16
#define SS 512
#define EE 512
#define HH 8
#define FFD 2048
#define LL 6
#define DH 64
#define TOK (BB*SS)              // 8192 tokens
#define NZ (BB*HH)               // 128 attention batches
#define SSS ((long long)SS*SS)

// ---------------------------------------------------------------------------
// Scratch (device globals; no allocations allowed)
// ---------------------------------------------------------------------------
__device__ float g_x[TOK*EE];                 // activations           16 MB
__device__ float g_qkv[TOK*3*EE];             // qkv                   48 MB
__device__ float g_biasm[NZ*SS*SS];           // rel-dist bias + mask 134 MB
__device__ float g_ctx[TOK*EE];               // attention context     16 MB
__device__ float g_ff[TOK*FFD];               // FF hidden             64 MB
__device__ float g_y[TOK*EE];                 // residual branch       16 MB
__device__ float g_wr[18874368];              // tf32-rounded weights  75 MB

__device__ __forceinline__ float tf32r(float x)
{
    uint32_t u;
    asm("cvt.rna.tf32.f32 %0, %1;" : "=r"(u) : "f"(x));
    return __uint_as_float(u);
}

__device__ __forceinline__ void mma8(float c[4], const float a[4], float b0, float b1)
{
    asm volatile(
        "mma.sync.aligned.m16n8k8.row.col.f32.tf32.tf32.f32 "
        "{%0,%1,%2,%3},{%4,%5,%6,%7},{%8,%9},{%0,%1,%2,%3};\n"
        : "+f"(c[0]), "+f"(c[1]), "+f"(c[2]), "+f"(c[3])
        : "r"(__float_as_uint(a[0])), "r"(__float_as_uint(a[1])),
          "r"(__float_as_uint(a[2])), "r"(__float_as_uint(a[3])),
          "r"(__float_as_uint(b0)), "r"(__float_as_uint(b1)));
}

__device__ __forceinline__ void cpa16(uint32_t s, const void* g)
{
    asm volatile("cp.async.cg.shared.global [%0], [%1], 16;\n" :: "r"(s), "l"(g));
}
#define CP_COMMIT() asm volatile("cp.async.commit_group;\n")
#define CP_WAIT(N)  asm volatile("cp.async.wait_group %0;\n" :: "n"(N))

// ---------------------------------------------------------------------------
// tf32 tensor-core GEMM, 128x128 tile, BK=16, cp.async 3-stage pipeline.
//   C[m,n] = A[m,:] . B[n,:]  (+bias[n]) (gelu) (round)   -- B is [N][K] K-major
//   EPI: 0 = (+bias), 1 = (+bias, exact gelu)
//   smem per stage: A 128x20 + B 128x20 floats; dynamic smem 3*5120*4 = 61440 B.
// ---------------------------------------------------------------------------
template<int EPI, bool RND>
__global__ void __launch_bounds__(256)
mma_gemm2(const float* __restrict__ A, const float* __restrict__ B,
          const float* __restrict__ bias, float* __restrict__ C,
          int K, int lda, int ldb, int ldc)
{
    extern __shared__ __align__(16) float sm[];
    const int tid = threadIdx.x;
    const int m0 = blockIdx.y * 128, n0 = blockIdx.x * 128;
    const int warp = tid >> 5, lane = tid & 31;
    const int g = lane >> 2, tg = lane & 3;
    const int wx = warp & 3, wy = warp >> 2;      // 4x2 warp grid, 32x64 tiles
    const int wm0 = wy * 64, wn0 = wx * 32;
    const int lr = tid >> 2, kc = (tid & 3) * 4;  // loader: row, k-chunk

    const uint32_t sb = (uint32_t)__cvta_generic_to_shared(sm);

    auto prefetch = [&](int t) {
        const int s = t % 3;
        const int k0 = t * 16;
        const uint32_t so = sb + (uint32_t)(s * 5120 * 4);
#pragma unroll
        for (int p = 0; p < 2; p++) {
            const int r = p * 64 + lr;
            cpa16(so + (uint32_t)((r * 20 + kc) * 4),
                  &A[(long long)(m0 + r) * lda + k0 + kc]);
            cpa16(so + (uint32_t)((2560 + r * 20 + kc) * 4),
                  &B[(long long)(n0 + r) * ldb + k0 + kc]);
        }
    };

    float acc[4][4][4];
#pragma unroll
    for (int i = 0; i < 4; i++)
#pragma unroll
        for (int j = 0; j < 4; j++)
#pragma unroll
            for (int c = 0; c < 4; c++) acc[i][j][c] = 0.f;

    const int nb = K / 16;
    prefetch(0); CP_COMMIT();
    prefetch(1); CP_COMMIT();

    for (int t = 0; t < nb; t++) {
        CP_WAIT(1);
        __syncthreads();
        if (t + 2 < nb) prefetch(t + 2);
        CP_COMMIT();
        const float* As = sm + (t % 3) * 5120;
        const float* Bs = As + 2560;
#pragma unroll
        for (int kb = 0; kb < 16; kb += 8) {
            float a[4][4], bf[4][2];
#pragma unroll
            for (int i = 0; i < 4; i++) {
                a[i][0] = As[(wm0 + i*16 +     g) * 20 + kb +     tg];
                a[i][1] = As[(wm0 + i*16 + 8 + g) * 20 + kb +     tg];
                a[i][2] = As[(wm0 + i*16 +     g) * 20 + kb + 4 + tg];
                a[i][3] = As[(wm0 + i*16 + 8 + g) * 20 + kb + 4 + tg];
            }
#pragma unroll
            for (int j = 0; j < 4; j++) {
                bf[j][0] = Bs[(wn0 + j*8 + g) * 20 + kb +     tg];
                bf[j][1] = Bs[(wn0 + j*8 + g) * 20 + kb + 4 + tg];
            }
#pragma unroll
            for (int i = 0; i < 4; i++)
#pragma unroll
                for (int j = 0; j < 4; j++)
                    mma8(acc[i][j], a[i], bf[j][0], bf[j][1]);
        }
    }

    // epilogue
#pragma unroll
    for (int i = 0; i < 4; i++) {
#pragma unroll
        for (int j = 0; j < 4; j++) {
#pragma unroll
            for (int half = 0; half < 2; half++) {
                const int r = m0 + wm0 + i*16 + g + half*8;
                const int c = n0 + wn0 + j*8 + 2*tg;
                float2 v;
                v.x = acc[i][j][half*2 + 0];
                v.y = acc[i][j][half*2 + 1];
                v.x += bias[c]; v.y += bias[c+1];
                if (EPI == 1) {
                    v.x = 0.5f * v.x * (1.f + erff(v.x * 0.70710678118654752f));
                    v.y = 0.5f * v.y * (1.f + erff(v.y * 0.70710678118654752f));
                }
                if (RND) { v.x = tf32r(v.x); v.y = tf32r(v.y); }
                *(float2*)&C[(long long)r*ldc + c] = v;
            }
        }
    }
}

// ---------------------------------------------------------------------------
// Fused flash attention: per (qtile=128 rows, z=(b,h)) CTA, 256 threads.
//   S = 0.125*Q.K^T + biasm ; P = softmax(S) ; ctx = P.V   (online softmax)
// smem layout (floats):
//   Ks [128][68]   @ 0        (8704)
//   Vs [128][72]   @ 8704     (9216)
//   per-warp region [2176]x8 @ 17920  (bias tile stride 136 / P tile stride 132)
//   Q staging [128][68] aliased @ 17920 (used once before main loop)
// total = 35328 floats = 141312 B
// ---------------------------------------------------------------------------
__global__ void __launch_bounds__(256)
flash_k(const float* __restrict__ qkv, const float* __restrict__ biasm,
        float* __restrict__ ctx)
{
    extern __shared__ __align__(16) float sm[];
    float* Ks = sm;
    float* Vs = sm + 8704;

    const int tid = threadIdx.x, lane = tid & 31, w = tid >> 5;
    const int g = lane >> 2, tg = lane & 3;
    const int qt = blockIdx.x;          // 0..3
    const int z  = blockIdx.y;          // b*H + h
    const int b  = z >> 3, h = z & 7;
    const int q0 = qt * 128;
    const int qr = w * 16;              // warp's row offset within q-tile

    float* wr = sm + 17920 + w * 2176;  // warp-private region
    const uint32_t wr_u32 = (uint32_t)__cvta_generic_to_shared(wr);

    const float* base = qkv + (long long)(b * SS) * 1536 + h * 64;

    // ---- stage Q (coalesced) then extract per-warp a-frags ----
    {
        float* Qs = sm + 17920;
#pragma unroll
        for (int p = 0; p < 8; p++) {
            const int idx = p * 256 + tid;      // < 2048
            const int r = idx >> 4, c4 = (idx & 15) * 4;
            *(float4*)&Qs[r * 68 + c4] =
                *(const float4*)&base[(long long)(q0 + r) * 1536 + c4];
        }
        __syncthreads();
        // fallthrough: qa extracted below from Qs
    }
    float qa[8][4];
    {
        const float* Qs = sm + 17920;
#pragma unroll
        for (int ks = 0; ks < 8; ks++) {
            qa[ks][0] = Qs[(qr + g    ) * 68 + ks*8 + tg    ] * 0.125f;
            qa[ks][1] = Qs[(qr + g + 8) * 68 + ks*8 + tg    ] * 0.125f;
            qa[ks][2] = Qs[(qr + g    ) * 68 + ks*8 + tg + 4] * 0.125f;
            qa[ks][3] = Qs[(qr + g + 8) * 68 + ks*8 + tg + 4] * 0.125f;
        }
    }

    float mrun[2] = {-INFINITY, -INFINITY};
    float lrun[2] = {0.f, 0.f};
    float oacc[8][4];
#pragma unroll
    for (int n = 0; n < 8; n++)
#pragma unroll
        for (int c = 0; c < 4; c++) oacc[n][c] = 0.f;

    const float* Bz = biasm + (long long)z * SSS + (long long)(q0 + qr) * SS;

    for (int kt = 0; kt < 4; kt++) {
        __syncthreads();   // Ks/Vs free (prev PV done), Q staging consumed
        // load K,V tiles (keys kt*128..+127)
#pragma unroll
        for (int p = 0; p < 8; p++) {
            const int idx = p * 256 + tid;
            const int r = idx >> 4, c4 = (idx & 15) * 4;
            const float* src = base + (long long)(kt * 128 + r) * 1536;
            *(float4*)&Ks[r * 68 + c4] = *(const float4*)&src[512  + c4];
            *(float4*)&Vs[r * 72 + c4] = *(const float4*)&src[1024 + c4];
        }
        // async-stage this warp's bias tile [16][128] into warp region (stride 136)
#pragma unroll
        for (int p = 0; p < 16; p++) {
            const int c = p * 32 + lane;            // < 512
            const int r = c >> 5, cc4 = (c & 31) * 4;
            cpa16(wr_u32 + (uint32_t)((r * 136 + cc4) * 4),
                  &Bz[(long long)r * SS + kt * 128 + cc4]);
        }
        CP_COMMIT();
        __syncthreads();   // K/V visible

        // ---- S = Q.K^T ----
        float sacc[16][4];
#pragma unroll
        for (int n = 0; n < 16; n++)
#pragma unroll
            for (int c = 0; c < 4; c++) sacc[n][c] = 0.f;
#pragma unroll
        for (int ks = 0; ks < 8; ks++) {
#pragma unroll
            for (int n = 0; n < 16; n++) {
                const float b0 = Ks[(n*8 + g) * 68 + ks*8 + tg    ];
                const float b1 = Ks[(n*8 + g) * 68 + ks*8 + tg + 4];
                mma8(sacc[n], qa[ks], b0, b1);
            }
        }

        // ---- + bias, online softmax ----
        CP_WAIT(0);
        __syncwarp();
        float tmax0 = -INFINITY, tmax1 = -INFINITY;
#pragma unroll
        for (int n = 0; n < 16; n++) {
            const float2 bv0 = *(const float2*)&wr[ g      * 136 + n*8 + 2*tg];
            const float2 bv1 = *(const float2*)&wr[(g + 8) * 136 + n*8 + 2*tg];
            sacc[n][0] += bv0.x; sacc[n][1] += bv0.y;
            sacc[n][2] += bv1.x; sacc[n][3] += bv1.y;
            tmax0 = fmaxf(tmax0, fmaxf(sacc[n][0], sacc[n][1]));
            tmax1 = fmaxf(tmax1, fmaxf(sacc[n][2], sacc[n][3]));
        }
        tmax0 = fmaxf(tmax0, __shfl_xor_sync(0xffffffffu, tmax0, 1));
        tmax0 = fmaxf(tmax0, __shfl_xor_sync(0xffffffffu, tmax0, 2));
        tmax1 = fmaxf(tmax1, __shfl_xor_sync(0xffffffffu, tmax1, 1));
        tmax1 = fmaxf(tmax1, __shfl_xor_sync(0xffffffffu, tmax1, 2));

        const float mnew0 = fmaxf(mrun[0], tmax0);
        const float mnew1 = fmaxf(mrun[1], tmax1);
        const float scl0 = __expf(mrun[0] - mnew0);
        const float scl1 = __expf(mrun[1] - mnew1);
        float ts0 = 0.f, ts1 = 0.f;
#pragma unroll
        for (int n = 0; n < 16; n++) {
            sacc[n][0] = __expf(sacc[n][0] - mnew0);
            sacc[n][1] = __expf(sacc[n][1] - mnew0);
            sacc[n][2] = __expf(sacc[n][2] - mnew1);
            sacc[n][3] = __expf(sacc[n][3] - mnew1);
            ts0 += sacc[n][0] + sacc[n][1];
            ts1 += sacc[n][2] + sacc[n][3];
        }
        ts0 += __shfl_xor_sync(0xffffffffu, ts0, 1);
        ts0 += __shfl_xor_sync(0xffffffffu, ts0, 2);
        ts1 += __shfl_xor_sync(0xffffffffu, ts1, 1);
        ts1 += __shfl_xor_sync(0xffffffffu, ts1, 2);
        lrun[0] = lrun[0] * scl0 + ts0;
        lrun[1] = lrun[1] * scl1 + ts1;
        mrun[0] = mnew0; mrun[1] = mnew1;
#pragma unroll
        for (int n = 0; n < 8; n++) {
            oacc[n][0] *= scl0; oacc[n][1] *= scl0;
            oacc[n][2] *= scl1; oacc[n][3] *= scl1;
        }

        // ---- write P (tf32) to warp region (stride 132), then P.V ----
        __syncwarp();   // all bias reads done before overwrite
#pragma unroll
        for (int n = 0; n < 16; n++) {
            wr[ g      * 132 + n*8 + 2*tg    ] = tf32r(sacc[n][0]);
            wr[ g      * 132 + n*8 + 2*tg + 1] = tf32r(sacc[n][1]);
            wr[(g + 8) * 132 + n*8 + 2*tg    ] = tf32r(sacc[n][2]);
            wr[(g + 8) * 132 + n*8 + 2*tg + 1] = tf32r(sacc[n][3]);
        }
        __syncwarp();
#pragma unroll
        for (int ks = 0; ks < 16; ks++) {
            float pa[4];
            pa[0] = wr[ g      * 132 + ks*8 + tg    ];
            pa[1] = wr[(g + 8) * 132 + ks*8 + tg    ];
            pa[2] = wr[ g      * 132 + ks*8 + tg + 4];
            pa[3] = wr[(g + 8) * 132 + ks*8 + tg + 4];
#pragma unroll
            for (int n = 0; n < 8; n++) {
                const float b0 = Vs[(ks*8 + tg    ) * 72 + n*8 + g];
                const float b1 = Vs[(ks*8 + tg + 4) * 72 + n*8 + g];
                mma8(oacc[n], pa, b0, b1);
            }
        }
    }

    // ---- normalize and write ctx ----
    const float inv0 = 1.f / lrun[0];
    const float inv1 = 1.f / lrun[1];
    const int t0 = b * SS + q0 + qr;
#pragma unroll
    for (int n = 0; n < 8; n++) {
        const int col = h * 64 + n * 8 + 2 * tg;
        float2 v0, v1;
        v0.x = tf32r(oacc[n][0] * inv0); v0.y = tf32r(oacc[n][1] * inv0);
        v1.x = tf32r(oacc[n][2] * inv1); v1.y = tf32r(oacc[n][3] * inv1);
        *(float2*)&ctx[(long long)(t0 + g    ) * EE + col] = v0;
        *(float2*)&ctx[(long long)(t0 + g + 8) * EE + col] = v1;
    }
}

// ---------------------------------------------------------------------------
__global__ void roundw_k(const float* __restrict__ src, float* __restrict__ dst, int n)
{
    int i = blockIdx.x * blockDim.x + threadIdx.x;
    if (i < n) dst[i] = tf32r(src[i]);
}

__global__ void embed_k(const int* __restrict__ seq, const float* __restrict__ emb,
                        float* __restrict__ x)
{
    int i = blockIdx.x * blockDim.x + threadIdx.x;   // < TOK*EE
    int e = i & (EE-1);
    int t = i >> 9;
    x[i] = tf32r(emb[seq[t]*EE + e] * 22.627416997969522f); // sqrt(512)
}

__global__ void bias_k(const int* __restrict__ squares, const int* __restrict__ seq,
                       const float* __restrict__ dist, float* __restrict__ bias)
{
    long long i = (long long)blockIdx.x * blockDim.x + threadIdx.x; // < NZ*SS*SS
    int k = (int)(i & (SS-1));
    long long r = i >> 9;
    int q = (int)(r & (SS-1)); r >>= 9;
    int h = (int)(r & (HH-1));
    int b = (int)(r >> 3);
    float m = (seq[b*SS + k] == 0) ? -1e9f : 0.f;
    bias[i] = dist[squares[((long long)(b*SS + q) << 9) + k]*HH + h] + m;
}

// ---------------------------------------------------------------------------
// Residual + LayerNorm
// ---------------------------------------------------------------------------
__device__ __forceinline__ void block_ln_stats(float v, float& mean, float& var)
{
    float s = v, q = v*v;
#pragma unroll
    for (int o = 16; o > 0; o >>= 1) {
        s += __shfl_xor_sync(0xffffffffu, s, o);
        q += __shfl_xor_sync(0xffffffffu, q, o);
    }
    __shared__ float shs[16], shq[16];
    const int wid = threadIdx.x >> 5, lane = threadIdx.x & 31;
    if (lane == 0) { shs[wid] = s; shq[wid] = q; }
    __syncthreads();
    if (threadIdx.x < 32) {
        float ss = (lane < 16) ? shs[lane] : 0.f;
        float qq = (lane < 16) ? shq[lane] : 0.f;
#pragma unroll
        for (int o = 8; o > 0; o >>= 1) {
            ss += __shfl_xor_sync(0xffffffffu, ss, o);
            qq += __shfl_xor_sync(0xffffffffu, qq, o);
        }
        if (lane == 0) { shs[0] = ss; shq[0] = qq; }
    }
    __syncthreads();
    mean = shs[0] * (1.f/EE);
    var  = shq[0] * (1.f/EE) - mean*mean;
}

__global__ void add_ln_k(float* __restrict__ x, const float* __restrict__ y,
                         const float* __restrict__ w, const float* __restrict__ b)
{
    const long long base = (long long)blockIdx.x * EE;
    const int t = threadIdx.x;
    float v = x[base + t] + y[base + t];
    float mean, var;
    block_ln_stats(v, mean, var);
    x[base + t] = tf32r((v - mean) * rsqrtf(var + 1e-5f) * w[t] + b[t]);
}

__global__ void ln_final_k(const float* __restrict__ x, const float* __restrict__ w,
                           const float* __restrict__ b, float* __restrict__ out)
{
    const int row = blockIdx.x;           // b*S + s
    const int bi = row >> 9, si = row & (SS-1);
    const int t = threadIdx.x;
    float v = x[(long long)row*EE + t];
    float mean, var;
    block_ln_stats(v, mean, var);
    out[((long long)si*BB + bi)*EE + t] = (v - mean) * rsqrtf(var + 1e-5f) * w[t] + b[t];
}

__global__ void mask_k(const int* __restrict__ seq, float* __restrict__ out)
{
    int i = blockIdx.x * blockDim.x + threadIdx.x; // < TOK
    out[i] = (seq[i] == 0) ? 1.f : 0.f;
}

// ---------------------------------------------------------------------------
extern "C" void kernel_launch(void* const* d_in, const int* in_sizes, int n_in,
                              void* d_out, int out_size)
{
    const int*   seq     = (const int*)  d_in[0];
    const int*   squares = (const int*)  d_in[1];
    const float* tok_emb = (const float*)d_in[2];
    const float* dist    = (const float*)d_in[3];
    const float* ipw     = (const float*)d_in[4];
    const float* ipb     = (const float*)d_in[5];
    const float* ow      = (const float*)d_in[6];
    const float* ob      = (const float*)d_in[7];
    const float* f1w     = (const float*)d_in[8];
    const float* f1b     = (const float*)d_in[9];
    const float* f2w     = (const float*)d_in[10];
    const float* f2b     = (const float*)d_in[11];
    const float* l1w     = (const float*)d_in[12];
    const float* l1b     = (const float*)d_in[13];
    const float* l2w     = (const float*)d_in[14];
    const float* l2b     = (const float*)d_in[15];
    const float* lfw     = (const float*)d_in[16];
    const float* lfb     = (const float*)d_in[17];
    float* out = (float*)d_out;

    float *x,*qkv,*bm,*ctx,*ff,*y,*wr;
    cudaGetSymbolAddress((void**)&x,   g_x);
    cudaGetSymbolAddress((void**)&qkv, g_qkv);
    cudaGetSymbolAddress((void**)&bm,  g_biasm);
    cudaGetSymbolAddress((void**)&ctx, g_ctx);
    cudaGetSymbolAddress((void**)&ff,  g_ff);
    cudaGetSymbolAddress((void**)&y,   g_y);
    cudaGetSymbolAddress((void**)&wr,  g_wr);

    // raise dynamic smem limits (idempotent host-side calls)
    const int GEMM_SMEM  = 3 * 5120 * 4;      // 61440
    const int FLASH_SMEM = 35328 * 4;         // 141312
    cudaFuncSetAttribute(mma_gemm2<0,true>,  cudaFuncAttributeMaxDynamicSharedMemorySize, GEMM_SMEM);
    cudaFuncSetAttribute(mma_gemm2<0,false>, cudaFuncAttributeMaxDynamicSharedMemorySize, GEMM_SMEM);
    cudaFuncSetAttribute(mma_gemm2<1,true>,  cudaFuncAttributeMaxDynamicSharedMemorySize, GEMM_SMEM);
    cudaFuncSetAttribute(flash_k,            cudaFuncAttributeMaxDynamicSharedMemorySize, FLASH_SMEM);

    // tf32-rounded weight copies
    const int N_IP = LL*3*EE*EE;
    const int N_OW = LL*EE*EE;
    const int N_F1 = LL*FFD*EE;
    const int N_F2 = LL*EE*FFD;
    float* ipr = wr;
    float* owr = ipr + N_IP;
    float* f1r = owr + N_OW;
    float* f2r = f1r + N_F1;
    roundw_k<<<(N_IP+255)/256, 256>>>(ipw, ipr, N_IP);
    roundw_k<<<(N_OW+255)/256, 256>>>(ow,  owr, N_OW);
    roundw_k<<<(N_F1+255)/256, 256>>>(f1w, f1r, N_F1);
    roundw_k<<<(N_F2+255)/256, 256>>>(f2w, f2r, N_F2);

    embed_k<<<(TOK*EE)/256, 256>>>(seq, tok_emb, x);
    bias_k<<<(int)(((long long)NZ*SSS)/256), 256>>>(squares, seq, dist, bm);

    for (int l = 0; l < LL; l++) {
        // qkv = x @ in_proj_w^T + b      [8192,1536] K=512
        mma_gemm2<0,true><<<dim3(12,64), 256, GEMM_SMEM>>>(
            x, ipr + (long long)l*3*EE*EE, ipb + l*3*EE, qkv, EE, EE, EE, 3*EE);

        // fused attention: ctx = softmax(0.125*QK^T + biasm) @ V
        flash_k<<<dim3(4, NZ), 256, FLASH_SMEM>>>(qkv, bm, ctx);

        // attn_out = ctx @ out_w^T + b   [8192,512] K=512
        mma_gemm2<0,false><<<dim3(4,64), 256, GEMM_SMEM>>>(
            ctx, owr + (long long)l*EE*EE, ob + l*EE, y, EE, EE, EE, EE);

        add_ln_k<<<TOK, EE>>>(x, y, l1w + l*EE, l1b + l*EE);

        // h = gelu(x @ ff1_w^T + b)      [8192,2048] K=512
        mma_gemm2<1,true><<<dim3(16,64), 256, GEMM_SMEM>>>(
            x, f1r + (long long)l*FFD*EE, f1b + l*FFD, ff, EE, EE, EE, FFD);

        // ff = h @ ff2_w^T + b           [8192,512] K=2048
        mma_gemm2<0,false><<<dim3(4,64), 256, GEMM_SMEM>>>(
            ff, f2r + (long long)l*EE*FFD, f2b + l*EE, y, FFD, FFD, FFD, EE);

        add_ln_k<<<TOK, EE>>>(x, y, l2w + l*EE, l2b + l*EE);
    }

    ln_final_k<<<TOK, EE>>>(x, lfw, lfb, out);

    if (out_size >= TOK*EE + TOK)
        mask_k<<<TOK/256, 256>>>(seq, out + (long long)TOK*EE);
}

// round 7
// speedup vs baseline: 4.7774x; 1.5957x over previous
#include <cuda_runtime.h>
#include <cuda_fp16.h>
#include <math.h>
#include <stdint.h>

// Fixed shapes for BaseEncoder_68702296867023
#define BB 16
#define SS 512
#define EE 512
#define HH 8
#define FFD 2048
#define LL 6
#define DH 64
#define TOK (BB*SS)              // 8192 tokens
#define NZ (BB*HH)               // 128 attention batches
#define SSS ((long long)SS*SS)

// ---------------------------------------------------------------------------
// Scratch (device globals; no allocations allowed)
// ---------------------------------------------------------------------------
__device__ __half g_xh[TOK*EE];               // activations (half)     8 MB
__device__ __half g_qkvh[TOK*3*EE];           // qkv (half)            24 MB
__device__ float  g_biasm[NZ*SS*SS];          // rel-dist bias + mask 134 MB
__device__ __half g_ctxh[TOK*EE];             // attention ctx (half)   8 MB
__device__ __half g_ffh[TOK*FFD];             // FF hidden (half)      32 MB
__device__ float  g_y[TOK*EE];                // residual branch (f32) 16 MB
__device__ __half g_wh[18874368];             // fp16 weights          38 MB

// ---------------------------------------------------------------------------
__device__ __forceinline__ void mma16(float c[4], const uint32_t a[4],
                                      uint32_t b0, uint32_t b1)
{
    asm volatile(
        "mma.sync.aligned.m16n8k16.row.col.f32.f16.f16.f32 "
        "{%0,%1,%2,%3},{%4,%5,%6,%7},{%8,%9},{%0,%1,%2,%3};\n"
        : "+f"(c[0]), "+f"(c[1]), "+f"(c[2]), "+f"(c[3])
        : "r"(a[0]), "r"(a[1]), "r"(a[2]), "r"(a[3]), "r"(b0), "r"(b1));
}

__device__ __forceinline__ void cpa16(uint32_t s, const void* g)
{
    asm volatile("cp.async.cg.shared.global [%0], [%1], 16;\n" :: "r"(s), "l"(g));
}
#define CP_COMMIT() asm volatile("cp.async.commit_group;\n")
#define CP_WAIT(N)  asm volatile("cp.async.wait_group %0;\n" :: "n"(N))

// ---------------------------------------------------------------------------
// fp16 tensor-core GEMM (m16n8k16), 128x128 tile, BK=32, 3-stage cp.async.
//   C[m,n] = A[m,:].B[n,:] + bias[n] (gelu) ; A [M,K], B [N,K] both K-major half.
//   smem stage: A 128x40h (10240 B) + B 128x40h; 3 stages = 61440 B.
//   EPI: 0 = bias, 1 = bias+exact gelu. OutT: __half (rounded) or float.
// ---------------------------------------------------------------------------
template<typename OutT, int EPI>
__global__ void __launch_bounds__(256)
hgemm(const __half* __restrict__ A, const __half* __restrict__ B,
      const float* __restrict__ bias, OutT* __restrict__ C,
      int K, int lda, int ldb, int ldc)
{
    extern __shared__ __align__(16) char dsm[];
    const uint32_t sb = (uint32_t)__cvta_generic_to_shared(dsm);
    const int tid = threadIdx.x;
    const int m0 = blockIdx.y * 128, n0 = blockIdx.x * 128;
    const int warp = tid >> 5, lane = tid & 31;
    const int g = lane >> 2, tg = lane & 3;
    const int wx = warp & 3, wy = warp >> 2;      // 4x2 grid: 64x32 warp tiles
    const int wm0 = wy * 64, wn0 = wx * 32;
    const int lr = tid >> 2, lc = (tid & 3) * 8;  // loader row / k-chunk (halfs)

    auto prefetch = [&](int t) {
        const int k0 = t * 32;
        const uint32_t st = sb + (uint32_t)((t % 3) * 20480);
#pragma unroll
        for (int i = 0; i < 2; i++) {
            const int r = i * 64 + lr;
            cpa16(st + (uint32_t)(r*80 + lc*2),
                  &A[(long long)(m0 + r) * lda + k0 + lc]);
            cpa16(st + (uint32_t)(10240 + r*80 + lc*2),
                  &B[(long long)(n0 + r) * ldb + k0 + lc]);
        }
    };

    float acc[4][4][4];
#pragma unroll
    for (int i = 0; i < 4; i++)
#pragma unroll
        for (int j = 0; j < 4; j++)
#pragma unroll
            for (int c = 0; c < 4; c++) acc[i][j][c] = 0.f;

    const int nb = K / 32;
    prefetch(0); CP_COMMIT();
    prefetch(1); CP_COMMIT();

    for (int t = 0; t < nb; t++) {
        CP_WAIT(1);
        __syncthreads();
        if (t + 2 < nb) prefetch(t + 2);
        CP_COMMIT();
        const __half* As = (const __half*)(dsm + (t % 3) * 20480);
        const __half* Bs = As + 5120;
#pragma unroll
        for (int kb = 0; kb < 32; kb += 16) {
            uint32_t a[4][4], bf[4][2];
#pragma unroll
            for (int i = 0; i < 4; i++) {
                const int r0 = (wm0 + i*16 + g) * 40, r1 = (wm0 + i*16 + 8 + g) * 40;
                a[i][0] = *(const uint32_t*)&As[r0 + kb + 2*tg];
                a[i][1] = *(const uint32_t*)&As[r1 + kb + 2*tg];
                a[i][2] = *(const uint32_t*)&As[r0 + kb + 2*tg + 8];
                a[i][3] = *(const uint32_t*)&As[r1 + kb + 2*tg + 8];
            }
#pragma unroll
            for (int j = 0; j < 4; j++) {
                const int rn = (wn0 + j*8 + g) * 40;
                bf[j][0] = *(const uint32_t*)&Bs[rn + kb + 2*tg];
                bf[j][1] = *(const uint32_t*)&Bs[rn + kb + 2*tg + 8];
            }
#pragma unroll
            for (int i = 0; i < 4; i++)
#pragma unroll
                for (int j = 0; j < 4; j++)
                    mma16(acc[i][j], a[i], bf[j][0], bf[j][1]);
        }
    }

    // epilogue
#pragma unroll
    for (int i = 0; i < 4; i++) {
#pragma unroll
        for (int j = 0; j < 4; j++) {
#pragma unroll
            for (int hh = 0; hh < 2; hh++) {
                const long long r = m0 + wm0 + i*16 + g + hh*8;
                const int c = n0 + wn0 + j*8 + 2*tg;
                float vx = acc[i][j][hh*2 + 0] + bias[c];
                float vy = acc[i][j][hh*2 + 1] + bias[c+1];
                if (EPI == 1) {
                    vx = 0.5f*vx*(1.f + erff(vx*0.70710678118654752f));
                    vy = 0.5f*vy*(1.f + erff(vy*0.70710678118654752f));
                }
                if (sizeof(OutT) == 2) {
                    *(__half2*)&((__half*)C)[r*ldc + c] = __floats2half2_rn(vx, vy);
                } else {
                    float2 v2; v2.x = vx; v2.y = vy;
                    *(float2*)&((float*)C)[r*ldc + c] = v2;
                }
            }
        }
    }
}

// ---------------------------------------------------------------------------
// Fused flash attention, fp16 operands / fp32 softmax.
// smem (bytes): Ks half[128][72] @0 (18432); Vt half[64][136] @18432 (17408);
//   warp regions @35840 + w*8704: bias float[16][136] / P half[16][136] alias;
//   Q staging half[128][72] aliased @35840.  Total 105472 B.
// ---------------------------------------------------------------------------
__global__ void __launch_bounds__(256)
flash_h(const __half* __restrict__ qkvh, const float* __restrict__ biasm,
        __half* __restrict__ ctxh)
{
    extern __shared__ __align__(16) char dsm[];
    __half* Ks = (__half*)dsm;
    __half* Vt = (__half*)(dsm + 18432);

    const int tid = threadIdx.x, lane = tid & 31, w = tid >> 5;
    const int g = lane >> 2, tg = lane & 3;
    const int qt = blockIdx.x;          // 0..3
    const int z  = blockIdx.y;          // b*H + h
    const int b  = z >> 3, h = z & 7;
    const int q0 = qt * 128;
    const int qr = w * 16;

    float*  wrf = (float*)(dsm + 35840 + w * 8704);
    __half* Pw  = (__half*)(dsm + 35840 + w * 8704);
    const uint32_t wr_u32 = (uint32_t)__cvta_generic_to_shared(wrf);

    const __half* qh = qkvh + (long long)(b * SS) * 1536 + h * 64;
    const __half* kh = qh + 512;
    const __half* vh = qh + 1024;

    // ---- stage Q, extract a-frags ----
    {
        __half* Qs = (__half*)(dsm + 35840);
#pragma unroll
        for (int i = 0; i < 4; i++) {
            const int id = tid + i * 256;          // < 1024
            const int r = id >> 3, c8 = (id & 7) * 8;
            *(float4*)&Qs[r * 72 + c8] =
                *(const float4*)&qh[(long long)(q0 + r) * 1536 + c8];
        }
        __syncthreads();
    }
    uint32_t qa[4][4];
    {
        const __half* Qs = (const __half*)(dsm + 35840);
#pragma unroll
        for (int ks = 0; ks < 4; ks++) {
            const int r0 = (qr + g) * 72, r1 = (qr + g + 8) * 72;
            qa[ks][0] = *(const uint32_t*)&Qs[r0 + ks*16 + 2*tg];
            qa[ks][1] = *(const uint32_t*)&Qs[r1 + ks*16 + 2*tg];
            qa[ks][2] = *(const uint32_t*)&Qs[r0 + ks*16 + 2*tg + 8];
            qa[ks][3] = *(const uint32_t*)&Qs[r1 + ks*16 + 2*tg + 8];
        }
    }

    float mrun[2] = {-INFINITY, -INFINITY};
    float lrun[2] = {0.f, 0.f};
    float oacc[8][4];
#pragma unroll
    for (int n = 0; n < 8; n++)
#pragma unroll
        for (int c = 0; c < 4; c++) oacc[n][c] = 0.f;

    const float* Bz = biasm + (long long)z * SSS + (long long)(q0 + qr) * SS;

    for (int kt = 0; kt < 4; kt++) {
        __syncthreads();    // prior-tile consumers done; Q staging consumed
        // K tile [128 keys][64 dh]
#pragma unroll
        for (int i = 0; i < 4; i++) {
            const int id = tid + i * 256;
            const int r = id >> 3, c8 = (id & 7) * 8;
            *(float4*)&Ks[r * 72 + c8] =
                *(const float4*)&kh[(long long)(kt*128 + r) * 1536 + c8];
        }
        // V tile transposed -> Vt[dh][key]
        {
            const int dg = tid >> 6;        // dh group of 16
            const int kp = tid & 63;        // key pair
            const __half* vp = vh + (long long)(kt*128 + 2*kp) * 1536 + dg*16;
            float4 x0 = *(const float4*)(vp);
            float4 x1 = *(const float4*)(vp + 8);
            float4 y0 = *(const float4*)(vp + 1536);
            float4 y1 = *(const float4*)(vp + 1536 + 8);
            const __half* h0 = (const __half*)&x0;
            const __half* h1 = (const __half*)&x1;
            const __half* j0 = (const __half*)&y0;
            const __half* j1 = (const __half*)&y1;
#pragma unroll
            for (int d = 0; d < 8; d++) {
                *(__half2*)&Vt[(dg*16 +     d)*136 + 2*kp] = __halves2half2(h0[d], j0[d]);
                *(__half2*)&Vt[(dg*16 + 8 + d)*136 + 2*kp] = __halves2half2(h1[d], j1[d]);
            }
        }
        // bias tile [16 q][128 k] fp32 into warp region (stride 136 floats)
#pragma unroll
        for (int p = 0; p < 16; p++) {
            const int c = p * 32 + lane;            // < 512
            const int r = c >> 5, cc4 = (c & 31) * 4;
            cpa16(wr_u32 + (uint32_t)((r * 136 + cc4) * 4),
                  &Bz[(long long)r * SS + kt * 128 + cc4]);
        }
        CP_COMMIT();
        __syncthreads();

        // ---- S = Q.K^T (fp16 mma) ----
        float sacc[16][4];
#pragma unroll
        for (int n = 0; n < 16; n++)
#pragma unroll
            for (int c = 0; c < 4; c++) sacc[n][c] = 0.f;
#pragma unroll
        for (int ks = 0; ks < 4; ks++) {
#pragma unroll
            for (int n = 0; n < 16; n++) {
                const int rn = (n*8 + g) * 72;
                const uint32_t b0 = *(const uint32_t*)&Ks[rn + ks*16 + 2*tg];
                const uint32_t b1 = *(const uint32_t*)&Ks[rn + ks*16 + 2*tg + 8];
                mma16(sacc[n], qa[ks], b0, b1);
            }
        }

        // ---- *0.125 (exact) + bias, online softmax (fp32) ----
        CP_WAIT(0);
        __syncwarp();
        float tmax0 = -INFINITY, tmax1 = -INFINITY;
#pragma unroll
        for (int n = 0; n < 16; n++) {
            const float2 bv0 = *(const float2*)&wrf[ g      * 136 + n*8 + 2*tg];
            const float2 bv1 = *(const float2*)&wrf[(g + 8) * 136 + n*8 + 2*tg];
            sacc[n][0] = sacc[n][0]*0.125f + bv0.x;
            sacc[n][1] = sacc[n][1]*0.125f + bv0.y;
            sacc[n][2] = sacc[n][2]*0.125f + bv1.x;
            sacc[n][3] = sacc[n][3]*0.125f + bv1.y;
            tmax0 = fmaxf(tmax0, fmaxf(sacc[n][0], sacc[n][1]));
            tmax1 = fmaxf(tmax1, fmaxf(sacc[n][2], sacc[n][3]));
        }
        tmax0 = fmaxf(tmax0, __shfl_xor_sync(0xffffffffu, tmax0, 1));
        tmax0 = fmaxf(tmax0, __shfl_xor_sync(0xffffffffu, tmax0, 2));
        tmax1 = fmaxf(tmax1, __shfl_xor_sync(0xffffffffu, tmax1, 1));
        tmax1 = fmaxf(tmax1, __shfl_xor_sync(0xffffffffu, tmax1, 2));

        const float mnew0 = fmaxf(mrun[0], tmax0);
        const float mnew1 = fmaxf(mrun[1], tmax1);
        const float scl0 = __expf(mrun[0] - mnew0);
        const float scl1 = __expf(mrun[1] - mnew1);
        float ts0 = 0.f, ts1 = 0.f;
#pragma unroll
        for (int n = 0; n < 16; n++) {
            sacc[n][0] = __expf(sacc[n][0] - mnew0);
            sacc[n][1] = __expf(sacc[n][1] - mnew0);
            sacc[n][2] = __expf(sacc[n][2] - mnew1);
            sacc[n][3] = __expf(sacc[n][3] - mnew1);
            ts0 += sacc[n][0] + sacc[n][1];
            ts1 += sacc[n][2] + sacc[n][3];
        }
        ts0 += __shfl_xor_sync(0xffffffffu, ts0, 1);
        ts0 += __shfl_xor_sync(0xffffffffu, ts0, 2);
        ts1 += __shfl_xor_sync(0xffffffffu, ts1, 1);
        ts1 += __shfl_xor_sync(0xffffffffu, ts1, 2);
        lrun[0] = lrun[0] * scl0 + ts0;
        lrun[1] = lrun[1] * scl1 + ts1;
        mrun[0] = mnew0; mrun[1] = mnew1;
#pragma unroll
        for (int n = 0; n < 8; n++) {
            oacc[n][0] *= scl0; oacc[n][1] *= scl0;
            oacc[n][2] *= scl1; oacc[n][3] *= scl1;
        }

        // ---- P (half) into warp region, then P.V ----
        __syncwarp();   // bias reads complete before alias overwrite
#pragma unroll
        for (int n = 0; n < 16; n++) {
            *(__half2*)&Pw[ g      * 136 + n*8 + 2*tg] = __floats2half2_rn(sacc[n][0], sacc[n][1]);
            *(__half2*)&Pw[(g + 8) * 136 + n*8 + 2*tg] = __floats2half2_rn(sacc[n][2], sacc[n][3]);
        }
        __syncwarp();
#pragma unroll
        for (int ks = 0; ks < 8; ks++) {
            uint32_t pa[4];
            pa[0] = *(const uint32_t*)&Pw[ g      * 136 + ks*16 + 2*tg];
            pa[1] = *(const uint32_t*)&Pw[(g + 8) * 136 + ks*16 + 2*tg];
            pa[2] = *(const uint32_t*)&Pw[ g      * 136 + ks*16 + 2*tg + 8];
            pa[3] = *(const uint32_t*)&Pw[(g + 8) * 136 + ks*16 + 2*tg + 8];
#pragma unroll
            for (int n = 0; n < 8; n++) {
                const int rn = (n*8 + g) * 136;
                const uint32_t b0 = *(const uint32_t*)&Vt[rn + ks*16 + 2*tg];
                const uint32_t b1 = *(const uint32_t*)&Vt[rn + ks*16 + 2*tg + 8];
                mma16(oacc[n], pa, b0, b1);
            }
        }
    }

    // ---- normalize and write ctx (half) ----
    const float inv0 = 1.f / lrun[0];
    const float inv1 = 1.f / lrun[1];
    const int t0 = b * SS + q0 + qr;
#pragma unroll
    for (int n = 0; n < 8; n++) {
        const int col = h * 64 + n * 8 + 2 * tg;
        *(__half2*)&ctxh[(long long)(t0 + g    ) * EE + col] =
            __floats2half2_rn(oacc[n][0] * inv0, oacc[n][1] * inv0);
        *(__half2*)&ctxh[(long long)(t0 + g + 8) * EE + col] =
            __floats2half2_rn(oacc[n][2] * inv1, oacc[n][3] * inv1);
    }
}

// ---------------------------------------------------------------------------
__global__ void convw_k(const float* __restrict__ src, __half* __restrict__ dst, int n)
{
    int i = blockIdx.x * blockDim.x + threadIdx.x;
    if (i < n) dst[i] = __float2half_rn(src[i]);
}

__global__ void embed_k(const int* __restrict__ seq, const float* __restrict__ emb,
                        __half* __restrict__ xh)
{
    int i = blockIdx.x * blockDim.x + threadIdx.x;   // < TOK*EE
    int e = i & (EE-1);
    int t = i >> 9;
    xh[i] = __float2half_rn(emb[seq[t]*EE + e] * 22.627416997969522f);
}

__global__ void bias_k(const int* __restrict__ squares, const int* __restrict__ seq,
                       const float* __restrict__ dist, float* __restrict__ bias)
{
    long long i = (long long)blockIdx.x * blockDim.x + threadIdx.x;
    int k = (int)(i & (SS-1));
    long long r = i >> 9;
    int q = (int)(r & (SS-1)); r >>= 9;
    int h = (int)(r & (HH-1));
    int b = (int)(r >> 3);
    float m = (seq[b*SS + k] == 0) ? -1e9f : 0.f;
    bias[i] = dist[squares[((long long)(b*SS + q) << 9) + k]*HH + h] + m;
}

// ---------------------------------------------------------------------------
__device__ __forceinline__ void block_ln_stats(float v, float& mean, float& var)
{
    float s = v, q = v*v;
#pragma unroll
    for (int o = 16; o > 0; o >>= 1) {
        s += __shfl_xor_sync(0xffffffffu, s, o);
        q += __shfl_xor_sync(0xffffffffu, q, o);
    }
    __shared__ float shs[16], shq[16];
    const int wid = threadIdx.x >> 5, lane = threadIdx.x & 31;
    if (lane == 0) { shs[wid] = s; shq[wid] = q; }
    __syncthreads();
    if (threadIdx.x < 32) {
        float ss = (lane < 16) ? shs[lane] : 0.f;
        float qq = (lane < 16) ? shq[lane] : 0.f;
#pragma unroll
        for (int o = 8; o > 0; o >>= 1) {
            ss += __shfl_xor_sync(0xffffffffu, ss, o);
            qq += __shfl_xor_sync(0xffffffffu, qq, o);
        }
        if (lane == 0) { shs[0] = ss; shq[0] = qq; }
    }
    __syncthreads();
    mean = shs[0] * (1.f/EE);
    var  = shq[0] * (1.f/EE) - mean*mean;
}

__global__ void add_ln_k(__half* __restrict__ xh, const float* __restrict__ y,
                         const float* __restrict__ w, const float* __restrict__ b)
{
    const long long base = (long long)blockIdx.x * EE;
    const int t = threadIdx.x;
    float v = __half2float(xh[base + t]) + y[base + t];
    float mean, var;
    block_ln_stats(v, mean, var);
    xh[base + t] = __float2half_rn((v - mean) * rsqrtf(var + 1e-5f) * w[t] + b[t]);
}

__global__ void ln_final_k(const __half* __restrict__ xh, const float* __restrict__ w,
                           const float* __restrict__ b, float* __restrict__ out)
{
    const int row = blockIdx.x;
    const int bi = row >> 9, si = row & (SS-1);
    const int t = threadIdx.x;
    float v = __half2float(xh[(long long)row*EE + t]);
    float mean, var;
    block_ln_stats(v, mean, var);
    out[((long long)si*BB + bi)*EE + t] = (v - mean) * rsqrtf(var + 1e-5f) * w[t] + b[t];
}

__global__ void mask_k(const int* __restrict__ seq, float* __restrict__ out)
{
    int i = blockIdx.x * blockDim.x + threadIdx.x;
    out[i] = (seq[i] == 0) ? 1.f : 0.f;
}

// ---------------------------------------------------------------------------
extern "C" void kernel_launch(void* const* d_in, const int* in_sizes, int n_in,
                              void* d_out, int out_size)
{
    const int*   seq     = (const int*)  d_in[0];
    const int*   squares = (const int*)  d_in[1];
    const float* tok_emb = (const float*)d_in[2];
    const float* dist    = (const float*)d_in[3];
    const float* ipw     = (const float*)d_in[4];
    const float* ipb     = (const float*)d_in[5];
    const float* ow      = (const float*)d_in[6];
    const float* ob      = (const float*)d_in[7];
    const float* f1w     = (const float*)d_in[8];
    const float* f1b     = (const float*)d_in[9];
    const float* f2w     = (const float*)d_in[10];
    const float* f2b     = (const float*)d_in[11];
    const float* l1w     = (const float*)d_in[12];
    const float* l1b     = (const float*)d_in[13];
    const float* l2w     = (const float*)d_in[14];
    const float* l2b     = (const float*)d_in[15];
    const float* lfw     = (const float*)d_in[16];
    const float* lfb     = (const float*)d_in[17];
    float* out = (float*)d_out;

    __half *xh,*qkvh,*ctxh,*ffh,*wh;
    float *bm,*y;
    cudaGetSymbolAddress((void**)&xh,   g_xh);
    cudaGetSymbolAddress((void**)&qkvh, g_qkvh);
    cudaGetSymbolAddress((void**)&bm,   g_biasm);
    cudaGetSymbolAddress((void**)&ctxh, g_ctxh);
    cudaGetSymbolAddress((void**)&ffh,  g_ffh);
    cudaGetSymbolAddress((void**)&y,    g_y);
    cudaGetSymbolAddress((void**)&wh,   g_wh);

    const int GEMM_SMEM  = 3 * 20480;     // 61440
    const int FLASH_SMEM = 105472;
    cudaFuncSetAttribute(hgemm<__half,0>, cudaFuncAttributeMaxDynamicSharedMemorySize, GEMM_SMEM);
    cudaFuncSetAttribute(hgemm<__half,1>, cudaFuncAttributeMaxDynamicSharedMemorySize, GEMM_SMEM);
    cudaFuncSetAttribute(hgemm<float,0>,  cudaFuncAttributeMaxDynamicSharedMemorySize, GEMM_SMEM);
    cudaFuncSetAttribute(flash_h,         cudaFuncAttributeMaxDynamicSharedMemorySize, FLASH_SMEM);

    const int N_IP = LL*3*EE*EE;
    const int N_OW = LL*EE*EE;
    const int N_F1 = LL*FFD*EE;
    const int N_F2 = LL*EE*FFD;
    __half* iph = wh;
    __half* owh = iph + N_IP;
    __half* f1h = owh + N_OW;
    __half* f2h = f1h + N_F1;
    convw_k<<<(N_IP+255)/256, 256>>>(ipw, iph, N_IP);
    convw_k<<<(N_OW+255)/256, 256>>>(ow,  owh, N_OW);
    convw_k<<<(N_F1+255)/256, 256>>>(f1w, f1h, N_F1);
    convw_k<<<(N_F2+255)/256, 256>>>(f2w, f2h, N_F2);

    embed_k<<<(TOK*EE)/256, 256>>>(seq, tok_emb, xh);
    bias_k<<<(int)(((long long)NZ*SSS)/256), 256>>>(squares, seq, dist, bm);

    for (int l = 0; l < LL; l++) {
        // qkv = x @ in_proj_w^T + b      [8192,1536] K=512
        hgemm<__half,0><<<dim3(12,64), 256, GEMM_SMEM>>>(
            xh, iph + (long long)l*3*EE*EE, ipb + l*3*EE, qkvh, EE, EE, EE, 3*EE);

        // fused attention: ctx = softmax(0.125*QK^T + biasm) @ V
        flash_h<<<dim3(4, NZ), 256, FLASH_SMEM>>>(qkvh, bm, ctxh);

        // attn_out = ctx @ out_w^T + b   [8192,512] K=512   (fp32 out)
        hgemm<float,0><<<dim3(4,64), 256, GEMM_SMEM>>>(
            ctxh, owh + (long long)l*EE*EE, ob + l*EE, y, EE, EE, EE, EE);

        add_ln_k<<<TOK, EE>>>(xh, y, l1w + l*EE, l1b + l*EE);

        // h = gelu(x @ ff1_w^T + b)      [8192,2048] K=512
        hgemm<__half,1><<<dim3(16,64), 256, GEMM_SMEM>>>(
            xh, f1h + (long long)l*FFD*EE, f1b + l*FFD, ffh, EE, EE, EE, FFD);

        // ff = h @ ff2_w^T + b           [8192,512] K=2048  (fp32 out)
        hgemm<float,0><<<dim3(4,64), 256, GEMM_SMEM>>>(
            ffh, f2h + (long long)l*EE*FFD, f2b + l*EE, y, FFD, FFD, FFD, EE);

        add_ln_k<<<TOK, EE>>>(xh, y, l2w + l*EE, l2b + l*EE);
    }

    ln_final_k<<<TOK, EE>>>(xh, lfw, lfb, out);

    if (out_size >= TOK*EE + TOK)
        mask_k<<<TOK/256, 256>>>(seq, out + (long long)TOK*EE);
}

// round 8
// speedup vs baseline: 5.0028x; 1.0472x over previous
#include <cuda_runtime.h>
#include <cuda_fp16.h>
#include <math.h>
#include <stdint.h>

// Fixed shapes for BaseEncoder_68702296867023
#define BB 16
#define SS 512
#define EE 512
#define HH 8
#define FFD 2048
#define LL 6
#define DH 64
#define TOK (BB*SS)              // 8192 tokens
#define NZ (BB*HH)               // 128 attention batches
#define SSS ((long long)SS*SS)

// ---------------------------------------------------------------------------
// Scratch (device globals; no allocations allowed)
// ---------------------------------------------------------------------------
__device__ __half g_xh[TOK*EE];               // activations (half)     8 MB
__device__ __half g_qkvh[TOK*3*EE];           // qkv (half)            24 MB
__device__ __half g_biasmh[NZ*SS*SS];         // rel-dist bias+mask    67 MB
__device__ __half g_ctxh[TOK*EE];             // attention ctx (half)   8 MB
__device__ __half g_ffh[TOK*FFD];             // FF hidden (half)      32 MB
__device__ float  g_y[TOK*EE];                // residual branch (f32) 16 MB
__device__ __half g_wh[18874368];             // fp16 weights          38 MB

#define N_IP (LL*3*EE*EE)
#define N_OW (LL*EE*EE)
#define N_F1 (LL*FFD*EE)
#define N_F2 (LL*EE*FFD)

// ---------------------------------------------------------------------------
__device__ __forceinline__ void mma16(float c[4], const uint32_t a[4],
                                      uint32_t b0, uint32_t b1)
{
    asm volatile(
        "mma.sync.aligned.m16n8k16.row.col.f32.f16.f16.f32 "
        "{%0,%1,%2,%3},{%4,%5,%6,%7},{%8,%9},{%0,%1,%2,%3};\n"
        : "+f"(c[0]), "+f"(c[1]), "+f"(c[2]), "+f"(c[3])
        : "r"(a[0]), "r"(a[1]), "r"(a[2]), "r"(a[3]), "r"(b0), "r"(b1));
}

__device__ __forceinline__ void cpa16(uint32_t s, const void* g)
{
    asm volatile("cp.async.cg.shared.global [%0], [%1], 16;\n" :: "r"(s), "l"(g));
}
#define CP_COMMIT() asm volatile("cp.async.commit_group;\n")
#define CP_WAIT(N)  asm volatile("cp.async.wait_group %0;\n" :: "n"(N))

#define LDSM4(r0,r1,r2,r3,addr) \
    asm volatile("ldmatrix.sync.aligned.m8n8.x4.shared.b16 {%0,%1,%2,%3}, [%4];" \
                 : "=r"(r0),"=r"(r1),"=r"(r2),"=r"(r3) : "r"(addr))
#define LDSM2(r0,r1,addr) \
    asm volatile("ldmatrix.sync.aligned.m8n8.x2.shared.b16 {%0,%1}, [%2];" \
                 : "=r"(r0),"=r"(r1) : "r"(addr))

// ---------------------------------------------------------------------------
// fp16 tensor-core GEMM (m16n8k16), 128x128 tile, BK=32, 3-stage cp.async,
// ldmatrix fragment loads.
//   C[m,n] = A[m,:].B[n,:] + bias[n] (gelu) ; A [M,K], B [N,K] K-major half.
//   smem stage: A 128x40h + B 128x40h = 20480 B; 3 stages = 61440 B.
// ---------------------------------------------------------------------------
template<typename OutT, int EPI>
__global__ void __launch_bounds__(256)
hgemm(const __half* __restrict__ A, const __half* __restrict__ B,
      const float* __restrict__ bias, OutT* __restrict__ C,
      int K, int lda, int ldb, int ldc)
{
    extern __shared__ __align__(16) char dsm[];
    const uint32_t sb = (uint32_t)__cvta_generic_to_shared(dsm);
    const int tid = threadIdx.x;
    const int m0 = blockIdx.y * 128, n0 = blockIdx.x * 128;
    const int warp = tid >> 5, lane = tid & 31;
    const int g = lane >> 2, tg = lane & 3;
    const int wx = warp & 3, wy = warp >> 2;      // 4x2 grid: 64x32 warp tiles
    const int wm0 = wy * 64, wn0 = wx * 32;
    const int lr = tid >> 2, lc = (tid & 3) * 8;  // loader row / k-chunk (halfs)

    // ldmatrix per-lane offsets (bytes, within stage)
    const uint32_t aoff = (uint32_t)(((wm0 + ((lane>>3)&1)*8 + (lane&7)) * 40
                                      + (lane>>4)*8) * 2);
    const uint32_t boff = (uint32_t)(10240 + ((wn0 + (lane&7)) * 40
                                      + ((lane>>3)&1)*8) * 2);

    auto prefetch = [&](int t) {
        const int k0 = t * 32;
        const uint32_t st = sb + (uint32_t)((t % 3) * 20480);
#pragma unroll
        for (int i = 0; i < 2; i++) {
            const int r = i * 64 + lr;
            cpa16(st + (uint32_t)(r*80 + lc*2),
                  &A[(long long)(m0 + r) * lda + k0 + lc]);
            cpa16(st + (uint32_t)(10240 + r*80 + lc*2),
                  &B[(long long)(n0 + r) * ldb + k0 + lc]);
        }
    };

    float acc[4][4][4];
#pragma unroll
    for (int i = 0; i < 4; i++)
#pragma unroll
        for (int j = 0; j < 4; j++)
#pragma unroll
            for (int c = 0; c < 4; c++) acc[i][j][c] = 0.f;

    const int nb = K / 32;
    prefetch(0); CP_COMMIT();
    prefetch(1); CP_COMMIT();

    for (int t = 0; t < nb; t++) {
        CP_WAIT(1);
        __syncthreads();
        if (t + 2 < nb) prefetch(t + 2);
        CP_COMMIT();
        const uint32_t st = sb + (uint32_t)((t % 3) * 20480);
#pragma unroll
        for (int kb = 0; kb < 32; kb += 16) {
            uint32_t a[4][4], bf[4][2];
#pragma unroll
            for (int i = 0; i < 4; i++)
                LDSM4(a[i][0], a[i][1], a[i][2], a[i][3],
                      st + aoff + (uint32_t)(i*1280 + kb*2));
#pragma unroll
            for (int j = 0; j < 4; j++)
                LDSM2(bf[j][0], bf[j][1],
                      st + boff + (uint32_t)(j*640 + kb*2));
#pragma unroll
            for (int i = 0; i < 4; i++)
#pragma unroll
                for (int j = 0; j < 4; j++)
                    mma16(acc[i][j], a[i], bf[j][0], bf[j][1]);
        }
    }

    // epilogue
#pragma unroll
    for (int i = 0; i < 4; i++) {
#pragma unroll
        for (int j = 0; j < 4; j++) {
#pragma unroll
            for (int hh = 0; hh < 2; hh++) {
                const long long r = m0 + wm0 + i*16 + g + hh*8;
                const int c = n0 + wn0 + j*8 + 2*tg;
                float vx = acc[i][j][hh*2 + 0] + bias[c];
                float vy = acc[i][j][hh*2 + 1] + bias[c+1];
                if (EPI == 1) {
                    vx = 0.5f*vx*(1.f + erff(vx*0.70710678118654752f));
                    vy = 0.5f*vy*(1.f + erff(vy*0.70710678118654752f));
                }
                if (sizeof(OutT) == 2) {
                    *(__half2*)&((__half*)C)[r*ldc + c] = __floats2half2_rn(vx, vy);
                } else {
                    float2 v2; v2.x = vx; v2.y = vy;
                    *(float2*)&((float*)C)[r*ldc + c] = v2;
                }
            }
        }
    }
}

// ---------------------------------------------------------------------------
// Fused flash attention, fp16 operands / fp32 softmax, fp16 bias.
// smem (bytes): Ks half[128][72] @0 (18432); Vt half[64][136] @18432 (17408);
//   warp regions @35840 + w*4352: bias half[16][136] / P half[16][136] alias;
//   Q staging half[128][72] aliased @35840 (18432 <= 8*4352).  Total 70656 B.
// ---------------------------------------------------------------------------
__global__ void __launch_bounds__(256)
flash_h(const __half* __restrict__ qkvh, const __half* __restrict__ biasmh,
        __half* __restrict__ ctxh)
{
    extern __shared__ __align__(16) char dsm[];
    __half* Ks = (__half*)dsm;
    __half* Vt = (__half*)(dsm + 18432);

    const int tid = threadIdx.x, lane = tid & 31, w = tid >> 5;
    const int g = lane >> 2, tg = lane & 3;
    const int qt = blockIdx.x;          // 0..3
    const int z  = blockIdx.y;          // b*H + h
    const int b  = z >> 3, h = z & 7;
    const int q0 = qt * 128;
    const int qr = w * 16;

    __half* wrh = (__half*)(dsm + 35840 + w * 4352);
    const uint32_t wr_u32 = (uint32_t)__cvta_generic_to_shared(wrh);

    const __half* qh = qkvh + (long long)(b * SS) * 1536 + h * 64;
    const __half* kh = qh + 512;
    const __half* vh = qh + 1024;

    // ---- stage Q, extract a-frags ----
    {
        __half* Qs = (__half*)(dsm + 35840);
#pragma unroll
        for (int i = 0; i < 4; i++) {
            const int id = tid + i * 256;          // < 1024
            const int r = id >> 3, c8 = (id & 7) * 8;
            *(float4*)&Qs[r * 72 + c8] =
                *(const float4*)&qh[(long long)(q0 + r) * 1536 + c8];
        }
        __syncthreads();
    }
    uint32_t qa[4][4];
    {
        const __half* Qs = (const __half*)(dsm + 35840);
#pragma unroll
        for (int ks = 0; ks < 4; ks++) {
            const int r0 = (qr + g) * 72, r1 = (qr + g + 8) * 72;
            qa[ks][0] = *(const uint32_t*)&Qs[r0 + ks*16 + 2*tg];
            qa[ks][1] = *(const uint32_t*)&Qs[r1 + ks*16 + 2*tg];
            qa[ks][2] = *(const uint32_t*)&Qs[r0 + ks*16 + 2*tg + 8];
            qa[ks][3] = *(const uint32_t*)&Qs[r1 + ks*16 + 2*tg + 8];
        }
    }

    float mrun[2] = {-INFINITY, -INFINITY};
    float lrun[2] = {0.f, 0.f};
    float oacc[8][4];
#pragma unroll
    for (int n = 0; n < 8; n++)
#pragma unroll
        for (int c = 0; c < 4; c++) oacc[n][c] = 0.f;

    const __half* Bz = biasmh + (long long)z * SSS + (long long)(q0 + qr) * SS;

    for (int kt = 0; kt < 4; kt++) {
        __syncthreads();    // prior-tile consumers done; Q staging consumed
        // K tile [128 keys][64 dh]
#pragma unroll
        for (int i = 0; i < 4; i++) {
            const int id = tid + i * 256;
            const int r = id >> 3, c8 = (id & 7) * 8;
            *(float4*)&Ks[r * 72 + c8] =
                *(const float4*)&kh[(long long)(kt*128 + r) * 1536 + c8];
        }
        // V tile transposed -> Vt[dh][key]
        {
            const int dg = tid >> 6;        // dh group of 16
            const int kp = tid & 63;        // key pair
            const __half* vp = vh + (long long)(kt*128 + 2*kp) * 1536 + dg*16;
            float4 x0 = *(const float4*)(vp);
            float4 x1 = *(const float4*)(vp + 8);
            float4 y0 = *(const float4*)(vp + 1536);
            float4 y1 = *(const float4*)(vp + 1536 + 8);
            const __half* h0 = (const __half*)&x0;
            const __half* h1 = (const __half*)&x1;
            const __half* j0 = (const __half*)&y0;
            const __half* j1 = (const __half*)&y1;
#pragma unroll
            for (int d = 0; d < 8; d++) {
                *(__half2*)&Vt[(dg*16 +     d)*136 + 2*kp] = __halves2half2(h0[d], j0[d]);
                *(__half2*)&Vt[(dg*16 + 8 + d)*136 + 2*kp] = __halves2half2(h1[d], j1[d]);
            }
        }
        // bias tile [16 q][128 k] half into warp region (stride 136 halfs)
#pragma unroll
        for (int p = 0; p < 8; p++) {
            const int c = p * 32 + lane;            // < 256
            const int r = c >> 4, cc8 = (c & 15) * 8;
            cpa16(wr_u32 + (uint32_t)((r * 136 + cc8) * 2),
                  &Bz[(long long)r * SS + kt * 128 + cc8]);
        }
        CP_COMMIT();
        __syncthreads();

        // ---- S = Q.K^T (fp16 mma) ----
        float sacc[16][4];
#pragma unroll
        for (int n = 0; n < 16; n++)
#pragma unroll
            for (int c = 0; c < 4; c++) sacc[n][c] = 0.f;
#pragma unroll
        for (int ks = 0; ks < 4; ks++) {
#pragma unroll
            for (int n = 0; n < 16; n++) {
                const int rn = (n*8 + g) * 72;
                const uint32_t b0 = *(const uint32_t*)&Ks[rn + ks*16 + 2*tg];
                const uint32_t b1 = *(const uint32_t*)&Ks[rn + ks*16 + 2*tg + 8];
                mma16(sacc[n], qa[ks], b0, b1);
            }
        }

        // ---- *0.125 (exact) + bias, online softmax (fp32) ----
        CP_WAIT(0);
        __syncwarp();
        float tmax0 = -INFINITY, tmax1 = -INFINITY;
#pragma unroll
        for (int n = 0; n < 16; n++) {
            const float2 bv0 = __half22float2(*(__half2*)&wrh[ g      * 136 + n*8 + 2*tg]);
            const float2 bv1 = __half22float2(*(__half2*)&wrh[(g + 8) * 136 + n*8 + 2*tg]);
            sacc[n][0] = sacc[n][0]*0.125f + bv0.x;
            sacc[n][1] = sacc[n][1]*0.125f + bv0.y;
            sacc[n][2] = sacc[n][2]*0.125f + bv1.x;
            sacc[n][3] = sacc[n][3]*0.125f + bv1.y;
            tmax0 = fmaxf(tmax0, fmaxf(sacc[n][0], sacc[n][1]));
            tmax1 = fmaxf(tmax1, fmaxf(sacc[n][2], sacc[n][3]));
        }
        tmax0 = fmaxf(tmax0, __shfl_xor_sync(0xffffffffu, tmax0, 1));
        tmax0 = fmaxf(tmax0, __shfl_xor_sync(0xffffffffu, tmax0, 2));
        tmax1 = fmaxf(tmax1, __shfl_xor_sync(0xffffffffu, tmax1, 1));
        tmax1 = fmaxf(tmax1, __shfl_xor_sync(0xffffffffu, tmax1, 2));

        const float mnew0 = fmaxf(mrun[0], tmax0);
        const float mnew1 = fmaxf(mrun[1], tmax1);
        const float scl0 = __expf(mrun[0] - mnew0);
        const float scl1 = __expf(mrun[1] - mnew1);
        float ts0 = 0.f, ts1 = 0.f;
#pragma unroll
        for (int n = 0; n < 16; n++) {
            sacc[n][0] = __expf(sacc[n][0] - mnew0);
            sacc[n][1] = __expf(sacc[n][1] - mnew0);
            sacc[n][2] = __expf(sacc[n][2] - mnew1);
            sacc[n][3] = __expf(sacc[n][3] - mnew1);
            ts0 += sacc[n][0] + sacc[n][1];
            ts1 += sacc[n][2] + sacc[n][3];
        }
        ts0 += __shfl_xor_sync(0xffffffffu, ts0, 1);
        ts0 += __shfl_xor_sync(0xffffffffu, ts0, 2);
        ts1 += __shfl_xor_sync(0xffffffffu, ts1, 1);
        ts1 += __shfl_xor_sync(0xffffffffu, ts1, 2);
        lrun[0] = lrun[0] * scl0 + ts0;
        lrun[1] = lrun[1] * scl1 + ts1;
        mrun[0] = mnew0; mrun[1] = mnew1;
#pragma unroll
        for (int n = 0; n < 8; n++) {
            oacc[n][0] *= scl0; oacc[n][1] *= scl0;
            oacc[n][2] *= scl1; oacc[n][3] *= scl1;
        }

        // ---- P (half) into warp region (alias), then P.V ----
        __syncwarp();   // bias reads complete before alias overwrite
#pragma unroll
        for (int n = 0; n < 16; n++) {
            *(__half2*)&wrh[ g      * 136 + n*8 + 2*tg] = __floats2half2_rn(sacc[n][0], sacc[n][1]);
            *(__half2*)&wrh[(g + 8) * 136 + n*8 + 2*tg] = __floats2half2_rn(sacc[n][2], sacc[n][3]);
        }
        __syncwarp();
#pragma unroll
        for (int ks = 0; ks < 8; ks++) {
            uint32_t pa[4];
            pa[0] = *(const uint32_t*)&wrh[ g      * 136 + ks*16 + 2*tg];
            pa[1] = *(const uint32_t*)&wrh[(g + 8) * 136 + ks*16 + 2*tg];
            pa[2] = *(const uint32_t*)&wrh[ g      * 136 + ks*16 + 2*tg + 8];
            pa[3] = *(const uint32_t*)&wrh[(g + 8) * 136 + ks*16 + 2*tg + 8];
#pragma unroll
            for (int n = 0; n < 8; n++) {
                const int rn = (n*8 + g) * 136;
                const uint32_t b0 = *(const uint32_t*)&Vt[rn + ks*16 + 2*tg];
                const uint32_t b1 = *(const uint32_t*)&Vt[rn + ks*16 + 2*tg + 8];
                mma16(oacc[n], pa, b0, b1);
            }
        }
    }

    // ---- normalize and write ctx (half) ----
    const float inv0 = 1.f / lrun[0];
    const float inv1 = 1.f / lrun[1];
    const int t0 = b * SS + q0 + qr;
#pragma unroll
    for (int n = 0; n < 8; n++) {
        const int col = h * 64 + n * 8 + 2 * tg;
        *(__half2*)&ctxh[(long long)(t0 + g    ) * EE + col] =
            __floats2half2_rn(oacc[n][0] * inv0, oacc[n][1] * inv0);
        *(__half2*)&ctxh[(long long)(t0 + g + 8) * EE + col] =
            __floats2half2_rn(oacc[n][2] * inv1, oacc[n][3] * inv1);
    }
}

// ---------------------------------------------------------------------------
// Merged weight convert: all 4 weight tensors -> g_wh in one launch
// ---------------------------------------------------------------------------
__global__ void convw4_k(const float* __restrict__ s0, const float* __restrict__ s1,
                         const float* __restrict__ s2, const float* __restrict__ s3,
                         __half* __restrict__ dst)
{
    const int i = blockIdx.x * blockDim.x + threadIdx.x;   // < N_IP+N_OW+N_F1+N_F2
    float v;
    if      (i < N_IP)                  v = s0[i];
    else if (i < N_IP + N_OW)           v = s1[i - N_IP];
    else if (i < N_IP + N_OW + N_F1)    v = s2[i - N_IP - N_OW];
    else                                v = s3[i - N_IP - N_OW - N_F1];
    dst[i] = __float2half_rn(v);
}

__global__ void embed_k(const int* __restrict__ seq, const float* __restrict__ emb,
                        __half* __restrict__ xh)
{
    int i = blockIdx.x * blockDim.x + threadIdx.x;   // < TOK*EE
    int e = i & (EE-1);
    int t = i >> 9;
    xh[i] = __float2half_rn(emb[seq[t]*EE + e] * 22.627416997969522f);
}

// biasm (half): dist + (masked ? -60000 : 0). -60000 is enough: after softmax
// row-max subtraction, expf(-59000-ish) == 0.0f exactly; rows always contain
// unmasked keys.
__global__ void bias_k(const int* __restrict__ squares, const int* __restrict__ seq,
                       const float* __restrict__ dist, __half* __restrict__ bias)
{
    long long i = (long long)blockIdx.x * blockDim.x + threadIdx.x;
    int k = (int)(i & (SS-1));
    long long r = i >> 9;
    int q = (int)(r & (SS-1)); r >>= 9;
    int h = (int)(r & (HH-1));
    int b = (int)(r >> 3);
    float m = (seq[b*SS + k] == 0) ? -60000.f : 0.f;
    bias[i] = __float2half_rn(dist[squares[((long long)(b*SS + q) << 9) + k]*HH + h] + m);
}

// ---------------------------------------------------------------------------
__device__ __forceinline__ void block_ln_stats(float v, float& mean, float& var)
{
    float s = v, q = v*v;
#pragma unroll
    for (int o = 16; o > 0; o >>= 1) {
        s += __shfl_xor_sync(0xffffffffu, s, o);
        q += __shfl_xor_sync(0xffffffffu, q, o);
    }
    __shared__ float shs[16], shq[16];
    const int wid = threadIdx.x >> 5, lane = threadIdx.x & 31;
    if (lane == 0) { shs[wid] = s; shq[wid] = q; }
    __syncthreads();
    if (threadIdx.x < 32) {
        float ss = (lane < 16) ? shs[lane] : 0.f;
        float qq = (lane < 16) ? shq[lane] : 0.f;
#pragma unroll
        for (int o = 8; o > 0; o >>= 1) {
            ss += __shfl_xor_sync(0xffffffffu, ss, o);
            qq += __shfl_xor_sync(0xffffffffu, qq, o);
        }
        if (lane == 0) { shs[0] = ss; shq[0] = qq; }
    }
    __syncthreads();
    mean = shs[0] * (1.f/EE);
    var  = shq[0] * (1.f/EE) - mean*mean;
}

__global__ void add_ln_k(__half* __restrict__ xh, const float* __restrict__ y,
                         const float* __restrict__ w, const float* __restrict__ b)
{
    const long long base = (long long)blockIdx.x * EE;
    const int t = threadIdx.x;
    float v = __half2float(xh[base + t]) + y[base + t];
    float mean, var;
    block_ln_stats(v, mean, var);
    xh[base + t] = __float2half_rn((v - mean) * rsqrtf(var + 1e-5f) * w[t] + b[t]);
}

__global__ void ln_final_k(const __half* __restrict__ xh, const float* __restrict__ w,
                           const float* __restrict__ b, float* __restrict__ out)
{
    const int row = blockIdx.x;
    const int bi = row >> 9, si = row & (SS-1);
    const int t = threadIdx.x;
    float v = __half2float(xh[(long long)row*EE + t]);
    float mean, var;
    block_ln_stats(v, mean, var);
    out[((long long)si*BB + bi)*EE + t] = (v - mean) * rsqrtf(var + 1e-5f) * w[t] + b[t];
}

__global__ void mask_k(const int* __restrict__ seq, float* __restrict__ out)
{
    int i = blockIdx.x * blockDim.x + threadIdx.x;
    out[i] = (seq[i] == 0) ? 1.f : 0.f;
}

// ---------------------------------------------------------------------------
extern "C" void kernel_launch(void* const* d_in, const int* in_sizes, int n_in,
                              void* d_out, int out_size)
{
    const int*   seq     = (const int*)  d_in[0];
    const int*   squares = (const int*)  d_in[1];
    const float* tok_emb = (const float*)d_in[2];
    const float* dist    = (const float*)d_in[3];
    const float* ipw     = (const float*)d_in[4];
    const float* ipb     = (const float*)d_in[5];
    const float* ow      = (const float*)d_in[6];
    const float* ob      = (const float*)d_in[7];
    const float* f1w     = (const float*)d_in[8];
    const float* f1b     = (const float*)d_in[9];
    const float* f2w     = (const float*)d_in[10];
    const float* f2b     = (const float*)d_in[11];
    const float* l1w     = (const float*)d_in[12];
    const float* l1b     = (const float*)d_in[13];
    const float* l2w     = (const float*)d_in[14];
    const float* l2b     = (const float*)d_in[15];
    const float* lfw     = (const float*)d_in[16];
    const float* lfb     = (const float*)d_in[17];
    float* out = (float*)d_out;

    __half *xh,*qkvh,*bmh,*ctxh,*ffh,*wh;
    float *y;
    cudaGetSymbolAddress((void**)&xh,   g_xh);
    cudaGetSymbolAddress((void**)&qkvh, g_qkvh);
    cudaGetSymbolAddress((void**)&bmh,  g_biasmh);
    cudaGetSymbolAddress((void**)&ctxh, g_ctxh);
    cudaGetSymbolAddress((void**)&ffh,  g_ffh);
    cudaGetSymbolAddress((void**)&y,    g_y);
    cudaGetSymbolAddress((void**)&wh,   g_wh);

    const int GEMM_SMEM  = 3 * 20480;     // 61440
    const int FLASH_SMEM = 70656;
    cudaFuncSetAttribute(hgemm<__half,0>, cudaFuncAttributeMaxDynamicSharedMemorySize, GEMM_SMEM);
    cudaFuncSetAttribute(hgemm<__half,1>, cudaFuncAttributeMaxDynamicSharedMemorySize, GEMM_SMEM);
    cudaFuncSetAttribute(hgemm<float,0>,  cudaFuncAttributeMaxDynamicSharedMemorySize, GEMM_SMEM);
    cudaFuncSetAttribute(flash_h,         cudaFuncAttributeMaxDynamicSharedMemorySize, FLASH_SMEM);

    __half* iph = wh;
    __half* owh = iph + N_IP;
    __half* f1h = owh + N_OW;
    __half* f2h = f1h + N_F1;
    convw4_k<<<(N_IP+N_OW+N_F1+N_F2)/256, 256>>>(ipw, ow, f1w, f2w, wh);

    embed_k<<<(TOK*EE)/256, 256>>>(seq, tok_emb, xh);
    bias_k<<<(int)(((long long)NZ*SSS)/256), 256>>>(squares, seq, dist, bmh);

    for (int l = 0; l < LL; l++) {
        // qkv = x @ in_proj_w^T + b      [8192,1536] K=512
        hgemm<__half,0><<<dim3(12,64), 256, GEMM_SMEM>>>(
            xh, iph + (long long)l*3*EE*EE, ipb + l*3*EE, qkvh, EE, EE, EE, 3*EE);

        // fused attention: ctx = softmax(0.125*QK^T + biasm) @ V
        flash_h<<<dim3(4, NZ), 256, FLASH_SMEM>>>(qkvh, bmh, ctxh);

        // attn_out = ctx @ out_w^T + b   [8192,512] K=512   (fp32 out)
        hgemm<float,0><<<dim3(4,64), 256, GEMM_SMEM>>>(
            ctxh, owh + (long long)l*EE*EE, ob + l*EE, y, EE, EE, EE, EE);

        add_ln_k<<<TOK, EE>>>(xh, y, l1w + l*EE, l1b + l*EE);

        // h = gelu(x @ ff1_w^T + b)      [8192,2048] K=512
        hgemm<__half,1><<<dim3(16,64), 256, GEMM_SMEM>>>(
            xh, f1h + (long long)l*FFD*EE, f1b + l*FFD, ffh, EE, EE, EE, FFD);

        // ff = h @ ff2_w^T + b           [8192,512] K=2048  (fp32 out)
        hgemm<float,0><<<dim3(4,64), 256, GEMM_SMEM>>>(
            ffh, f2h + (long long)l*EE*FFD, f2b + l*EE, y, FFD, FFD, FFD, EE);

        add_ln_k<<<TOK, EE>>>(xh, y, l2w + l*EE, l2b + l*EE);
    }

    ln_final_k<<<TOK, EE>>>(xh, lfw, lfb, out);

    if (out_size >= TOK*EE + TOK)
        mask_k<<<TOK/256, 256>>>(seq, out + (long long)TOK*EE);
}

// round 11
// speedup vs baseline: 5.0323x; 1.0059x over previous
#include <cuda_runtime.h>
#include <cuda_fp16.h>
#include <math.h>
#include <stdint.h>

// Fixed shapes for BaseEncoder_68702296867023
#define BB 16
#define SS 512
#define EE 512
#define HH 8
#define FFD 2048
#define LL 6
#define DH 64
#define TOK (BB*SS)              // 8192 tokens
#define NZ (BB*HH)               // 128 attention batches
#define SSS ((long long)SS*SS)

// ---------------------------------------------------------------------------
// Scratch (device globals; no allocations allowed)
// ---------------------------------------------------------------------------
__device__ __half g_xh[TOK*EE];               // activations (half)     8 MB
__device__ __half g_qkvh[TOK*3*EE];           // qkv (half)            24 MB
__device__ __half g_biasmh[NZ*SS*SS];         // rel-dist bias+mask    67 MB
__device__ __half g_ctxh[TOK*EE];             // attention ctx (half)   8 MB
__device__ __half g_ffh[TOK*FFD];             // FF hidden (half)      32 MB
__device__ float  g_y[TOK*EE];                // residual branch (f32) 16 MB
__device__ __half g_wh[18874368];             // fp16 weights          38 MB

#define N_IP (LL*3*EE*EE)
#define N_OW (LL*EE*EE)
#define N_F1 (LL*FFD*EE)
#define N_F2 (LL*EE*FFD)

// ---------------------------------------------------------------------------
__device__ __forceinline__ void mma16(float c[4], const uint32_t a[4],
                                      uint32_t b0, uint32_t b1)
{
    asm volatile(
        "mma.sync.aligned.m16n8k16.row.col.f32.f16.f16.f32 "
        "{%0,%1,%2,%3},{%4,%5,%6,%7},{%8,%9},{%0,%1,%2,%3};\n"
        : "+f"(c[0]), "+f"(c[1]), "+f"(c[2]), "+f"(c[3])
        : "r"(a[0]), "r"(a[1]), "r"(a[2]), "r"(a[3]), "r"(b0), "r"(b1));
}

__device__ __forceinline__ void cpa16(uint32_t s, const void* g)
{
    asm volatile("cp.async.cg.shared.global [%0], [%1], 16;\n" :: "r"(s), "l"(g));
}
#define CP_COMMIT() asm volatile("cp.async.commit_group;\n")
#define CP_WAIT(N)  asm volatile("cp.async.wait_group %0;\n" :: "n"(N))

#define LDSM4(r0,r1,r2,r3,addr) \
    asm volatile("ldmatrix.sync.aligned.m8n8.x4.shared.b16 {%0,%1,%2,%3}, [%4];" \
                 : "=r"(r0),"=r"(r1),"=r"(r2),"=r"(r3) : "r"(addr))
#define LDSM2(r0,r1,addr) \
    asm volatile("ldmatrix.sync.aligned.m8n8.x2.shared.b16 {%0,%1}, [%2];" \
                 : "=r"(r0),"=r"(r1) : "r"(addr))

// ---------------------------------------------------------------------------
// fp16 tensor-core GEMM (m16n8k16), 128x128 tile, BK=32, 4-stage cp.async,
// ldmatrix fragment loads. (Proven R8 structure; pipeline deepened 3->4.)
//   C[m,n] = A[m,:].B[n,:] + bias[n] (gelu) ; A [M,K], B [N,K] K-major half.
//   smem stage: A 128x40h + B 128x40h = 20480 B; 4 stages = 81920 B.
// ---------------------------------------------------------------------------
template<typename OutT, int EPI>
__global__ void __launch_bounds__(256)
hgemm(const __half* __restrict__ A, const __half* __restrict__ B,
      const float* __restrict__ bias, OutT* __restrict__ C,
      int K, int lda, int ldb, int ldc)
{
    extern __shared__ __align__(16) char dsm[];
    const uint32_t sb = (uint32_t)__cvta_generic_to_shared(dsm);
    const int tid = threadIdx.x;
    const int m0 = blockIdx.y * 128, n0 = blockIdx.x * 128;
    const int warp = tid >> 5, lane = tid & 31;
    const int g = lane >> 2, tg = lane & 3;
    const int wx = warp & 3, wy = warp >> 2;      // 4x2 grid: 64x32 warp tiles
    const int wm0 = wy * 64, wn0 = wx * 32;
    const int lr = tid >> 2, lc = (tid & 3) * 8;  // loader row / k-chunk (halfs)

    // ldmatrix per-lane offsets (bytes, within stage)
    const uint32_t aoff = (uint32_t)(((wm0 + ((lane>>3)&1)*8 + (lane&7)) * 40
                                      + (lane>>4)*8) * 2);
    const uint32_t boff = (uint32_t)(10240 + ((wn0 + (lane&7)) * 40
                                      + ((lane>>3)&1)*8) * 2);

    auto prefetch = [&](int t) {
        const int k0 = t * 32;
        const uint32_t st = sb + (uint32_t)((t % 4) * 20480);
#pragma unroll
        for (int i = 0; i < 2; i++) {
            const int r = i * 64 + lr;
            cpa16(st + (uint32_t)(r*80 + lc*2),
                  &A[(long long)(m0 + r) * lda + k0 + lc]);
            cpa16(st + (uint32_t)(10240 + r*80 + lc*2),
                  &B[(long long)(n0 + r) * ldb + k0 + lc]);
        }
    };

    float acc[4][4][4];
#pragma unroll
    for (int i = 0; i < 4; i++)
#pragma unroll
        for (int j = 0; j < 4; j++)
#pragma unroll
            for (int c = 0; c < 4; c++) acc[i][j][c] = 0.f;

    const int nb = K / 32;        // all call sites have nb >= 16
    prefetch(0); CP_COMMIT();
    prefetch(1); CP_COMMIT();
    prefetch(2); CP_COMMIT();

    for (int t = 0; t < nb; t++) {
        CP_WAIT(2);
        __syncthreads();
        if (t + 3 < nb) prefetch(t + 3);
        CP_COMMIT();
        const uint32_t st = sb + (uint32_t)((t % 4) * 20480);
#pragma unroll
        for (int kb = 0; kb < 32; kb += 16) {
            uint32_t a[4][4], bf[4][2];
#pragma unroll
            for (int i = 0; i < 4; i++)
                LDSM4(a[i][0], a[i][1], a[i][2], a[i][3],
                      st + aoff + (uint32_t)(i*1280 + kb*2));
#pragma unroll
            for (int j = 0; j < 4; j++)
                LDSM2(bf[j][0], bf[j][1],
                      st + boff + (uint32_t)(j*640 + kb*2));
#pragma unroll
            for (int i = 0; i < 4; i++)
#pragma unroll
                for (int j = 0; j < 4; j++)
                    mma16(acc[i][j], a[i], bf[j][0], bf[j][1]);
        }
    }

    // epilogue
#pragma unroll
    for (int i = 0; i < 4; i++) {
#pragma unroll
        for (int j = 0; j < 4; j++) {
#pragma unroll
            for (int hh = 0; hh < 2; hh++) {
                const long long r = m0 + wm0 + i*16 + g + hh*8;
                const int c = n0 + wn0 + j*8 + 2*tg;
                float vx = acc[i][j][hh*2 + 0] + bias[c];
                float vy = acc[i][j][hh*2 + 1] + bias[c+1];
                if (EPI == 1) {
                    vx = 0.5f*vx*(1.f + erff(vx*0.70710678118654752f));
                    vy = 0.5f*vy*(1.f + erff(vy*0.70710678118654752f));
                }
                if (sizeof(OutT) == 2) {
                    *(__half2*)&((__half*)C)[r*ldc + c] = __floats2half2_rn(vx, vy);
                } else {
                    float2 v2; v2.x = vx; v2.y = vy;
                    *(float2*)&((float*)C)[r*ldc + c] = v2;
                }
            }
        }
    }
}

// ---------------------------------------------------------------------------
// Fused flash attention, fp16 operands / fp32 softmax, fp16 bias (R8-proven).
// smem (bytes): Ks half[128][72] @0 (18432); Vt half[64][136] @18432 (17408);
//   warp regions @35840 + w*4352: bias/P half[16][136] alias;
//   Q staging half[128][72] aliased @35840.  Total 70656 B.
// ---------------------------------------------------------------------------
__global__ void __launch_bounds__(256)
flash_h(const __half* __restrict__ qkvh, const __half* __restrict__ biasmh,
        __half* __restrict__ ctxh)
{
    extern __shared__ __align__(16) char dsm[];
    __half* Ks = (__half*)dsm;
    __half* Vt = (__half*)(dsm + 18432);

    const int tid = threadIdx.x, lane = tid & 31, w = tid >> 5;
    const int g = lane >> 2, tg = lane & 3;
    const int qt = blockIdx.x;          // 0..3
    const int z  = blockIdx.y;          // b*H + h
    const int b  = z >> 3, h = z & 7;
    const int q0 = qt * 128;
    const int qr = w * 16;

    __half* wrh = (__half*)(dsm + 35840 + w * 4352);
    const uint32_t wr_u32 = (uint32_t)__cvta_generic_to_shared(wrh);

    const __half* qh = qkvh + (long long)(b * SS) * 1536 + h * 64;
    const __half* kh = qh + 512;
    const __half* vh = qh + 1024;

    // ---- stage Q, extract a-frags ----
    {
        __half* Qs = (__half*)(dsm + 35840);
#pragma unroll
        for (int i = 0; i < 4; i++) {
            const int id = tid + i * 256;          // < 1024
            const int r = id >> 3, c8 = (id & 7) * 8;
            *(float4*)&Qs[r * 72 + c8] =
                *(const float4*)&qh[(long long)(q0 + r) * 1536 + c8];
        }
        __syncthreads();
    }
    uint32_t qa[4][4];
    {
        const __half* Qs = (const __half*)(dsm + 35840);
#pragma unroll
        for (int ks = 0; ks < 4; ks++) {
            const int r0 = (qr + g) * 72, r1 = (qr + g + 8) * 72;
            qa[ks][0] = *(const uint32_t*)&Qs[r0 + ks*16 + 2*tg];
            qa[ks][1] = *(const uint32_t*)&Qs[r1 + ks*16 + 2*tg];
            qa[ks][2] = *(const uint32_t*)&Qs[r0 + ks*16 + 2*tg + 8];
            qa[ks][3] = *(const uint32_t*)&Qs[r1 + ks*16 + 2*tg + 8];
        }
    }

    float mrun[2] = {-INFINITY, -INFINITY};
    float lrun[2] = {0.f, 0.f};
    float oacc[8][4];
#pragma unroll
    for (int n = 0; n < 8; n++)
#pragma unroll
        for (int c = 0; c < 4; c++) oacc[n][c] = 0.f;

    const __half* Bz = biasmh + (long long)z * SSS + (long long)(q0 + qr) * SS;

    for (int kt = 0; kt < 4; kt++) {
        __syncthreads();    // prior-tile consumers done; Q staging consumed
        // K tile [128 keys][64 dh]
#pragma unroll
        for (int i = 0; i < 4; i++) {
            const int id = tid + i * 256;
            const int r = id >> 3, c8 = (id & 7) * 8;
            *(float4*)&Ks[r * 72 + c8] =
                *(const float4*)&kh[(long long)(kt*128 + r) * 1536 + c8];
        }
        // V tile transposed -> Vt[dh][key]
        {
            const int dg = tid >> 6;        // dh group of 16
            const int kp = tid & 63;        // key pair
            const __half* vp = vh + (long long)(kt*128 + 2*kp) * 1536 + dg*16;
            float4 x0 = *(const float4*)(vp);
            float4 x1 = *(const float4*)(vp + 8);
            float4 y0 = *(const float4*)(vp + 1536);
            float4 y1 = *(const float4*)(vp + 1536 + 8);
            const __half* h0 = (const __half*)&x0;
            const __half* h1 = (const __half*)&x1;
            const __half* j0 = (const __half*)&y0;
            const __half* j1 = (const __half*)&y1;
#pragma unroll
            for (int d = 0; d < 8; d++) {
                *(__half2*)&Vt[(dg*16 +     d)*136 + 2*kp] = __halves2half2(h0[d], j0[d]);
                *(__half2*)&Vt[(dg*16 + 8 + d)*136 + 2*kp] = __halves2half2(h1[d], j1[d]);
            }
        }
        // bias tile [16 q][128 k] half into warp region (stride 136 halfs)
#pragma unroll
        for (int p = 0; p < 8; p++) {
            const int c = p * 32 + lane;            // < 256
            const int r = c >> 4, cc8 = (c & 15) * 8;
            cpa16(wr_u32 + (uint32_t)((r * 136 + cc8) * 2),
                  &Bz[(long long)r * SS + kt * 128 + cc8]);
        }
        CP_COMMIT();
        __syncthreads();

        // ---- S = Q.K^T (fp16 mma) ----
        float sacc[16][4];
#pragma unroll
        for (int n = 0; n < 16; n++)
#pragma unroll
            for (int c = 0; c < 4; c++) sacc[n][c] = 0.f;
#pragma unroll
        for (int ks = 0; ks < 4; ks++) {
#pragma unroll
            for (int n = 0; n < 16; n++) {
                const int rn = (n*8 + g) * 72;
                const uint32_t b0 = *(const uint32_t*)&Ks[rn + ks*16 + 2*tg];
                const uint32_t b1 = *(const uint32_t*)&Ks[rn + ks*16 + 2*tg + 8];
                mma16(sacc[n], qa[ks], b0, b1);
            }
        }

        // ---- *0.125 (exact) + bias, online softmax (fp32) ----
        CP_WAIT(0);
        __syncwarp();
        float tmax0 = -INFINITY, tmax1 = -INFINITY;
#pragma unroll
        for (int n = 0; n < 16; n++) {
            const float2 bv0 = __half22float2(*(__half2*)&wrh[ g      * 136 + n*8 + 2*tg]);
            const float2 bv1 = __half22float2(*(__half2*)&wrh[(g + 8) * 136 + n*8 + 2*tg]);
            sacc[n][0] = sacc[n][0]*0.125f + bv0.x;
            sacc[n][1] = sacc[n][1]*0.125f + bv0.y;
            sacc[n][2] = sacc[n][2]*0.125f + bv1.x;
            sacc[n][3] = sacc[n][3]*0.125f + bv1.y;
            tmax0 = fmaxf(tmax0, fmaxf(sacc[n][0], sacc[n][1]));
            tmax1 = fmaxf(tmax1, fmaxf(sacc[n][2], sacc[n][3]));
        }
        tmax0 = fmaxf(tmax0, __shfl_xor_sync(0xffffffffu, tmax0, 1));
        tmax0 = fmaxf(tmax0, __shfl_xor_sync(0xffffffffu, tmax0, 2));
        tmax1 = fmaxf(tmax1, __shfl_xor_sync(0xffffffffu, tmax1, 1));
        tmax1 = fmaxf(tmax1, __shfl_xor_sync(0xffffffffu, tmax1, 2));

        const float mnew0 = fmaxf(mrun[0], tmax0);
        const float mnew1 = fmaxf(mrun[1], tmax1);
        const float scl0 = __expf(mrun[0] - mnew0);
        const float scl1 = __expf(mrun[1] - mnew1);
        float ts0 = 0.f, ts1 = 0.f;
#pragma unroll
        for (int n = 0; n < 16; n++) {
            sacc[n][0] = __expf(sacc[n][0] - mnew0);
            sacc[n][1] = __expf(sacc[n][1] - mnew0);
            sacc[n][2] = __expf(sacc[n][2] - mnew1);
            sacc[n][3] = __expf(sacc[n][3] - mnew1);
            ts0 += sacc[n][0] + sacc[n][1];
            ts1 += sacc[n][2] + sacc[n][3];
        }
        ts0 += __shfl_xor_sync(0xffffffffu, ts0, 1);
        ts0 += __shfl_xor_sync(0xffffffffu, ts0, 2);
        ts1 += __shfl_xor_sync(0xffffffffu, ts1, 1);
        ts1 += __shfl_xor_sync(0xffffffffu, ts1, 2);
        lrun[0] = lrun[0] * scl0 + ts0;
        lrun[1] = lrun[1] * scl1 + ts1;
        mrun[0] = mnew0; mrun[1] = mnew1;
#pragma unroll
        for (int n = 0; n < 8; n++) {
            oacc[n][0] *= scl0; oacc[n][1] *= scl0;
            oacc[n][2] *= scl1; oacc[n][3] *= scl1;
        }

        // ---- P (half) into warp region (alias), then P.V ----
        __syncwarp();   // bias reads complete before alias overwrite
#pragma unroll
        for (int n = 0; n < 16; n++) {
            *(__half2*)&wrh[ g      * 136 + n*8 + 2*tg] = __floats2half2_rn(sacc[n][0], sacc[n][1]);
            *(__half2*)&wrh[(g + 8) * 136 + n*8 + 2*tg] = __floats2half2_rn(sacc[n][2], sacc[n][3]);
        }
        __syncwarp();
#pragma unroll
        for (int ks = 0; ks < 8; ks++) {
            uint32_t pa[4];
            pa[0] = *(const uint32_t*)&wrh[ g      * 136 + ks*16 + 2*tg];
            pa[1] = *(const uint32_t*)&wrh[(g + 8) * 136 + ks*16 + 2*tg];
            pa[2] = *(const uint32_t*)&wrh[ g      * 136 + ks*16 + 2*tg + 8];
            pa[3] = *(const uint32_t*)&wrh[(g + 8) * 136 + ks*16 + 2*tg + 8];
#pragma unroll
            for (int n = 0; n < 8; n++) {
                const int rn = (n*8 + g) * 136;
                const uint32_t b0 = *(const uint32_t*)&Vt[rn + ks*16 + 2*tg];
                const uint32_t b1 = *(const uint32_t*)&Vt[rn + ks*16 + 2*tg + 8];
                mma16(oacc[n], pa, b0, b1);
            }
        }
    }

    // ---- normalize and write ctx (half) ----
    const float inv0 = 1.f / lrun[0];
    const float inv1 = 1.f / lrun[1];
    const int t0 = b * SS + q0 + qr;
#pragma unroll
    for (int n = 0; n < 8; n++) {
        const int col = h * 64 + n * 8 + 2 * tg;
        *(__half2*)&ctxh[(long long)(t0 + g    ) * EE + col] =
            __floats2half2_rn(oacc[n][0] * inv0, oacc[n][1] * inv0);
        *(__half2*)&ctxh[(long long)(t0 + g + 8) * EE + col] =
            __floats2half2_rn(oacc[n][2] * inv1, oacc[n][3] * inv1);
    }
}

// ---------------------------------------------------------------------------
__global__ void convw4_k(const float* __restrict__ s0, const float* __restrict__ s1,
                         const float* __restrict__ s2, const float* __restrict__ s3,
                         __half* __restrict__ dst)
{
    const int i = blockIdx.x * blockDim.x + threadIdx.x;
    float v;
    if      (i < N_IP)                  v = s0[i];
    else if (i < N_IP + N_OW)           v = s1[i - N_IP];
    else if (i < N_IP + N_OW + N_F1)    v = s2[i - N_IP - N_OW];
    else                                v = s3[i - N_IP - N_OW - N_F1];
    dst[i] = __float2half_rn(v);
}

__global__ void embed_k(const int* __restrict__ seq, const float* __restrict__ emb,
                        __half* __restrict__ xh)
{
    int i = blockIdx.x * blockDim.x + threadIdx.x;
    int e = i & (EE-1);
    int t = i >> 9;
    xh[i] = __float2half_rn(emb[seq[t]*EE + e] * 22.627416997969522f);
}

__global__ void bias_k(const int* __restrict__ squares, const int* __restrict__ seq,
                       const float* __restrict__ dist, __half* __restrict__ bias)
{
    long long i = (long long)blockIdx.x * blockDim.x + threadIdx.x;
    int k = (int)(i & (SS-1));
    long long r = i >> 9;
    int q = (int)(r & (SS-1)); r >>= 9;
    int h = (int)(r & (HH-1));
    int b = (int)(r >> 3);
    float m = (seq[b*SS + k] == 0) ? -60000.f : 0.f;
    bias[i] = __float2half_rn(dist[squares[((long long)(b*SS + q) << 9) + k]*HH + h] + m);
}

// ---------------------------------------------------------------------------
__device__ __forceinline__ void block_ln_stats(float v, float& mean, float& var)
{
    float s = v, q = v*v;
#pragma unroll
    for (int o = 16; o > 0; o >>= 1) {
        s += __shfl_xor_sync(0xffffffffu, s, o);
        q += __shfl_xor_sync(0xffffffffu, q, o);
    }
    __shared__ float shs[16], shq[16];
    const int wid = threadIdx.x >> 5, lane = threadIdx.x & 31;
    if (lane == 0) { shs[wid] = s; shq[wid] = q; }
    __syncthreads();
    if (threadIdx.x < 32) {
        float ss = (lane < 16) ? shs[lane] : 0.f;
        float qq = (lane < 16) ? shq[lane] : 0.f;
#pragma unroll
        for (int o = 8; o > 0; o >>= 1) {
            ss += __shfl_xor_sync(0xffffffffu, ss, o);
            qq += __shfl_xor_sync(0xffffffffu, qq, o);
        }
        if (lane == 0) { shs[0] = ss; shq[0] = qq; }
    }
    __syncthreads();
    mean = shs[0] * (1.f/EE);
    var  = shq[0] * (1.f/EE) - mean*mean;
}

__global__ void add_ln_k(__half* __restrict__ xh, const float* __restrict__ y,
                         const float* __restrict__ w, const float* __restrict__ b)
{
    const long long base = (long long)blockIdx.x * EE;
    const int t = threadIdx.x;
    float v = __half2float(xh[base + t]) + y[base + t];
    float mean, var;
    block_ln_stats(v, mean, var);
    xh[base + t] = __float2half_rn((v - mean) * rsqrtf(var + 1e-5f) * w[t] + b[t]);
}

__global__ void ln_final_k(const __half* __restrict__ xh, const float* __restrict__ w,
                           const float* __restrict__ b, float* __restrict__ out)
{
    const int row = blockIdx.x;
    const int bi = row >> 9, si = row & (SS-1);
    const int t = threadIdx.x;
    float v = __half2float(xh[(long long)row*EE + t]);
    float mean, var;
    block_ln_stats(v, mean, var);
    out[((long long)si*BB + bi)*EE + t] = (v - mean) * rsqrtf(var + 1e-5f) * w[t] + b[t];
}

__global__ void mask_k(const int* __restrict__ seq, float* __restrict__ out)
{
    int i = blockIdx.x * blockDim.x + threadIdx.x;
    out[i] = (seq[i] == 0) ? 1.f : 0.f;
}

// ---------------------------------------------------------------------------
extern "C" void kernel_launch(void* const* d_in, const int* in_sizes, int n_in,
                              void* d_out, int out_size)
{
    const int*   seq     = (const int*)  d_in[0];
    const int*   squares = (const int*)  d_in[1];
    const float* tok_emb = (const float*)d_in[2];
    const float* dist    = (const float*)d_in[3];
    const float* ipw     = (const float*)d_in[4];
    const float* ipb     = (const float*)d_in[5];
    const float* ow      = (const float*)d_in[6];
    const float* ob      = (const float*)d_in[7];
    const float* f1w     = (const float*)d_in[8];
    const float* f1b     = (const float*)d_in[9];
    const float* f2w     = (const float*)d_in[10];
    const float* f2b     = (const float*)d_in[11];
    const float* l1w     = (const float*)d_in[12];
    const float* l1b     = (const float*)d_in[13];
    const float* l2w     = (const float*)d_in[14];
    const float* l2b     = (const float*)d_in[15];
    const float* lfw     = (const float*)d_in[16];
    const float* lfb     = (const float*)d_in[17];
    float* out = (float*)d_out;

    __half *xh,*qkvh,*bmh,*ctxh,*ffh,*wh;
    float *y;
    cudaGetSymbolAddress((void**)&xh,   g_xh);
    cudaGetSymbolAddress((void**)&qkvh, g_qkvh);
    cudaGetSymbolAddress((void**)&bmh,  g_biasmh);
    cudaGetSymbolAddress((void**)&ctxh, g_ctxh);
    cudaGetSymbolAddress((void**)&ffh,  g_ffh);
    cudaGetSymbolAddress((void**)&y,    g_y);
    cudaGetSymbolAddress((void**)&wh,   g_wh);

    const int GEMM_SMEM  = 4 * 20480;     // 81920
    const int FLASH_SMEM = 70656;
    cudaFuncSetAttribute(hgemm<__half,0>, cudaFuncAttributeMaxDynamicSharedMemorySize, GEMM_SMEM);
    cudaFuncSetAttribute(hgemm<__half,1>, cudaFuncAttributeMaxDynamicSharedMemorySize, GEMM_SMEM);
    cudaFuncSetAttribute(hgemm<float,0>,  cudaFuncAttributeMaxDynamicSharedMemorySize, GEMM_SMEM);
    cudaFuncSetAttribute(flash_h,         cudaFuncAttributeMaxDynamicSharedMemorySize, FLASH_SMEM);

    __half* iph = wh;
    __half* owh = iph + N_IP;
    __half* f1h = owh + N_OW;
    __half* f2h = f1h + N_F1;
    convw4_k<<<(N_IP+N_OW+N_F1+N_F2)/256, 256>>>(ipw, ow, f1w, f2w, wh);

    embed_k<<<(TOK*EE)/256, 256>>>(seq, tok_emb, xh);
    bias_k<<<(int)(((long long)NZ*SSS)/256), 256>>>(squares, seq, dist, bmh);

    for (int l = 0; l < LL; l++) {
        // qkv = x @ in_proj_w^T + b      [8192,1536] K=512
        hgemm<__half,0><<<dim3(12,64), 256, GEMM_SMEM>>>(
            xh, iph + (long long)l*3*EE*EE, ipb + l*3*EE, qkvh, EE, EE, EE, 3*EE);

        // fused attention: ctx = softmax(0.125*QK^T + biasm) @ V
        flash_h<<<dim3(4, NZ), 256, FLASH_SMEM>>>(qkvh, bmh, ctxh);

        // attn_out = ctx @ out_w^T + b   [8192,512] K=512   (fp32 out)
        hgemm<float,0><<<dim3(4,64), 256, GEMM_SMEM>>>(
            ctxh, owh + (long long)l*EE*EE, ob + l*EE, y, EE, EE, EE, EE);

        add_ln_k<<<TOK, EE>>>(xh, y, l1w + l*EE, l1b + l*EE);

        // h = gelu(x @ ff1_w^T + b)      [8192,2048] K=512
        hgemm<__half,1><<<dim3(16,64), 256, GEMM_SMEM>>>(
            xh, f1h + (long long)l*FFD*EE, f1b + l*FFD, ffh, EE, EE, EE, FFD);

        // ff = h @ ff2_w^T + b           [8192,512] K=2048  (fp32 out)
        hgemm<float,0><<<dim3(4,64), 256, GEMM_SMEM>>>(
            ffh, f2h + (long long)l*EE*FFD, f2b + l*EE, y, FFD, FFD, FFD, EE);

        add_ln_k<<<TOK, EE>>>(xh, y, l2w + l*EE, l2b + l*EE);
    }

    ln_final_k<<<TOK, EE>>>(xh, lfw, lfb, out);

    if (out_size >= TOK*EE + TOK)
        mask_k<<<TOK/256, 256>>>(seq, out + (long long)TOK*EE);
}

// round 12
// speedup vs baseline: 5.1008x; 1.0136x over previous
#include <cuda_runtime.h>
#include <cuda_fp16.h>
#include <math.h>
#include <stdint.h>

// Fixed shapes for BaseEncoder_68702296867023
#define BB 16
#define SS 512
#define EE 512
#define HH 8
#define FFD 2048
#define LL 6
#define DH 64
#define TOK (BB*SS)              // 8192 tokens
#define NZ (BB*HH)               // 128 attention batches
#define SSS ((long long)SS*SS)

// ---------------------------------------------------------------------------
// Scratch (device globals; no allocations allowed)
// ---------------------------------------------------------------------------
__device__ __half g_xh[TOK*EE];               // activations (half)     8 MB
__device__ __half g_qkvh[TOK*3*EE];           // qkv (half)            24 MB
__device__ __half g_biasmh[NZ*SS*SS];         // rel-dist bias+mask    67 MB
__device__ __half g_ctxh[TOK*EE];             // attention ctx (half)   8 MB
__device__ __half g_ffh[TOK*FFD];             // FF hidden (half)      32 MB
__device__ float  g_y[TOK*EE];                // residual branch (f32) 16 MB
__device__ __half g_wh[18874368];             // fp16 weights          38 MB

#define N_IP (LL*3*EE*EE)
#define N_OW (LL*EE*EE)
#define N_F1 (LL*FFD*EE)
#define N_F2 (LL*EE*FFD)

// ---------------------------------------------------------------------------
__device__ __forceinline__ void mma16(float c[4], const uint32_t a[4],
                                      uint32_t b0, uint32_t b1)
{
    asm volatile(
        "mma.sync.aligned.m16n8k16.row.col.f32.f16.f16.f32 "
        "{%0,%1,%2,%3},{%4,%5,%6,%7},{%8,%9},{%0,%1,%2,%3};\n"
        : "+f"(c[0]), "+f"(c[1]), "+f"(c[2]), "+f"(c[3])
        : "r"(a[0]), "r"(a[1]), "r"(a[2]), "r"(a[3]), "r"(b0), "r"(b1));
}

__device__ __forceinline__ void cpa16(uint32_t s, const void* g)
{
    asm volatile("cp.async.cg.shared.global [%0], [%1], 16;\n" :: "r"(s), "l"(g));
}
#define CP_COMMIT() asm volatile("cp.async.commit_group;\n")
#define CP_WAIT(N)  asm volatile("cp.async.wait_group %0;\n" :: "n"(N))

#define LDSM4(r0,r1,r2,r3,addr) \
    asm volatile("ldmatrix.sync.aligned.m8n8.x4.shared.b16 {%0,%1,%2,%3}, [%4];" \
                 : "=r"(r0),"=r"(r1),"=r"(r2),"=r"(r3) : "r"(addr))
#define LDSM2(r0,r1,addr) \
    asm volatile("ldmatrix.sync.aligned.m8n8.x2.shared.b16 {%0,%1}, [%2];" \
                 : "=r"(r0),"=r"(r1) : "r"(addr))

// ---------------------------------------------------------------------------
// fp16 tensor-core GEMM (m16n8k16), 128x128 tile, BK=32, 4-stage cp.async.
// 512 threads / 16 warps, 32x32 warp tiles (low regs -> 2 CTAs/SM, 32 warps).
//   C[m,n] = A[m,:].B[n,:] + bias[n] (gelu) ; A [M,K], B [N,K] K-major half.
//   smem stage: A 128x40h + B 128x40h = 20480 B; 4 stages = 81920 B.
// ---------------------------------------------------------------------------
template<typename OutT, int EPI>
__global__ void __launch_bounds__(512)
hgemm(const __half* __restrict__ A, const __half* __restrict__ B,
      const float* __restrict__ bias, OutT* __restrict__ C,
      int K, int lda, int ldb, int ldc)
{
    extern __shared__ __align__(16) char dsm[];
    const uint32_t sb = (uint32_t)__cvta_generic_to_shared(dsm);
    const int tid = threadIdx.x;
    const int m0 = blockIdx.y * 128, n0 = blockIdx.x * 128;
    const int warp = tid >> 5, lane = tid & 31;
    const int g = lane >> 2, tg = lane & 3;
    const int wx = warp & 3, wy = warp >> 2;      // 4x4 grid: 32x32 warp tiles
    const int wm0 = wy * 32, wn0 = wx * 32;
    const int lr = tid >> 2, lc = (tid & 3) * 8;  // loader: one cpa16/thread

    // ldmatrix per-lane offsets (bytes, within stage) — same formulas as R8
    const uint32_t aoff = (uint32_t)(((wm0 + ((lane>>3)&1)*8 + (lane&7)) * 40
                                      + (lane>>4)*8) * 2);
    const uint32_t boff = (uint32_t)(10240 + ((wn0 + (lane&7)) * 40
                                      + ((lane>>3)&1)*8) * 2);

    auto prefetch = [&](int t) {
        const int k0 = t * 32;
        const uint32_t st = sb + (uint32_t)((t % 4) * 20480);
        cpa16(st + (uint32_t)(lr*80 + lc*2),
              &A[(long long)(m0 + lr) * lda + k0 + lc]);
        cpa16(st + (uint32_t)(10240 + lr*80 + lc*2),
              &B[(long long)(n0 + lr) * ldb + k0 + lc]);
    };

    float acc[2][4][4];
#pragma unroll
    for (int i = 0; i < 2; i++)
#pragma unroll
        for (int j = 0; j < 4; j++)
#pragma unroll
            for (int c = 0; c < 4; c++) acc[i][j][c] = 0.f;

    const int nb = K / 32;        // all call sites have nb >= 16
    prefetch(0); CP_COMMIT();
    prefetch(1); CP_COMMIT();
    prefetch(2); CP_COMMIT();

    for (int t = 0; t < nb; t++) {
        CP_WAIT(2);
        __syncthreads();
        if (t + 3 < nb) prefetch(t + 3);
        CP_COMMIT();
        const uint32_t st = sb + (uint32_t)((t % 4) * 20480);
#pragma unroll
        for (int kb = 0; kb < 32; kb += 16) {
            uint32_t a[2][4], bf[4][2];
#pragma unroll
            for (int i = 0; i < 2; i++)
                LDSM4(a[i][0], a[i][1], a[i][2], a[i][3],
                      st + aoff + (uint32_t)(i*1280 + kb*2));
#pragma unroll
            for (int j = 0; j < 4; j++)
                LDSM2(bf[j][0], bf[j][1],
                      st + boff + (uint32_t)(j*640 + kb*2));
#pragma unroll
            for (int i = 0; i < 2; i++)
#pragma unroll
                for (int j = 0; j < 4; j++)
                    mma16(acc[i][j], a[i], bf[j][0], bf[j][1]);
        }
    }

    // epilogue
#pragma unroll
    for (int i = 0; i < 2; i++) {
#pragma unroll
        for (int j = 0; j < 4; j++) {
#pragma unroll
            for (int hh = 0; hh < 2; hh++) {
                const long long r = m0 + wm0 + i*16 + g + hh*8;
                const int c = n0 + wn0 + j*8 + 2*tg;
                float vx = acc[i][j][hh*2 + 0] + bias[c];
                float vy = acc[i][j][hh*2 + 1] + bias[c+1];
                if (EPI == 1) {
                    vx = 0.5f*vx*(1.f + erff(vx*0.70710678118654752f));
                    vy = 0.5f*vy*(1.f + erff(vy*0.70710678118654752f));
                }
                if (sizeof(OutT) == 2) {
                    *(__half2*)&((__half*)C)[r*ldc + c] = __floats2half2_rn(vx, vy);
                } else {
                    float2 v2; v2.x = vx; v2.y = vy;
                    *(float2*)&((float*)C)[r*ldc + c] = v2;
                }
            }
        }
    }
}

// ---------------------------------------------------------------------------
// Fused flash attention, fp16 operands / fp32 softmax, fp16 bias (R8-proven).
// smem (bytes): Ks half[128][72] @0 (18432); Vt half[64][136] @18432 (17408);
//   warp regions @35840 + w*4352: bias/P half[16][136] alias;
//   Q staging half[128][72] aliased @35840.  Total 70656 B.
// ---------------------------------------------------------------------------
__global__ void __launch_bounds__(256)
flash_h(const __half* __restrict__ qkvh, const __half* __restrict__ biasmh,
        __half* __restrict__ ctxh)
{
    extern __shared__ __align__(16) char dsm[];
    __half* Ks = (__half*)dsm;
    __half* Vt = (__half*)(dsm + 18432);

    const int tid = threadIdx.x, lane = tid & 31, w = tid >> 5;
    const int g = lane >> 2, tg = lane & 3;
    const int qt = blockIdx.x;          // 0..3
    const int z  = blockIdx.y;          // b*H + h
    const int b  = z >> 3, h = z & 7;
    const int q0 = qt * 128;
    const int qr = w * 16;

    __half* wrh = (__half*)(dsm + 35840 + w * 4352);
    const uint32_t wr_u32 = (uint32_t)__cvta_generic_to_shared(wrh);

    const __half* qh = qkvh + (long long)(b * SS) * 1536 + h * 64;
    const __half* kh = qh + 512;
    const __half* vh = qh + 1024;

    // ---- stage Q, extract a-frags ----
    {
        __half* Qs = (__half*)(dsm + 35840);
#pragma unroll
        for (int i = 0; i < 4; i++) {
            const int id = tid + i * 256;          // < 1024
            const int r = id >> 3, c8 = (id & 7) * 8;
            *(float4*)&Qs[r * 72 + c8] =
                *(const float4*)&qh[(long long)(q0 + r) * 1536 + c8];
        }
        __syncthreads();
    }
    uint32_t qa[4][4];
    {
        const __half* Qs = (const __half*)(dsm + 35840);
#pragma unroll
        for (int ks = 0; ks < 4; ks++) {
            const int r0 = (qr + g) * 72, r1 = (qr + g + 8) * 72;
            qa[ks][0] = *(const uint32_t*)&Qs[r0 + ks*16 + 2*tg];
            qa[ks][1] = *(const uint32_t*)&Qs[r1 + ks*16 + 2*tg];
            qa[ks][2] = *(const uint32_t*)&Qs[r0 + ks*16 + 2*tg + 8];
            qa[ks][3] = *(const uint32_t*)&Qs[r1 + ks*16 + 2*tg + 8];
        }
    }

    float mrun[2] = {-INFINITY, -INFINITY};
    float lrun[2] = {0.f, 0.f};
    float oacc[8][4];
#pragma unroll
    for (int n = 0; n < 8; n++)
#pragma unroll
        for (int c = 0; c < 4; c++) oacc[n][c] = 0.f;

    const __half* Bz = biasmh + (long long)z * SSS + (long long)(q0 + qr) * SS;

    for (int kt = 0; kt < 4; kt++) {
        __syncthreads();    // prior-tile consumers done; Q staging consumed
        // K tile [128 keys][64 dh]
#pragma unroll
        for (int i = 0; i < 4; i++) {
            const int id = tid + i * 256;
            const int r = id >> 3, c8 = (id & 7) * 8;
            *(float4*)&Ks[r * 72 + c8] =
                *(const float4*)&kh[(long long)(kt*128 + r) * 1536 + c8];
        }
        // V tile transposed -> Vt[dh][key]
        {
            const int dg = tid >> 6;        // dh group of 16
            const int kp = tid & 63;        // key pair
            const __half* vp = vh + (long long)(kt*128 + 2*kp) * 1536 + dg*16;
            float4 x0 = *(const float4*)(vp);
            float4 x1 = *(const float4*)(vp + 8);
            float4 y0 = *(const float4*)(vp + 1536);
            float4 y1 = *(const float4*)(vp + 1536 + 8);
            const __half* h0 = (const __half*)&x0;
            const __half* h1 = (const __half*)&x1;
            const __half* j0 = (const __half*)&y0;
            const __half* j1 = (const __half*)&y1;
#pragma unroll
            for (int d = 0; d < 8; d++) {
                *(__half2*)&Vt[(dg*16 +     d)*136 + 2*kp] = __halves2half2(h0[d], j0[d]);
                *(__half2*)&Vt[(dg*16 + 8 + d)*136 + 2*kp] = __halves2half2(h1[d], j1[d]);
            }
        }
        // bias tile [16 q][128 k] half into warp region (stride 136 halfs)
#pragma unroll
        for (int p = 0; p < 8; p++) {
            const int c = p * 32 + lane;            // < 256
            const int r = c >> 4, cc8 = (c & 15) * 8;
            cpa16(wr_u32 + (uint32_t)((r * 136 + cc8) * 2),
                  &Bz[(long long)r * SS + kt * 128 + cc8]);
        }
        CP_COMMIT();
        __syncthreads();

        // ---- S = Q.K^T (fp16 mma) ----
        float sacc[16][4];
#pragma unroll
        for (int n = 0; n < 16; n++)
#pragma unroll
            for (int c = 0; c < 4; c++) sacc[n][c] = 0.f;
#pragma unroll
        for (int ks = 0; ks < 4; ks++) {
#pragma unroll
            for (int n = 0; n < 16; n++) {
                const int rn = (n*8 + g) * 72;
                const uint32_t b0 = *(const uint32_t*)&Ks[rn + ks*16 + 2*tg];
                const uint32_t b1 = *(const uint32_t*)&Ks[rn + ks*16 + 2*tg + 8];
                mma16(sacc[n], qa[ks], b0, b1);
            }
        }

        // ---- *0.125 (exact) + bias, online softmax (fp32) ----
        CP_WAIT(0);
        __syncwarp();
        float tmax0 = -INFINITY, tmax1 = -INFINITY;
#pragma unroll
        for (int n = 0; n < 16; n++) {
            const float2 bv0 = __half22float2(*(__half2*)&wrh[ g      * 136 + n*8 + 2*tg]);
            const float2 bv1 = __half22float2(*(__half2*)&wrh[(g + 8) * 136 + n*8 + 2*tg]);
            sacc[n][0] = sacc[n][0]*0.125f + bv0.x;
            sacc[n][1] = sacc[n][1]*0.125f + bv0.y;
            sacc[n][2] = sacc[n][2]*0.125f + bv1.x;
            sacc[n][3] = sacc[n][3]*0.125f + bv1.y;
            tmax0 = fmaxf(tmax0, fmaxf(sacc[n][0], sacc[n][1]));
            tmax1 = fmaxf(tmax1, fmaxf(sacc[n][2], sacc[n][3]));
        }
        tmax0 = fmaxf(tmax0, __shfl_xor_sync(0xffffffffu, tmax0, 1));
        tmax0 = fmaxf(tmax0, __shfl_xor_sync(0xffffffffu, tmax0, 2));
        tmax1 = fmaxf(tmax1, __shfl_xor_sync(0xffffffffu, tmax1, 1));
        tmax1 = fmaxf(tmax1, __shfl_xor_sync(0xffffffffu, tmax1, 2));

        const float mnew0 = fmaxf(mrun[0], tmax0);
        const float mnew1 = fmaxf(mrun[1], tmax1);
        const float scl0 = __expf(mrun[0] - mnew0);
        const float scl1 = __expf(mrun[1] - mnew1);
        float ts0 = 0.f, ts1 = 0.f;
#pragma unroll
        for (int n = 0; n < 16; n++) {
            sacc[n][0] = __expf(sacc[n][0] - mnew0);
            sacc[n][1] = __expf(sacc[n][1] - mnew0);
            sacc[n][2] = __expf(sacc[n][2] - mnew1);
            sacc[n][3] = __expf(sacc[n][3] - mnew1);
            ts0 += sacc[n][0] + sacc[n][1];
            ts1 += sacc[n][2] + sacc[n][3];
        }
        ts0 += __shfl_xor_sync(0xffffffffu, ts0, 1);
        ts0 += __shfl_xor_sync(0xffffffffu, ts0, 2);
        ts1 += __shfl_xor_sync(0xffffffffu, ts1, 1);
        ts1 += __shfl_xor_sync(0xffffffffu, ts1, 2);
        lrun[0] = lrun[0] * scl0 + ts0;
        lrun[1] = lrun[1] * scl1 + ts1;
        mrun[0] = mnew0; mrun[1] = mnew1;
#pragma unroll
        for (int n = 0; n < 8; n++) {
            oacc[n][0] *= scl0; oacc[n][1] *= scl0;
            oacc[n][2] *= scl1; oacc[n][3] *= scl1;
        }

        // ---- P (half) into warp region (alias), then P.V ----
        __syncwarp();   // bias reads complete before alias overwrite
#pragma unroll
        for (int n = 0; n < 16; n++) {
            *(__half2*)&wrh[ g      * 136 + n*8 + 2*tg] = __floats2half2_rn(sacc[n][0], sacc[n][1]);
            *(__half2*)&wrh[(g + 8) * 136 + n*8 + 2*tg] = __floats2half2_rn(sacc[n][2], sacc[n][3]);
        }
        __syncwarp();
#pragma unroll
        for (int ks = 0; ks < 8; ks++) {
            uint32_t pa[4];
            pa[0] = *(const uint32_t*)&wrh[ g      * 136 + ks*16 + 2*tg];
            pa[1] = *(const uint32_t*)&wrh[(g + 8) * 136 + ks*16 + 2*tg];
            pa[2] = *(const uint32_t*)&wrh[ g      * 136 + ks*16 + 2*tg + 8];
            pa[3] = *(const uint32_t*)&wrh[(g + 8) * 136 + ks*16 + 2*tg + 8];
#pragma unroll
            for (int n = 0; n < 8; n++) {
                const int rn = (n*8 + g) * 136;
                const uint32_t b0 = *(const uint32_t*)&Vt[rn + ks*16 + 2*tg];
                const uint32_t b1 = *(const uint32_t*)&Vt[rn + ks*16 + 2*tg + 8];
                mma16(oacc[n], pa, b0, b1);
            }
        }
    }

    // ---- normalize and write ctx (half) ----
    const float inv0 = 1.f / lrun[0];
    const float inv1 = 1.f / lrun[1];
    const int t0 = b * SS + q0 + qr;
#pragma unroll
    for (int n = 0; n < 8; n++) {
        const int col = h * 64 + n * 8 + 2 * tg;
        *(__half2*)&ctxh[(long long)(t0 + g    ) * EE + col] =
            __floats2half2_rn(oacc[n][0] * inv0, oacc[n][1] * inv0);
        *(__half2*)&ctxh[(long long)(t0 + g + 8) * EE + col] =
            __floats2half2_rn(oacc[n][2] * inv1, oacc[n][3] * inv1);
    }
}

// ---------------------------------------------------------------------------
__global__ void convw4_k(const float* __restrict__ s0, const float* __restrict__ s1,
                         const float* __restrict__ s2, const float* __restrict__ s3,
                         __half* __restrict__ dst)
{
    const int i = blockIdx.x * blockDim.x + threadIdx.x;
    float v;
    if      (i < N_IP)                  v = s0[i];
    else if (i < N_IP + N_OW)           v = s1[i - N_IP];
    else if (i < N_IP + N_OW + N_F1)    v = s2[i - N_IP - N_OW];
    else                                v = s3[i - N_IP - N_OW - N_F1];
    dst[i] = __float2half_rn(v);
}

__global__ void embed_k(const int* __restrict__ seq, const float* __restrict__ emb,
                        __half* __restrict__ xh)
{
    int i = blockIdx.x * blockDim.x + threadIdx.x;
    int e = i & (EE-1);
    int t = i >> 9;
    xh[i] = __float2half_rn(emb[seq[t]*EE + e] * 22.627416997969522f);
}

__global__ void bias_k(const int* __restrict__ squares, const int* __restrict__ seq,
                       const float* __restrict__ dist, __half* __restrict__ bias)
{
    long long i = (long long)blockIdx.x * blockDim.x + threadIdx.x;
    int k = (int)(i & (SS-1));
    long long r = i >> 9;
    int q = (int)(r & (SS-1)); r >>= 9;
    int h = (int)(r & (HH-1));
    int b = (int)(r >> 3);
    float m = (seq[b*SS + k] == 0) ? -60000.f : 0.f;
    bias[i] = __float2half_rn(dist[squares[((long long)(b*SS + q) << 9) + k]*HH + h] + m);
}

// ---------------------------------------------------------------------------
__device__ __forceinline__ void block_ln_stats(float v, float& mean, float& var)
{
    float s = v, q = v*v;
#pragma unroll
    for (int o = 16; o > 0; o >>= 1) {
        s += __shfl_xor_sync(0xffffffffu, s, o);
        q += __shfl_xor_sync(0xffffffffu, q, o);
    }
    __shared__ float shs[16], shq[16];
    const int wid = threadIdx.x >> 5, lane = threadIdx.x & 31;
    if (lane == 0) { shs[wid] = s; shq[wid] = q; }
    __syncthreads();
    if (threadIdx.x < 32) {
        float ss = (lane < 16) ? shs[lane] : 0.f;
        float qq = (lane < 16) ? shq[lane] : 0.f;
#pragma unroll
        for (int o = 8; o > 0; o >>= 1) {
            ss += __shfl_xor_sync(0xffffffffu, ss, o);
            qq += __shfl_xor_sync(0xffffffffu, qq, o);
        }
        if (lane == 0) { shs[0] = ss; shq[0] = qq; }
    }
    __syncthreads();
    mean = shs[0] * (1.f/EE);
    var  = shq[0] * (1.f/EE) - mean*mean;
}

__global__ void add_ln_k(__half* __restrict__ xh, const float* __restrict__ y,
                         const float* __restrict__ w, const float* __restrict__ b)
{
    const long long base = (long long)blockIdx.x * EE;
    const int t = threadIdx.x;
    float v = __half2float(xh[base + t]) + y[base + t];
    float mean, var;
    block_ln_stats(v, mean, var);
    xh[base + t] = __float2half_rn((v - mean) * rsqrtf(var + 1e-5f) * w[t] + b[t]);
}

__global__ void ln_final_k(const __half* __restrict__ xh, const float* __restrict__ w,
                           const float* __restrict__ b, float* __restrict__ out)
{
    const int row = blockIdx.x;
    const int bi = row >> 9, si = row & (SS-1);
    const int t = threadIdx.x;
    float v = __half2float(xh[(long long)row*EE + t]);
    float mean, var;
    block_ln_stats(v, mean, var);
    out[((long long)si*BB + bi)*EE + t] = (v - mean) * rsqrtf(var + 1e-5f) * w[t] + b[t];
}

__global__ void mask_k(const int* __restrict__ seq, float* __restrict__ out)
{
    int i = blockIdx.x * blockDim.x + threadIdx.x;
    out[i] = (seq[i] == 0) ? 1.f : 0.f;
}

// ---------------------------------------------------------------------------
extern "C" void kernel_launch(void* const* d_in, const int* in_sizes, int n_in,
                              void* d_out, int out_size)
{
    const int*   seq     = (const int*)  d_in[0];
    const int*   squares = (const int*)  d_in[1];
    const float* tok_emb = (const float*)d_in[2];
    const float* dist    = (const float*)d_in[3];
    const float* ipw     = (const float*)d_in[4];
    const float* ipb     = (const float*)d_in[5];
    const float* ow      = (const float*)d_in[6];
    const float* ob      = (const float*)d_in[7];
    const float* f1w     = (const float*)d_in[8];
    const float* f1b     = (const float*)d_in[9];
    const float* f2w     = (const float*)d_in[10];
    const float* f2b     = (const float*)d_in[11];
    const float* l1w     = (const float*)d_in[12];
    const float* l1b     = (const float*)d_in[13];
    const float* l2w     = (const float*)d_in[14];
    const float* l2b     = (const float*)d_in[15];
    const float* lfw     = (const float*)d_in[16];
    const float* lfb     = (const float*)d_in[17];
    float* out = (float*)d_out;

    __half *xh,*qkvh,*bmh,*ctxh,*ffh,*wh;
    float *y;
    cudaGetSymbolAddress((void**)&xh,   g_xh);
    cudaGetSymbolAddress((void**)&qkvh, g_qkvh);
    cudaGetSymbolAddress((void**)&bmh,  g_biasmh);
    cudaGetSymbolAddress((void**)&ctxh, g_ctxh);
    cudaGetSymbolAddress((void**)&ffh,  g_ffh);
    cudaGetSymbolAddress((void**)&y,    g_y);
    cudaGetSymbolAddress((void**)&wh,   g_wh);

    const int GEMM_SMEM  = 4 * 20480;     // 81920
    const int FLASH_SMEM = 70656;
    cudaFuncSetAttribute(hgemm<__half,0>, cudaFuncAttributeMaxDynamicSharedMemorySize, GEMM_SMEM);
    cudaFuncSetAttribute(hgemm<__half,1>, cudaFuncAttributeMaxDynamicSharedMemorySize, GEMM_SMEM);
    cudaFuncSetAttribute(hgemm<float,0>,  cudaFuncAttributeMaxDynamicSharedMemorySize, GEMM_SMEM);
    cudaFuncSetAttribute(flash_h,         cudaFuncAttributeMaxDynamicSharedMemorySize, FLASH_SMEM);

    __half* iph = wh;
    __half* owh = iph + N_IP;
    __half* f1h = owh + N_OW;
    __half* f2h = f1h + N_F1;
    convw4_k<<<(N_IP+N_OW+N_F1+N_F2)/256, 256>>>(ipw, ow, f1w, f2w, wh);

    embed_k<<<(TOK*EE)/256, 256>>>(seq, tok_emb, xh);
    bias_k<<<(int)(((long long)NZ*SSS)/256), 256>>>(squares, seq, dist, bmh);

    for (int l = 0; l < LL; l++) {
        // qkv = x @ in_proj_w^T + b      [8192,1536] K=512
        hgemm<__half,0><<<dim3(12,64), 512, GEMM_SMEM>>>(
            xh, iph + (long long)l*3*EE*EE, ipb + l*3*EE, qkvh, EE, EE, EE, 3*EE);

        // fused attention: ctx = softmax(0.125*QK^T + biasm) @ V
        flash_h<<<dim3(4, NZ), 256, FLASH_SMEM>>>(qkvh, bmh, ctxh);

        // attn_out = ctx @ out_w^T + b   [8192,512] K=512   (fp32 out)
        hgemm<float,0><<<dim3(4,64), 512, GEMM_SMEM>>>(
            ctxh, owh + (long long)l*EE*EE, ob + l*EE, y, EE, EE, EE, EE);

        add_ln_k<<<TOK, EE>>>(xh, y, l1w + l*EE, l1b + l*EE);

        // h = gelu(x @ ff1_w^T + b)      [8192,2048] K=512
        hgemm<__half,1><<<dim3(16,64), 512, GEMM_SMEM>>>(
            xh, f1h + (long long)l*FFD*EE, f1b + l*FFD, ffh, EE, EE, EE, FFD);

        // ff = h @ ff2_w^T + b           [8192,512] K=2048  (fp32 out)
        hgemm<float,0><<<dim3(4,64), 512, GEMM_SMEM>>>(
            ffh, f2h + (long long)l*EE*FFD, f2b + l*EE, y, FFD, FFD, FFD, EE);

        add_ln_k<<<TOK, EE>>>(xh, y, l2w + l*EE, l2b + l*EE);
    }

    ln_final_k<<<TOK, EE>>>(xh, lfw, lfb, out);

    if (out_size >= TOK*EE + TOK)
        mask_k<<<TOK/256, 256>>>(seq, out + (long long)TOK*EE);
}

// round 13
// speedup vs baseline: 5.1386x; 1.0074x over previous
#include <cuda_runtime.h>
#include <cuda_fp16.h>
#include <math.h>
#include <stdint.h>

// Fixed shapes for BaseEncoder_68702296867023
#define BB 16
#define SS 512
#define EE 512
#define HH 8
#define FFD 2048
#define LL 6
#define DH 64
#define TOK (BB*SS)              // 8192 tokens
#define NZ (BB*HH)               // 128 attention batches
#define SSS ((long long)SS*SS)

// ---------------------------------------------------------------------------
// Scratch (device globals; no allocations allowed)
// ---------------------------------------------------------------------------
__device__ __half g_xh[TOK*EE];               // activations (half)     8 MB
__device__ __half g_qkvh[TOK*3*EE];           // qkv (half)            24 MB
__device__ __half g_biasmh[NZ*SS*SS];         // rel-dist bias+mask    67 MB
__device__ __half g_ctxh[TOK*EE];             // attention ctx (half)   8 MB
__device__ __half g_ffh[TOK*FFD];             // FF hidden (half)      32 MB
__device__ float  g_part[4*TOK*EE];           // split-K partials      64 MB
__device__ __half g_wh[18874368];             // fp16 weights          38 MB

#define N_IP (LL*3*EE*EE)
#define N_OW (LL*EE*EE)
#define N_F1 (LL*FFD*EE)
#define N_F2 (LL*EE*FFD)

// ---------------------------------------------------------------------------
__device__ __forceinline__ void mma16(float c[4], const uint32_t a[4],
                                      uint32_t b0, uint32_t b1)
{
    asm volatile(
        "mma.sync.aligned.m16n8k16.row.col.f32.f16.f16.f32 "
        "{%0,%1,%2,%3},{%4,%5,%6,%7},{%8,%9},{%0,%1,%2,%3};\n"
        : "+f"(c[0]), "+f"(c[1]), "+f"(c[2]), "+f"(c[3])
        : "r"(a[0]), "r"(a[1]), "r"(a[2]), "r"(a[3]), "r"(b0), "r"(b1));
}

__device__ __forceinline__ void cpa16(uint32_t s, const void* g)
{
    asm volatile("cp.async.cg.shared.global [%0], [%1], 16;\n" :: "r"(s), "l"(g));
}
#define CP_COMMIT() asm volatile("cp.async.commit_group;\n")
#define CP_WAIT(N)  asm volatile("cp.async.wait_group %0;\n" :: "n"(N))

#define LDSM4(r0,r1,r2,r3,addr) \
    asm volatile("ldmatrix.sync.aligned.m8n8.x4.shared.b16 {%0,%1,%2,%3}, [%4];" \
                 : "=r"(r0),"=r"(r1),"=r"(r2),"=r"(r3) : "r"(addr))
#define LDSM2(r0,r1,addr) \
    asm volatile("ldmatrix.sync.aligned.m8n8.x2.shared.b16 {%0,%1}, [%2];" \
                 : "=r"(r0),"=r"(r1) : "r"(addr))

// ---------------------------------------------------------------------------
// fp16 tensor-core GEMM (m16n8k16), 128x128 tile, BK=32, 4-stage cp.async.
// 512 threads / 16 warps, 32x32 warp tiles. (R12-proven core.)
//   Split-K via blockIdx.z: A,B advance z*K along K; C advances z*pstride.
//   EPI: 0 = +bias          (OutT half or float)
//        1 = +bias, gelu    (OutT half)
//        3 = raw partial    (OutT float, no bias)
//   smem stage: A 128x40h + B 128x40h = 20480 B; 4 stages = 81920 B.
// ---------------------------------------------------------------------------
template<typename OutT, int EPI>
__global__ void __launch_bounds__(512)
hgemm(const __half* __restrict__ A, const __half* __restrict__ B,
      const float* __restrict__ bias, OutT* __restrict__ C,
      int K, int lda, int ldb, int ldc, long long pstride)
{
    extern __shared__ __align__(16) char dsm[];
    const uint32_t sb = (uint32_t)__cvta_generic_to_shared(dsm);
    const int tid = threadIdx.x;
    const int m0 = blockIdx.y * 128, n0 = blockIdx.x * 128;
    const int z = blockIdx.z;
    A += (long long)z * K;
    B += (long long)z * K;
    C += (long long)z * pstride;
    const int warp = tid >> 5, lane = tid & 31;
    const int g = lane >> 2, tg = lane & 3;
    const int wx = warp & 3, wy = warp >> 2;      // 4x4 grid: 32x32 warp tiles
    const int wm0 = wy * 32, wn0 = wx * 32;
    const int lr = tid >> 2, lc = (tid & 3) * 8;  // loader: one cpa16/thread

    const uint32_t aoff = (uint32_t)(((wm0 + ((lane>>3)&1)*8 + (lane&7)) * 40
                                      + (lane>>4)*8) * 2);
    const uint32_t boff = (uint32_t)(10240 + ((wn0 + (lane&7)) * 40
                                      + ((lane>>3)&1)*8) * 2);

    auto prefetch = [&](int t) {
        const int k0 = t * 32;
        const uint32_t st = sb + (uint32_t)((t % 4) * 20480);
        cpa16(st + (uint32_t)(lr*80 + lc*2),
              &A[(long long)(m0 + lr) * lda + k0 + lc]);
        cpa16(st + (uint32_t)(10240 + lr*80 + lc*2),
              &B[(long long)(n0 + lr) * ldb + k0 + lc]);
    };

    float acc[2][4][4];
#pragma unroll
    for (int i = 0; i < 2; i++)
#pragma unroll
        for (int j = 0; j < 4; j++)
#pragma unroll
            for (int c = 0; c < 4; c++) acc[i][j][c] = 0.f;

    const int nb = K / 32;        // all call sites have nb >= 8
    prefetch(0); CP_COMMIT();
    prefetch(1); CP_COMMIT();
    prefetch(2); CP_COMMIT();

    for (int t = 0; t < nb; t++) {
        CP_WAIT(2);
        __syncthreads();
        if (t + 3 < nb) prefetch(t + 3);
        CP_COMMIT();
        const uint32_t st = sb + (uint32_t)((t % 4) * 20480);
#pragma unroll
        for (int kb = 0; kb < 32; kb += 16) {
            uint32_t a[2][4], bf[4][2];
#pragma unroll
            for (int i = 0; i < 2; i++)
                LDSM4(a[i][0], a[i][1], a[i][2], a[i][3],
                      st + aoff + (uint32_t)(i*1280 + kb*2));
#pragma unroll
            for (int j = 0; j < 4; j++)
                LDSM2(bf[j][0], bf[j][1],
                      st + boff + (uint32_t)(j*640 + kb*2));
#pragma unroll
            for (int i = 0; i < 2; i++)
#pragma unroll
                for (int j = 0; j < 4; j++)
                    mma16(acc[i][j], a[i], bf[j][0], bf[j][1]);
        }
    }

    // epilogue
#pragma unroll
    for (int i = 0; i < 2; i++) {
#pragma unroll
        for (int j = 0; j < 4; j++) {
#pragma unroll
            for (int hh = 0; hh < 2; hh++) {
                const long long r = m0 + wm0 + i*16 + g + hh*8;
                const int c = n0 + wn0 + j*8 + 2*tg;
                float vx = acc[i][j][hh*2 + 0];
                float vy = acc[i][j][hh*2 + 1];
                if (EPI != 3) { vx += bias[c]; vy += bias[c+1]; }
                if (EPI == 1) {
                    vx = 0.5f*vx*(1.f + erff(vx*0.70710678118654752f));
                    vy = 0.5f*vy*(1.f + erff(vy*0.70710678118654752f));
                }
                if (sizeof(OutT) == 2) {
                    *(__half2*)&((__half*)C)[r*ldc + c] = __floats2half2_rn(vx, vy);
                } else {
                    float2 v2; v2.x = vx; v2.y = vy;
                    *(float2*)&((float*)C)[r*ldc + c] = v2;
                }
            }
        }
    }
}

// ---------------------------------------------------------------------------
// Fused flash attention, fp16 operands / fp32 softmax, fp16 bias (R8-proven).
// ---------------------------------------------------------------------------
__global__ void __launch_bounds__(256)
flash_h(const __half* __restrict__ qkvh, const __half* __restrict__ biasmh,
        __half* __restrict__ ctxh)
{
    extern __shared__ __align__(16) char dsm[];
    __half* Ks = (__half*)dsm;
    __half* Vt = (__half*)(dsm + 18432);

    const int tid = threadIdx.x, lane = tid & 31, w = tid >> 5;
    const int g = lane >> 2, tg = lane & 3;
    const int qt = blockIdx.x;          // 0..3
    const int z  = blockIdx.y;          // b*H + h
    const int b  = z >> 3, h = z & 7;
    const int q0 = qt * 128;
    const int qr = w * 16;

    __half* wrh = (__half*)(dsm + 35840 + w * 4352);
    const uint32_t wr_u32 = (uint32_t)__cvta_generic_to_shared(wrh);

    const __half* qh = qkvh + (long long)(b * SS) * 1536 + h * 64;
    const __half* kh = qh + 512;
    const __half* vh = qh + 1024;

    {
        __half* Qs = (__half*)(dsm + 35840);
#pragma unroll
        for (int i = 0; i < 4; i++) {
            const int id = tid + i * 256;          // < 1024
            const int r = id >> 3, c8 = (id & 7) * 8;
            *(float4*)&Qs[r * 72 + c8] =
                *(const float4*)&qh[(long long)(q0 + r) * 1536 + c8];
        }
        __syncthreads();
    }
    uint32_t qa[4][4];
    {
        const __half* Qs = (const __half*)(dsm + 35840);
#pragma unroll
        for (int ks = 0; ks < 4; ks++) {
            const int r0 = (qr + g) * 72, r1 = (qr + g + 8) * 72;
            qa[ks][0] = *(const uint32_t*)&Qs[r0 + ks*16 + 2*tg];
            qa[ks][1] = *(const uint32_t*)&Qs[r1 + ks*16 + 2*tg];
            qa[ks][2] = *(const uint32_t*)&Qs[r0 + ks*16 + 2*tg + 8];
            qa[ks][3] = *(const uint32_t*)&Qs[r1 + ks*16 + 2*tg + 8];
        }
    }

    float mrun[2] = {-INFINITY, -INFINITY};
    float lrun[2] = {0.f, 0.f};
    float oacc[8][4];
#pragma unroll
    for (int n = 0; n < 8; n++)
#pragma unroll
        for (int c = 0; c < 4; c++) oacc[n][c] = 0.f;

    const __half* Bz = biasmh + (long long)z * SSS + (long long)(q0 + qr) * SS;

    for (int kt = 0; kt < 4; kt++) {
        __syncthreads();
#pragma unroll
        for (int i = 0; i < 4; i++) {
            const int id = tid + i * 256;
            const int r = id >> 3, c8 = (id & 7) * 8;
            *(float4*)&Ks[r * 72 + c8] =
                *(const float4*)&kh[(long long)(kt*128 + r) * 1536 + c8];
        }
        {
            const int dg = tid >> 6;        // dh group of 16
            const int kp = tid & 63;        // key pair
            const __half* vp = vh + (long long)(kt*128 + 2*kp) * 1536 + dg*16;
            float4 x0 = *(const float4*)(vp);
            float4 x1 = *(const float4*)(vp + 8);
            float4 y0 = *(const float4*)(vp + 1536);
            float4 y1 = *(const float4*)(vp + 1536 + 8);
            const __half* h0 = (const __half*)&x0;
            const __half* h1 = (const __half*)&x1;
            const __half* j0 = (const __half*)&y0;
            const __half* j1 = (const __half*)&y1;
#pragma unroll
            for (int d = 0; d < 8; d++) {
                *(__half2*)&Vt[(dg*16 +     d)*136 + 2*kp] = __halves2half2(h0[d], j0[d]);
                *(__half2*)&Vt[(dg*16 + 8 + d)*136 + 2*kp] = __halves2half2(h1[d], j1[d]);
            }
        }
#pragma unroll
        for (int p = 0; p < 8; p++) {
            const int c = p * 32 + lane;            // < 256
            const int r = c >> 4, cc8 = (c & 15) * 8;
            cpa16(wr_u32 + (uint32_t)((r * 136 + cc8) * 2),
                  &Bz[(long long)r * SS + kt * 128 + cc8]);
        }
        CP_COMMIT();
        __syncthreads();

        float sacc[16][4];
#pragma unroll
        for (int n = 0; n < 16; n++)
#pragma unroll
            for (int c = 0; c < 4; c++) sacc[n][c] = 0.f;
#pragma unroll
        for (int ks = 0; ks < 4; ks++) {
#pragma unroll
            for (int n = 0; n < 16; n++) {
                const int rn = (n*8 + g) * 72;
                const uint32_t b0 = *(const uint32_t*)&Ks[rn + ks*16 + 2*tg];
                const uint32_t b1 = *(const uint32_t*)&Ks[rn + ks*16 + 2*tg + 8];
                mma16(sacc[n], qa[ks], b0, b1);
            }
        }

        CP_WAIT(0);
        __syncwarp();
        float tmax0 = -INFINITY, tmax1 = -INFINITY;
#pragma unroll
        for (int n = 0; n < 16; n++) {
            const float2 bv0 = __half22float2(*(__half2*)&wrh[ g      * 136 + n*8 + 2*tg]);
            const float2 bv1 = __half22float2(*(__half2*)&wrh[(g + 8) * 136 + n*8 + 2*tg]);
            sacc[n][0] = sacc[n][0]*0.125f + bv0.x;
            sacc[n][1] = sacc[n][1]*0.125f + bv0.y;
            sacc[n][2] = sacc[n][2]*0.125f + bv1.x;
            sacc[n][3] = sacc[n][3]*0.125f + bv1.y;
            tmax0 = fmaxf(tmax0, fmaxf(sacc[n][0], sacc[n][1]));
            tmax1 = fmaxf(tmax1, fmaxf(sacc[n][2], sacc[n][3]));
        }
        tmax0 = fmaxf(tmax0, __shfl_xor_sync(0xffffffffu, tmax0, 1));
        tmax0 = fmaxf(tmax0, __shfl_xor_sync(0xffffffffu, tmax0, 2));
        tmax1 = fmaxf(tmax1, __shfl_xor_sync(0xffffffffu, tmax1, 1));
        tmax1 = fmaxf(tmax1, __shfl_xor_sync(0xffffffffu, tmax1, 2));

        const float mnew0 = fmaxf(mrun[0], tmax0);
        const float mnew1 = fmaxf(mrun[1], tmax1);
        const float scl0 = __expf(mrun[0] - mnew0);
        const float scl1 = __expf(mrun[1] - mnew1);
        float ts0 = 0.f, ts1 = 0.f;
#pragma unroll
        for (int n = 0; n < 16; n++) {
            sacc[n][0] = __expf(sacc[n][0] - mnew0);
            sacc[n][1] = __expf(sacc[n][1] - mnew0);
            sacc[n][2] = __expf(sacc[n][2] - mnew1);
            sacc[n][3] = __expf(sacc[n][3] - mnew1);
            ts0 += sacc[n][0] + sacc[n][1];
            ts1 += sacc[n][2] + sacc[n][3];
        }
        ts0 += __shfl_xor_sync(0xffffffffu, ts0, 1);
        ts0 += __shfl_xor_sync(0xffffffffu, ts0, 2);
        ts1 += __shfl_xor_sync(0xffffffffu, ts1, 1);
        ts1 += __shfl_xor_sync(0xffffffffu, ts1, 2);
        lrun[0] = lrun[0] * scl0 + ts0;
        lrun[1] = lrun[1] * scl1 + ts1;
        mrun[0] = mnew0; mrun[1] = mnew1;
#pragma unroll
        for (int n = 0; n < 8; n++) {
            oacc[n][0] *= scl0; oacc[n][1] *= scl0;
            oacc[n][2] *= scl1; oacc[n][3] *= scl1;
        }

        __syncwarp();
#pragma unroll
        for (int n = 0; n < 16; n++) {
            *(__half2*)&wrh[ g      * 136 + n*8 + 2*tg] = __floats2half2_rn(sacc[n][0], sacc[n][1]);
            *(__half2*)&wrh[(g + 8) * 136 + n*8 + 2*tg] = __floats2half2_rn(sacc[n][2], sacc[n][3]);
        }
        __syncwarp();
#pragma unroll
        for (int ks = 0; ks < 8; ks++) {
            uint32_t pa[4];
            pa[0] = *(const uint32_t*)&wrh[ g      * 136 + ks*16 + 2*tg];
            pa[1] = *(const uint32_t*)&wrh[(g + 8) * 136 + ks*16 + 2*tg];
            pa[2] = *(const uint32_t*)&wrh[ g      * 136 + ks*16 + 2*tg + 8];
            pa[3] = *(const uint32_t*)&wrh[(g + 8) * 136 + ks*16 + 2*tg + 8];
#pragma unroll
            for (int n = 0; n < 8; n++) {
                const int rn = (n*8 + g) * 136;
                const uint32_t b0 = *(const uint32_t*)&Vt[rn + ks*16 + 2*tg];
                const uint32_t b1 = *(const uint32_t*)&Vt[rn + ks*16 + 2*tg + 8];
                mma16(oacc[n], pa, b0, b1);
            }
        }
    }

    const float inv0 = 1.f / lrun[0];
    const float inv1 = 1.f / lrun[1];
    const int t0 = b * SS + q0 + qr;
#pragma unroll
    for (int n = 0; n < 8; n++) {
        const int col = h * 64 + n * 8 + 2 * tg;
        *(__half2*)&ctxh[(long long)(t0 + g    ) * EE + col] =
            __floats2half2_rn(oacc[n][0] * inv0, oacc[n][1] * inv0);
        *(__half2*)&ctxh[(long long)(t0 + g + 8) * EE + col] =
            __floats2half2_rn(oacc[n][2] * inv1, oacc[n][3] * inv1);
    }
}

// ---------------------------------------------------------------------------
__global__ void convw4_k(const float* __restrict__ s0, const float* __restrict__ s1,
                         const float* __restrict__ s2, const float* __restrict__ s3,
                         __half* __restrict__ dst)
{
    const int i = blockIdx.x * blockDim.x + threadIdx.x;
    float v;
    if      (i < N_IP)                  v = s0[i];
    else if (i < N_IP + N_OW)           v = s1[i - N_IP];
    else if (i < N_IP + N_OW + N_F1)    v = s2[i - N_IP - N_OW];
    else                                v = s3[i - N_IP - N_OW - N_F1];
    dst[i] = __float2half_rn(v);
}

__global__ void embed_k(const int* __restrict__ seq, const float* __restrict__ emb,
                        __half* __restrict__ xh)
{
    int i = blockIdx.x * blockDim.x + threadIdx.x;
    int e = i & (EE-1);
    int t = i >> 9;
    xh[i] = __float2half_rn(emb[seq[t]*EE + e] * 22.627416997969522f);
}

__global__ void bias_k(const int* __restrict__ squares, const int* __restrict__ seq,
                       const float* __restrict__ dist, __half* __restrict__ bias)
{
    long long i = (long long)blockIdx.x * blockDim.x + threadIdx.x;
    int k = (int)(i & (SS-1));
    long long r = i >> 9;
    int q = (int)(r & (SS-1)); r >>= 9;
    int h = (int)(r & (HH-1));
    int b = (int)(r >> 3);
    float m = (seq[b*SS + k] == 0) ? -60000.f : 0.f;
    bias[i] = __float2half_rn(dist[squares[((long long)(b*SS + q) << 9) + k]*HH + h] + m);
}

// ---------------------------------------------------------------------------
__device__ __forceinline__ void block_ln_stats(float v, float& mean, float& var)
{
    float s = v, q = v*v;
#pragma unroll
    for (int o = 16; o > 0; o >>= 1) {
        s += __shfl_xor_sync(0xffffffffu, s, o);
        q += __shfl_xor_sync(0xffffffffu, q, o);
    }
    __shared__ float shs[16], shq[16];
    const int wid = threadIdx.x >> 5, lane = threadIdx.x & 31;
    if (lane == 0) { shs[wid] = s; shq[wid] = q; }
    __syncthreads();
    if (threadIdx.x < 32) {
        float ss = (lane < 16) ? shs[lane] : 0.f;
        float qq = (lane < 16) ? shq[lane] : 0.f;
#pragma unroll
        for (int o = 8; o > 0; o >>= 1) {
            ss += __shfl_xor_sync(0xffffffffu, ss, o);
            qq += __shfl_xor_sync(0xffffffffu, qq, o);
        }
        if (lane == 0) { shs[0] = ss; shq[0] = qq; }
    }
    __syncthreads();
    mean = shs[0] * (1.f/EE);
    var  = shq[0] * (1.f/EE) - mean*mean;
}

// x = LN(x + sum_p part[p] + bias)  — split-K reduction fused into LN
template<int P>
__global__ void add_ln_red_k(__half* __restrict__ xh, const float* __restrict__ part,
                             const float* __restrict__ bias,
                             const float* __restrict__ w, const float* __restrict__ b)
{
    const long long base = (long long)blockIdx.x * EE;
    const int t = threadIdx.x;
    float v = __half2float(xh[base + t]) + bias[t];
#pragma unroll
    for (int p = 0; p < P; p++)
        v += part[(long long)p * (TOK*EE) + base + t];
    float mean, var;
    block_ln_stats(v, mean, var);
    xh[base + t] = __float2half_rn((v - mean) * rsqrtf(var + 1e-5f) * w[t] + b[t]);
}

__global__ void ln_final_k(const __half* __restrict__ xh, const float* __restrict__ w,
                           const float* __restrict__ b, float* __restrict__ out)
{
    const int row = blockIdx.x;
    const int bi = row >> 9, si = row & (SS-1);
    const int t = threadIdx.x;
    float v = __half2float(xh[(long long)row*EE + t]);
    float mean, var;
    block_ln_stats(v, mean, var);
    out[((long long)si*BB + bi)*EE + t] = (v - mean) * rsqrtf(var + 1e-5f) * w[t] + b[t];
}

__global__ void mask_k(const int* __restrict__ seq, float* __restrict__ out)
{
    int i = blockIdx.x * blockDim.x + threadIdx.x;
    out[i] = (seq[i] == 0) ? 1.f : 0.f;
}

// ---------------------------------------------------------------------------
extern "C" void kernel_launch(void* const* d_in, const int* in_sizes, int n_in,
                              void* d_out, int out_size)
{
    const int*   seq     = (const int*)  d_in[0];
    const int*   squares = (const int*)  d_in[1];
    const float* tok_emb = (const float*)d_in[2];
    const float* dist    = (const float*)d_in[3];
    const float* ipw     = (const float*)d_in[4];
    const float* ipb     = (const float*)d_in[5];
    const float* ow      = (const float*)d_in[6];
    const float* ob      = (const float*)d_in[7];
    const float* f1w     = (const float*)d_in[8];
    const float* f1b     = (const float*)d_in[9];
    const float* f2w     = (const float*)d_in[10];
    const float* f2b     = (const float*)d_in[11];
    const float* l1w     = (const float*)d_in[12];
    const float* l1b     = (const float*)d_in[13];
    const float* l2w     = (const float*)d_in[14];
    const float* l2b     = (const float*)d_in[15];
    const float* lfw     = (const float*)d_in[16];
    const float* lfb     = (const float*)d_in[17];
    float* out = (float*)d_out;

    __half *xh,*qkvh,*bmh,*ctxh,*ffh,*wh;
    float *part;
    cudaGetSymbolAddress((void**)&xh,   g_xh);
    cudaGetSymbolAddress((void**)&qkvh, g_qkvh);
    cudaGetSymbolAddress((void**)&bmh,  g_biasmh);
    cudaGetSymbolAddress((void**)&ctxh, g_ctxh);
    cudaGetSymbolAddress((void**)&ffh,  g_ffh);
    cudaGetSymbolAddress((void**)&part, g_part);
    cudaGetSymbolAddress((void**)&wh,   g_wh);

    const int GEMM_SMEM  = 4 * 20480;     // 81920
    const int FLASH_SMEM = 70656;
    cudaFuncSetAttribute(hgemm<__half,0>, cudaFuncAttributeMaxDynamicSharedMemorySize, GEMM_SMEM);
    cudaFuncSetAttribute(hgemm<__half,1>, cudaFuncAttributeMaxDynamicSharedMemorySize, GEMM_SMEM);
    cudaFuncSetAttribute(hgemm<float,3>,  cudaFuncAttributeMaxDynamicSharedMemorySize, GEMM_SMEM);
    cudaFuncSetAttribute(flash_h,         cudaFuncAttributeMaxDynamicSharedMemorySize, FLASH_SMEM);

    __half* iph = wh;
    __half* owh = iph + N_IP;
    __half* f1h = owh + N_OW;
    __half* f2h = f1h + N_F1;
    convw4_k<<<(N_IP+N_OW+N_F1+N_F2)/256, 256>>>(ipw, ow, f1w, f2w, wh);

    embed_k<<<(TOK*EE)/256, 256>>>(seq, tok_emb, xh);
    bias_k<<<(int)(((long long)NZ*SSS)/256), 256>>>(squares, seq, dist, bmh);

    const long long PSTR = (long long)TOK*EE;

    for (int l = 0; l < LL; l++) {
        // qkv = x @ in_proj_w^T + b      [8192,1536] K=512
        hgemm<__half,0><<<dim3(12,64,1), 512, GEMM_SMEM>>>(
            xh, iph + (long long)l*3*EE*EE, ipb + l*3*EE, qkvh, EE, EE, EE, 3*EE, 0);

        // fused attention: ctx = softmax(0.125*QK^T + biasm) @ V
        flash_h<<<dim3(4, NZ), 256, FLASH_SMEM>>>(qkvh, bmh, ctxh);

        // attn partials: ctx @ out_w^T, split-K=2 (K=256 each)
        hgemm<float,3><<<dim3(4,64,2), 512, GEMM_SMEM>>>(
            ctxh, owh + (long long)l*EE*EE, nullptr, part, 256, EE, EE, EE, PSTR);

        // x = LN(x + p0 + p1 + ob)
        add_ln_red_k<2><<<TOK, EE>>>(xh, part, ob + l*EE, l1w + l*EE, l1b + l*EE);

        // h = gelu(x @ ff1_w^T + b)      [8192,2048] K=512
        hgemm<__half,1><<<dim3(16,64,1), 512, GEMM_SMEM>>>(
            xh, f1h + (long long)l*FFD*EE, f1b + l*FFD, ffh, EE, EE, EE, FFD, 0);

        // ff partials: h @ ff2_w^T, split-K=4 (K=512 each)
        hgemm<float,3><<<dim3(4,64,4), 512, GEMM_SMEM>>>(
            ffh, f2h + (long long)l*EE*FFD, nullptr, part, 512, FFD, FFD, EE, PSTR);

        // x = LN(x + p0+p1+p2+p3 + f2b)
        add_ln_red_k<4><<<TOK, EE>>>(xh, part, f2b + l*EE, l2w + l*EE, l2b + l*EE);
    }

    ln_final_k<<<TOK, EE>>>(xh, lfw, lfb, out);

    if (out_size >= TOK*EE + TOK)
        mask_k<<<TOK/256, 256>>>(seq, out + (long long)TOK*EE);
}

// round 14
// speedup vs baseline: 5.3773x; 1.0464x over previous
#include <cuda_runtime.h>
#include <cuda_fp16.h>
#include <math.h>
#include <stdint.h>

// Fixed shapes for BaseEncoder_68702296867023
#define BB 16
#define SS 512
#define EE 512
#define HH 8
#define FFD 2048
#define LL 6
#define DH 64
#define TOK (BB*SS)              // 8192 tokens
#define NZ (BB*HH)               // 128 attention batches
#define SSS ((long long)SS*SS)

// ---------------------------------------------------------------------------
// Scratch (device globals; no allocations allowed)
// ---------------------------------------------------------------------------
__device__ __half g_xh[TOK*EE];               // activations (half)     8 MB
__device__ __half g_qkvh[TOK*3*EE];           // qkv (half)            24 MB
__device__ __half g_biasmh[NZ*SS*SS];         // rel-dist bias+mask    67 MB
__device__ __half g_ctxh[TOK*EE];             // attention ctx (half)   8 MB
__device__ __half g_ffh[TOK*FFD];             // FF hidden (half)      32 MB
__device__ float  g_part[4*TOK*EE];           // split-K partials      64 MB
__device__ __half g_wh[18874368];             // fp16 weights          38 MB

#define N_IP (LL*3*EE*EE)
#define N_OW (LL*EE*EE)
#define N_F1 (LL*FFD*EE)
#define N_F2 (LL*EE*FFD)

// ---------------------------------------------------------------------------
__device__ __forceinline__ void mma16(float c[4], const uint32_t a[4],
                                      uint32_t b0, uint32_t b1)
{
    asm volatile(
        "mma.sync.aligned.m16n8k16.row.col.f32.f16.f16.f32 "
        "{%0,%1,%2,%3},{%4,%5,%6,%7},{%8,%9},{%0,%1,%2,%3};\n"
        : "+f"(c[0]), "+f"(c[1]), "+f"(c[2]), "+f"(c[3])
        : "r"(a[0]), "r"(a[1]), "r"(a[2]), "r"(a[3]), "r"(b0), "r"(b1));
}

__device__ __forceinline__ void cpa16(uint32_t s, const void* g)
{
    asm volatile("cp.async.cg.shared.global [%0], [%1], 16;\n" :: "r"(s), "l"(g));
}
#define CP_COMMIT() asm volatile("cp.async.commit_group;\n")
#define CP_WAIT(N)  asm volatile("cp.async.wait_group %0;\n" :: "n"(N))

#define LDSM4(r0,r1,r2,r3,addr) \
    asm volatile("ldmatrix.sync.aligned.m8n8.x4.shared.b16 {%0,%1,%2,%3}, [%4];" \
                 : "=r"(r0),"=r"(r1),"=r"(r2),"=r"(r3) : "r"(addr))
#define LDSM2(r0,r1,addr) \
    asm volatile("ldmatrix.sync.aligned.m8n8.x2.shared.b16 {%0,%1}, [%2];" \
                 : "=r"(r0),"=r"(r1) : "r"(addr))
#define LDSM2T(r0,r1,addr) \
    asm volatile("ldmatrix.sync.aligned.m8n8.x2.trans.shared.b16 {%0,%1}, [%2];" \
                 : "=r"(r0),"=r"(r1) : "r"(addr))

// ---------------------------------------------------------------------------
// fp16 tensor-core GEMM (m16n8k16), 128x128 tile, BK=32, 4-stage cp.async.
// 512 threads / 16 warps, 32x32 warp tiles. (R13-proven core, unchanged.)
//   Split-K via blockIdx.z. EPI: 0 +bias, 1 +bias+gelu, 3 raw partial.
// ---------------------------------------------------------------------------
template<typename OutT, int EPI>
__global__ void __launch_bounds__(512)
hgemm(const __half* __restrict__ A, const __half* __restrict__ B,
      const float* __restrict__ bias, OutT* __restrict__ C,
      int K, int lda, int ldb, int ldc, long long pstride)
{
    extern __shared__ __align__(16) char dsm[];
    const uint32_t sb = (uint32_t)__cvta_generic_to_shared(dsm);
    const int tid = threadIdx.x;
    const int m0 = blockIdx.y * 128, n0 = blockIdx.x * 128;
    const int z = blockIdx.z;
    A += (long long)z * K;
    B += (long long)z * K;
    C += (long long)z * pstride;
    const int warp = tid >> 5, lane = tid & 31;
    const int g = lane >> 2, tg = lane & 3;
    const int wx = warp & 3, wy = warp >> 2;      // 4x4 grid: 32x32 warp tiles
    const int wm0 = wy * 32, wn0 = wx * 32;
    const int lr = tid >> 2, lc = (tid & 3) * 8;  // loader: one cpa16/thread

    const uint32_t aoff = (uint32_t)(((wm0 + ((lane>>3)&1)*8 + (lane&7)) * 40
                                      + (lane>>4)*8) * 2);
    const uint32_t boff = (uint32_t)(10240 + ((wn0 + (lane&7)) * 40
                                      + ((lane>>3)&1)*8) * 2);

    auto prefetch = [&](int t) {
        const int k0 = t * 32;
        const uint32_t st = sb + (uint32_t)((t % 4) * 20480);
        cpa16(st + (uint32_t)(lr*80 + lc*2),
              &A[(long long)(m0 + lr) * lda + k0 + lc]);
        cpa16(st + (uint32_t)(10240 + lr*80 + lc*2),
              &B[(long long)(n0 + lr) * ldb + k0 + lc]);
    };

    float acc[2][4][4];
#pragma unroll
    for (int i = 0; i < 2; i++)
#pragma unroll
        for (int j = 0; j < 4; j++)
#pragma unroll
            for (int c = 0; c < 4; c++) acc[i][j][c] = 0.f;

    const int nb = K / 32;
    prefetch(0); CP_COMMIT();
    prefetch(1); CP_COMMIT();
    prefetch(2); CP_COMMIT();

    for (int t = 0; t < nb; t++) {
        CP_WAIT(2);
        __syncthreads();
        if (t + 3 < nb) prefetch(t + 3);
        CP_COMMIT();
        const uint32_t st = sb + (uint32_t)((t % 4) * 20480);
#pragma unroll
        for (int kb = 0; kb < 32; kb += 16) {
            uint32_t a[2][4], bf[4][2];
#pragma unroll
            for (int i = 0; i < 2; i++)
                LDSM4(a[i][0], a[i][1], a[i][2], a[i][3],
                      st + aoff + (uint32_t)(i*1280 + kb*2));
#pragma unroll
            for (int j = 0; j < 4; j++)
                LDSM2(bf[j][0], bf[j][1],
                      st + boff + (uint32_t)(j*640 + kb*2));
#pragma unroll
            for (int i = 0; i < 2; i++)
#pragma unroll
                for (int j = 0; j < 4; j++)
                    mma16(acc[i][j], a[i], bf[j][0], bf[j][1]);
        }
    }

    // epilogue
#pragma unroll
    for (int i = 0; i < 2; i++) {
#pragma unroll
        for (int j = 0; j < 4; j++) {
#pragma unroll
            for (int hh = 0; hh < 2; hh++) {
                const long long r = m0 + wm0 + i*16 + g + hh*8;
                const int c = n0 + wn0 + j*8 + 2*tg;
                float vx = acc[i][j][hh*2 + 0];
                float vy = acc[i][j][hh*2 + 1];
                if (EPI != 3) { vx += bias[c]; vy += bias[c+1]; }
                if (EPI == 1) {
                    vx = 0.5f*vx*(1.f + erff(vx*0.70710678118654752f));
                    vy = 0.5f*vy*(1.f + erff(vy*0.70710678118654752f));
                }
                if (sizeof(OutT) == 2) {
                    *(__half2*)&((__half*)C)[r*ldc + c] = __floats2half2_rn(vx, vy);
                } else {
                    float2 v2; v2.x = vx; v2.y = vy;
                    *(float2*)&((float*)C)[r*ldc + c] = v2;
                }
            }
        }
    }
}

// ---------------------------------------------------------------------------
// Fused flash attention v2: cp.async double-buffered K/V stages + trans-LDSM PV.
// smem (bytes):
//   stage s∈{0,1} @ s*36864: K half[128][72] (18432) | Vraw half[128][72] (18432)
//   warp regions @73728 + w*4352: bias/P half[16][136] alias
//   Q staging half[128][72] aliased @73728.   Total 108544 B.
// Commit order per iter: [bias kt], [KV kt+1]; WAIT(1) before softmax; WAIT(0) at top.
// ---------------------------------------------------------------------------
__global__ void __launch_bounds__(256)
flash_h(const __half* __restrict__ qkvh, const __half* __restrict__ biasmh,
        __half* __restrict__ ctxh)
{
    extern __shared__ __align__(16) char dsm[];
    const uint32_t sbase = (uint32_t)__cvta_generic_to_shared(dsm);

    const int tid = threadIdx.x, lane = tid & 31, w = tid >> 5;
    const int g = lane >> 2, tg = lane & 3;
    const int qt = blockIdx.x;          // 0..3
    const int z  = blockIdx.y;          // b*H + h
    const int b  = z >> 3, h = z & 7;
    const int q0 = qt * 128;
    const int qr = w * 16;

    __half* wrh = (__half*)(dsm + 73728 + w * 4352);
    const uint32_t wr_u32 = (uint32_t)__cvta_generic_to_shared(wrh);
    const int vrow = (lane & 7) + ((lane >> 3) & 1) * 8;   // trans-LDSM row select

    const __half* qh = qkvh + (long long)(b * SS) * 1536 + h * 64;
    const __half* kh = qh + 512;
    const __half* vh = qh + 1024;

    auto kv_prefetch = [&](int kt) {
        const uint32_t st = sbase + (uint32_t)((kt & 1) * 36864);
#pragma unroll
        for (int i = 0; i < 8; i++) {
            const int id = tid + (i & 3) * 256;     // < 1024
            const int r = id >> 3, c = id & 7;
            if (i < 4)
                cpa16(st + (uint32_t)(r*144 + c*16),
                      &kh[(long long)(kt*128 + r) * 1536 + c*8]);
            else
                cpa16(st + 18432u + (uint32_t)(r*144 + c*16),
                      &vh[(long long)(kt*128 + r) * 1536 + c*8]);
        }
    };

    kv_prefetch(0); CP_COMMIT();

    // ---- stage Q (alias @73728), extract a-frags ----
    {
        __half* Qs = (__half*)(dsm + 73728);
#pragma unroll
        for (int i = 0; i < 4; i++) {
            const int id = tid + i * 256;           // < 1024
            const int r = id >> 3, c8 = (id & 7) * 8;
            *(float4*)&Qs[r * 72 + c8] =
                *(const float4*)&qh[(long long)(q0 + r) * 1536 + c8];
        }
        __syncthreads();
    }
    uint32_t qa[4][4];
    {
        const __half* Qs = (const __half*)(dsm + 73728);
#pragma unroll
        for (int ks = 0; ks < 4; ks++) {
            const int r0 = (qr + g) * 72, r1 = (qr + g + 8) * 72;
            qa[ks][0] = *(const uint32_t*)&Qs[r0 + ks*16 + 2*tg];
            qa[ks][1] = *(const uint32_t*)&Qs[r1 + ks*16 + 2*tg];
            qa[ks][2] = *(const uint32_t*)&Qs[r0 + ks*16 + 2*tg + 8];
            qa[ks][3] = *(const uint32_t*)&Qs[r1 + ks*16 + 2*tg + 8];
        }
    }

    float mrun[2] = {-INFINITY, -INFINITY};
    float lrun[2] = {0.f, 0.f};
    float oacc[8][4];
#pragma unroll
    for (int n = 0; n < 8; n++)
#pragma unroll
        for (int c = 0; c < 4; c++) oacc[n][c] = 0.f;

    const __half* Bz = biasmh + (long long)z * SSS + (long long)(q0 + qr) * SS;

    for (int kt = 0; kt < 4; kt++) {
        CP_WAIT(0);          // KV(kt) landed
        __syncthreads();     // visible to all; prev P consumed; Q alias consumed

        // [group A] bias tile for kt  (must drain before softmax)
#pragma unroll
        for (int p = 0; p < 8; p++) {
            const int c = p * 32 + lane;            // < 256
            const int r = c >> 4, cc8 = (c & 15) * 8;
            cpa16(wr_u32 + (uint32_t)((r * 136 + cc8) * 2),
                  &Bz[(long long)r * SS + kt * 128 + cc8]);
        }
        CP_COMMIT();
        // [group B] KV(kt+1) — allowed to stay in flight through this iteration
        if (kt + 1 < 4) kv_prefetch(kt + 1);
        CP_COMMIT();

        const __half* KsS = (const __half*)(dsm + (kt & 1) * 36864);
        const uint32_t Vb = sbase + (uint32_t)((kt & 1) * 36864 + 18432);

        // ---- S = Q.K^T (fp16 mma) ----
        float sacc[16][4];
#pragma unroll
        for (int n = 0; n < 16; n++)
#pragma unroll
            for (int c = 0; c < 4; c++) sacc[n][c] = 0.f;
#pragma unroll
        for (int ks = 0; ks < 4; ks++) {
#pragma unroll
            for (int n = 0; n < 16; n++) {
                const int rn = (n*8 + g) * 72;
                const uint32_t b0 = *(const uint32_t*)&KsS[rn + ks*16 + 2*tg];
                const uint32_t b1 = *(const uint32_t*)&KsS[rn + ks*16 + 2*tg + 8];
                mma16(sacc[n], qa[ks], b0, b1);
            }
        }

        // ---- *0.125 + bias, online softmax (fp32) ----
        CP_WAIT(1);          // bias drained; KV(kt+1) may still fly
        __syncwarp();
        float tmax0 = -INFINITY, tmax1 = -INFINITY;
#pragma unroll
        for (int n = 0; n < 16; n++) {
            const float2 bv0 = __half22float2(*(__half2*)&wrh[ g      * 136 + n*8 + 2*tg]);
            const float2 bv1 = __half22float2(*(__half2*)&wrh[(g + 8) * 136 + n*8 + 2*tg]);
            sacc[n][0] = sacc[n][0]*0.125f + bv0.x;
            sacc[n][1] = sacc[n][1]*0.125f + bv0.y;
            sacc[n][2] = sacc[n][2]*0.125f + bv1.x;
            sacc[n][3] = sacc[n][3]*0.125f + bv1.y;
            tmax0 = fmaxf(tmax0, fmaxf(sacc[n][0], sacc[n][1]));
            tmax1 = fmaxf(tmax1, fmaxf(sacc[n][2], sacc[n][3]));
        }
        tmax0 = fmaxf(tmax0, __shfl_xor_sync(0xffffffffu, tmax0, 1));
        tmax0 = fmaxf(tmax0, __shfl_xor_sync(0xffffffffu, tmax0, 2));
        tmax1 = fmaxf(tmax1, __shfl_xor_sync(0xffffffffu, tmax1, 1));
        tmax1 = fmaxf(tmax1, __shfl_xor_sync(0xffffffffu, tmax1, 2));

        const float mnew0 = fmaxf(mrun[0], tmax0);
        const float mnew1 = fmaxf(mrun[1], tmax1);
        const float scl0 = __expf(mrun[0] - mnew0);
        const float scl1 = __expf(mrun[1] - mnew1);
        float ts0 = 0.f, ts1 = 0.f;
#pragma unroll
        for (int n = 0; n < 16; n++) {
            sacc[n][0] = __expf(sacc[n][0] - mnew0);
            sacc[n][1] = __expf(sacc[n][1] - mnew0);
            sacc[n][2] = __expf(sacc[n][2] - mnew1);
            sacc[n][3] = __expf(sacc[n][3] - mnew1);
            ts0 += sacc[n][0] + sacc[n][1];
            ts1 += sacc[n][2] + sacc[n][3];
        }
        ts0 += __shfl_xor_sync(0xffffffffu, ts0, 1);
        ts0 += __shfl_xor_sync(0xffffffffu, ts0, 2);
        ts1 += __shfl_xor_sync(0xffffffffu, ts1, 1);
        ts1 += __shfl_xor_sync(0xffffffffu, ts1, 2);
        lrun[0] = lrun[0] * scl0 + ts0;
        lrun[1] = lrun[1] * scl1 + ts1;
        mrun[0] = mnew0; mrun[1] = mnew1;
#pragma unroll
        for (int n = 0; n < 8; n++) {
            oacc[n][0] *= scl0; oacc[n][1] *= scl0;
            oacc[n][2] *= scl1; oacc[n][3] *= scl1;
        }

        // ---- P (half) into warp region (alias over bias), then P.V ----
        __syncwarp();   // bias reads complete before alias overwrite
#pragma unroll
        for (int n = 0; n < 16; n++) {
            *(__half2*)&wrh[ g      * 136 + n*8 + 2*tg] = __floats2half2_rn(sacc[n][0], sacc[n][1]);
            *(__half2*)&wrh[(g + 8) * 136 + n*8 + 2*tg] = __floats2half2_rn(sacc[n][2], sacc[n][3]);
        }
        __syncwarp();
#pragma unroll
        for (int ks = 0; ks < 8; ks++) {
            uint32_t pa[4];
            pa[0] = *(const uint32_t*)&wrh[ g      * 136 + ks*16 + 2*tg];
            pa[1] = *(const uint32_t*)&wrh[(g + 8) * 136 + ks*16 + 2*tg];
            pa[2] = *(const uint32_t*)&wrh[ g      * 136 + ks*16 + 2*tg + 8];
            pa[3] = *(const uint32_t*)&wrh[(g + 8) * 136 + ks*16 + 2*tg + 8];
            const uint32_t vr = Vb + (uint32_t)((ks*16 + vrow) * 144);
#pragma unroll
            for (int n = 0; n < 8; n++) {
                uint32_t b0, b1;
                LDSM2T(b0, b1, vr + (uint32_t)(n * 16));
                mma16(oacc[n], pa, b0, b1);
            }
        }
    }

    // ---- normalize and write ctx (half) ----
    const float inv0 = 1.f / lrun[0];
    const float inv1 = 1.f / lrun[1];
    const int t0 = b * SS + q0 + qr;
#pragma unroll
    for (int n = 0; n < 8; n++) {
        const int col = h * 64 + n * 8 + 2 * tg;
        *(__half2*)&ctxh[(long long)(t0 + g    ) * EE + col] =
            __floats2half2_rn(oacc[n][0] * inv0, oacc[n][1] * inv0);
        *(__half2*)&ctxh[(long long)(t0 + g + 8) * EE + col] =
            __floats2half2_rn(oacc[n][2] * inv1, oacc[n][3] * inv1);
    }
}

// ---------------------------------------------------------------------------
__global__ void convw4_k(const float* __restrict__ s0, const float* __restrict__ s1,
                         const float* __restrict__ s2, const float* __restrict__ s3,
                         __half* __restrict__ dst)
{
    const int i = blockIdx.x * blockDim.x + threadIdx.x;
    float v;
    if      (i < N_IP)                  v = s0[i];
    else if (i < N_IP + N_OW)           v = s1[i - N_IP];
    else if (i < N_IP + N_OW + N_F1)    v = s2[i - N_IP - N_OW];
    else                                v = s3[i - N_IP - N_OW - N_F1];
    dst[i] = __float2half_rn(v);
}

__global__ void embed_k(const int* __restrict__ seq, const float* __restrict__ emb,
                        __half* __restrict__ xh)
{
    int i = blockIdx.x * blockDim.x + threadIdx.x;
    int e = i & (EE-1);
    int t = i >> 9;
    xh[i] = __float2half_rn(emb[seq[t]*EE + e] * 22.627416997969522f);
}

__global__ void bias_k(const int* __restrict__ squares, const int* __restrict__ seq,
                       const float* __restrict__ dist, __half* __restrict__ bias)
{
    long long i = (long long)blockIdx.x * blockDim.x + threadIdx.x;
    int k = (int)(i & (SS-1));
    long long r = i >> 9;
    int q = (int)(r & (SS-1)); r >>= 9;
    int h = (int)(r & (HH-1));
    int b = (int)(r >> 3);
    float m = (seq[b*SS + k] == 0) ? -60000.f : 0.f;
    bias[i] = __float2half_rn(dist[squares[((long long)(b*SS + q) << 9) + k]*HH + h] + m);
}

// ---------------------------------------------------------------------------
__device__ __forceinline__ void block_ln_stats(float v, float& mean, float& var)
{
    float s = v, q = v*v;
#pragma unroll
    for (int o = 16; o > 0; o >>= 1) {
        s += __shfl_xor_sync(0xffffffffu, s, o);
        q += __shfl_xor_sync(0xffffffffu, q, o);
    }
    __shared__ float shs[16], shq[16];
    const int wid = threadIdx.x >> 5, lane = threadIdx.x & 31;
    if (lane == 0) { shs[wid] = s; shq[wid] = q; }
    __syncthreads();
    if (threadIdx.x < 32) {
        float ss = (lane < 16) ? shs[lane] : 0.f;
        float qq = (lane < 16) ? shq[lane] : 0.f;
#pragma unroll
        for (int o = 8; o > 0; o >>= 1) {
            ss += __shfl_xor_sync(0xffffffffu, ss, o);
            qq += __shfl_xor_sync(0xffffffffu, qq, o);
        }
        if (lane == 0) { shs[0] = ss; shq[0] = qq; }
    }
    __syncthreads();
    mean = shs[0] * (1.f/EE);
    var  = shq[0] * (1.f/EE) - mean*mean;
}

// x = LN(x + sum_p part[p] + bias)  — split-K reduction fused into LN
template<int P>
__global__ void add_ln_red_k(__half* __restrict__ xh, const float* __restrict__ part,
                             const float* __restrict__ bias,
                             const float* __restrict__ w, const float* __restrict__ b)
{
    const long long base = (long long)blockIdx.x * EE;
    const int t = threadIdx.x;
    float v = __half2float(xh[base + t]) + bias[t];
#pragma unroll
    for (int p = 0; p < P; p++)
        v += part[(long long)p * (TOK*EE) + base + t];
    float mean, var;
    block_ln_stats(v, mean, var);
    xh[base + t] = __float2half_rn((v - mean) * rsqrtf(var + 1e-5f) * w[t] + b[t]);
}

__global__ void ln_final_k(const __half* __restrict__ xh, const float* __restrict__ w,
                           const float* __restrict__ b, float* __restrict__ out)
{
    const int row = blockIdx.x;
    const int bi = row >> 9, si = row & (SS-1);
    const int t = threadIdx.x;
    float v = __half2float(xh[(long long)row*EE + t]);
    float mean, var;
    block_ln_stats(v, mean, var);
    out[((long long)si*BB + bi)*EE + t] = (v - mean) * rsqrtf(var + 1e-5f) * w[t] + b[t];
}

__global__ void mask_k(const int* __restrict__ seq, float* __restrict__ out)
{
    int i = blockIdx.x * blockDim.x + threadIdx.x;
    out[i] = (seq[i] == 0) ? 1.f : 0.f;
}

// ---------------------------------------------------------------------------
extern "C" void kernel_launch(void* const* d_in, const int* in_sizes, int n_in,
                              void* d_out, int out_size)
{
    const int*   seq     = (const int*)  d_in[0];
    const int*   squares = (const int*)  d_in[1];
    const float* tok_emb = (const float*)d_in[2];
    const float* dist    = (const float*)d_in[3];
    const float* ipw     = (const float*)d_in[4];
    const float* ipb     = (const float*)d_in[5];
    const float* ow      = (const float*)d_in[6];
    const float* ob      = (const float*)d_in[7];
    const float* f1w     = (const float*)d_in[8];
    const float* f1b     = (const float*)d_in[9];
    const float* f2w     = (const float*)d_in[10];
    const float* f2b     = (const float*)d_in[11];
    const float* l1w     = (const float*)d_in[12];
    const float* l1b     = (const float*)d_in[13];
    const float* l2w     = (const float*)d_in[14];
    const float* l2b     = (const float*)d_in[15];
    const float* lfw     = (const float*)d_in[16];
    const float* lfb     = (const float*)d_in[17];
    float* out = (float*)d_out;

    __half *xh,*qkvh,*bmh,*ctxh,*ffh,*wh;
    float *part;
    cudaGetSymbolAddress((void**)&xh,   g_xh);
    cudaGetSymbolAddress((void**)&qkvh, g_qkvh);
    cudaGetSymbolAddress((void**)&bmh,  g_biasmh);
    cudaGetSymbolAddress((void**)&ctxh, g_ctxh);
    cudaGetSymbolAddress((void**)&ffh,  g_ffh);
    cudaGetSymbolAddress((void**)&part, g_part);
    cudaGetSymbolAddress((void**)&wh,   g_wh);

    const int GEMM_SMEM  = 4 * 20480;     // 81920
    const int FLASH_SMEM = 108544;
    cudaFuncSetAttribute(hgemm<__half,0>, cudaFuncAttributeMaxDynamicSharedMemorySize, GEMM_SMEM);
    cudaFuncSetAttribute(hgemm<__half,1>, cudaFuncAttributeMaxDynamicSharedMemorySize, GEMM_SMEM);
    cudaFuncSetAttribute(hgemm<float,3>,  cudaFuncAttributeMaxDynamicSharedMemorySize, GEMM_SMEM);
    cudaFuncSetAttribute(flash_h,         cudaFuncAttributeMaxDynamicSharedMemorySize, FLASH_SMEM);

    __half* iph = wh;
    __half* owh = iph + N_IP;
    __half* f1h = owh + N_OW;
    __half* f2h = f1h + N_F1;
    convw4_k<<<(N_IP+N_OW+N_F1+N_F2)/256, 256>>>(ipw, ow, f1w, f2w, wh);

    embed_k<<<(TOK*EE)/256, 256>>>(seq, tok_emb, xh);
    bias_k<<<(int)(((long long)NZ*SSS)/256), 256>>>(squares, seq, dist, bmh);

    const long long PSTR = (long long)TOK*EE;

    for (int l = 0; l < LL; l++) {
        // qkv = x @ in_proj_w^T + b      [8192,1536] K=512
        hgemm<__half,0><<<dim3(12,64,1), 512, GEMM_SMEM>>>(
            xh, iph + (long long)l*3*EE*EE, ipb + l*3*EE, qkvh, EE, EE, EE, 3*EE, 0);

        // fused attention: ctx = softmax(0.125*QK^T + biasm) @ V
        flash_h<<<dim3(4, NZ), 256, FLASH_SMEM>>>(qkvh, bmh, ctxh);

        // attn partials: ctx @ out_w^T, split-K=2 (K=256 each)
        hgemm<float,3><<<dim3(4,64,2), 512, GEMM_SMEM>>>(
            ctxh, owh + (long long)l*EE*EE, nullptr, part, 256, EE, EE, EE, PSTR);

        // x = LN(x + p0 + p1 + ob)
        add_ln_red_k<2><<<TOK, EE>>>(xh, part, ob + l*EE, l1w + l*EE, l1b + l*EE);

        // h = gelu(x @ ff1_w^T + b)      [8192,2048] K=512
        hgemm<__half,1><<<dim3(16,64,1), 512, GEMM_SMEM>>>(
            xh, f1h + (long long)l*FFD*EE, f1b + l*FFD, ffh, EE, EE, EE, FFD, 0);

        // ff partials: h @ ff2_w^T, split-K=4 (K=512 each)
        hgemm<float,3><<<dim3(4,64,4), 512, GEMM_SMEM>>>(
            ffh, f2h + (long long)l*EE*FFD, nullptr, part, 512, FFD, FFD, EE, PSTR);

        // x = LN(x + p0+p1+p2+p3 + f2b)
        add_ln_red_k<4><<<TOK, EE>>>(xh, part, f2b + l*EE, l2w + l*EE, l2b + l*EE);
    }

    ln_final_k<<<TOK, EE>>>(xh, lfw, lfb, out);

    if (out_size >= TOK*EE + TOK)
        mask_k<<<TOK/256, 256>>>(seq, out + (long long)TOK*EE);
}

// round 17
// speedup vs baseline: 5.4087x; 1.0058x over previous
#include <cuda_runtime.h>
#include <cuda_fp16.h>
#include <math.h>
#include <stdint.h>

// Fixed shapes for BaseEncoder_68702296867023
#define BB 16
#define SS 512
#define EE 512
#define HH 8
#define FFD 2048
#define LL 6
#define DH 64
#define TOK (BB*SS)              // 8192 tokens
#define NZ (BB*HH)               // 128 attention batches
#define SSS ((long long)SS*SS)

// ---------------------------------------------------------------------------
// Scratch (device globals; no allocations allowed)
// ---------------------------------------------------------------------------
__device__ __half g_xh[TOK*EE];               // activations (half)     8 MB
__device__ __half g_qkvh[TOK*3*EE];           // qkv (half)            24 MB
__device__ __half g_biasmh[NZ*SS*SS];         // rel-dist bias+mask    67 MB
__device__ __half g_ctxh[TOK*EE];             // attention ctx (half)   8 MB
__device__ __half g_ffh[TOK*FFD];             // FF hidden (half)      32 MB
__device__ float  g_part[4*TOK*EE];           // split-K partials      64 MB
__device__ __half g_wh[18874368];             // fp16 weights          38 MB

#define N_IP (LL*3*EE*EE)
#define N_OW (LL*EE*EE)
#define N_F1 (LL*FFD*EE)
#define N_F2 (LL*EE*FFD)

// ---------------------------------------------------------------------------
__device__ __forceinline__ void mma16(float c[4], const uint32_t a[4],
                                      uint32_t b0, uint32_t b1)
{
    asm volatile(
        "mma.sync.aligned.m16n8k16.row.col.f32.f16.f16.f32 "
        "{%0,%1,%2,%3},{%4,%5,%6,%7},{%8,%9},{%0,%1,%2,%3};\n"
        : "+f"(c[0]), "+f"(c[1]), "+f"(c[2]), "+f"(c[3])
        : "r"(a[0]), "r"(a[1]), "r"(a[2]), "r"(a[3]), "r"(b0), "r"(b1));
}

__device__ __forceinline__ void cpa16(uint32_t s, const void* g)
{
    asm volatile("cp.async.cg.shared.global [%0], [%1], 16;\n" :: "r"(s), "l"(g));
}
#define CP_COMMIT() asm volatile("cp.async.commit_group;\n")
#define CP_WAIT(N)  asm volatile("cp.async.wait_group %0;\n" :: "n"(N))

#define LDSM4(r0,r1,r2,r3,addr) \
    asm volatile("ldmatrix.sync.aligned.m8n8.x4.shared.b16 {%0,%1,%2,%3}, [%4];" \
                 : "=r"(r0),"=r"(r1),"=r"(r2),"=r"(r3) : "r"(addr))
#define LDSM2(r0,r1,addr) \
    asm volatile("ldmatrix.sync.aligned.m8n8.x2.shared.b16 {%0,%1}, [%2];" \
                 : "=r"(r0),"=r"(r1) : "r"(addr))
#define LDSM2T(r0,r1,addr) \
    asm volatile("ldmatrix.sync.aligned.m8n8.x2.trans.shared.b16 {%0,%1}, [%2];" \
                 : "=r"(r0),"=r"(r1) : "r"(addr))

// ---------------------------------------------------------------------------
// fp16 tensor-core GEMM (m16n8k16), 128x128 tile, BK=32, 4-stage cp.async.
// 512 threads / 16 warps, 32x32 warp tiles. (R13-proven core, unchanged.)
//   Split-K via blockIdx.z. EPI: 0 +bias, 1 +bias+gelu, 3 raw partial.
// ---------------------------------------------------------------------------
template<typename OutT, int EPI>
__global__ void __launch_bounds__(512)
hgemm(const __half* __restrict__ A, const __half* __restrict__ B,
      const float* __restrict__ bias, OutT* __restrict__ C,
      int K, int lda, int ldb, int ldc, long long pstride)
{
    extern __shared__ __align__(16) char dsm[];
    const uint32_t sb = (uint32_t)__cvta_generic_to_shared(dsm);
    const int tid = threadIdx.x;
    const int m0 = blockIdx.y * 128, n0 = blockIdx.x * 128;
    const int z = blockIdx.z;
    A += (long long)z * K;
    B += (long long)z * K;
    C += (long long)z * pstride;
    const int warp = tid >> 5, lane = tid & 31;
    const int g = lane >> 2, tg = lane & 3;
    const int wx = warp & 3, wy = warp >> 2;      // 4x4 grid: 32x32 warp tiles
    const int wm0 = wy * 32, wn0 = wx * 32;
    const int lr = tid >> 2, lc = (tid & 3) * 8;  // loader: one cpa16/thread

    const uint32_t aoff = (uint32_t)(((wm0 + ((lane>>3)&1)*8 + (lane&7)) * 40
                                      + (lane>>4)*8) * 2);
    const uint32_t boff = (uint32_t)(10240 + ((wn0 + (lane&7)) * 40
                                      + ((lane>>3)&1)*8) * 2);

    auto prefetch = [&](int t) {
        const int k0 = t * 32;
        const uint32_t st = sb + (uint32_t)((t % 4) * 20480);
        cpa16(st + (uint32_t)(lr*80 + lc*2),
              &A[(long long)(m0 + lr) * lda + k0 + lc]);
        cpa16(st + (uint32_t)(10240 + lr*80 + lc*2),
              &B[(long long)(n0 + lr) * ldb + k0 + lc]);
    };

    float acc[2][4][4];
#pragma unroll
    for (int i = 0; i < 2; i++)
#pragma unroll
        for (int j = 0; j < 4; j++)
#pragma unroll
            for (int c = 0; c < 4; c++) acc[i][j][c] = 0.f;

    const int nb = K / 32;
    prefetch(0); CP_COMMIT();
    prefetch(1); CP_COMMIT();
    prefetch(2); CP_COMMIT();

    for (int t = 0; t < nb; t++) {
        CP_WAIT(2);
        __syncthreads();
        if (t + 3 < nb) prefetch(t + 3);
        CP_COMMIT();
        const uint32_t st = sb + (uint32_t)((t % 4) * 20480);
#pragma unroll
        for (int kb = 0; kb < 32; kb += 16) {
            uint32_t a[2][4], bf[4][2];
#pragma unroll
            for (int i = 0; i < 2; i++)
                LDSM4(a[i][0], a[i][1], a[i][2], a[i][3],
                      st + aoff + (uint32_t)(i*1280 + kb*2));
#pragma unroll
            for (int j = 0; j < 4; j++)
                LDSM2(bf[j][0], bf[j][1],
                      st + boff + (uint32_t)(j*640 + kb*2));
#pragma unroll
            for (int i = 0; i < 2; i++)
#pragma unroll
                for (int j = 0; j < 4; j++)
                    mma16(acc[i][j], a[i], bf[j][0], bf[j][1]);
        }
    }

    // epilogue
#pragma unroll
    for (int i = 0; i < 2; i++) {
#pragma unroll
        for (int j = 0; j < 4; j++) {
#pragma unroll
            for (int hh = 0; hh < 2; hh++) {
                const long long r = m0 + wm0 + i*16 + g + hh*8;
                const int c = n0 + wn0 + j*8 + 2*tg;
                float vx = acc[i][j][hh*2 + 0];
                float vy = acc[i][j][hh*2 + 1];
                if (EPI != 3) { vx += bias[c]; vy += bias[c+1]; }
                if (EPI == 1) {
                    vx = 0.5f*vx*(1.f + erff(vx*0.70710678118654752f));
                    vy = 0.5f*vy*(1.f + erff(vy*0.70710678118654752f));
                }
                if (sizeof(OutT) == 2) {
                    *(__half2*)&((__half*)C)[r*ldc + c] = __floats2half2_rn(vx, vy);
                } else {
                    float2 v2; v2.x = vx; v2.y = vy;
                    *(float2*)&((float*)C)[r*ldc + c] = v2;
                }
            }
        }
    }
}

// ---------------------------------------------------------------------------
// Fused flash attention v2 (R14-proven, unchanged).
// ---------------------------------------------------------------------------
__global__ void __launch_bounds__(256)
flash_h(const __half* __restrict__ qkvh, const __half* __restrict__ biasmh,
        __half* __restrict__ ctxh)
{
    extern __shared__ __align__(16) char dsm[];
    const uint32_t sbase = (uint32_t)__cvta_generic_to_shared(dsm);

    const int tid = threadIdx.x, lane = tid & 31, w = tid >> 5;
    const int g = lane >> 2, tg = lane & 3;
    const int qt = blockIdx.x;          // 0..3
    const int z  = blockIdx.y;          // b*H + h
    const int b  = z >> 3, h = z & 7;
    const int q0 = qt * 128;
    const int qr = w * 16;

    __half* wrh = (__half*)(dsm + 73728 + w * 4352);
    const uint32_t wr_u32 = (uint32_t)__cvta_generic_to_shared(wrh);
    const int vrow = (lane & 7) + ((lane >> 3) & 1) * 8;

    const __half* qh = qkvh + (long long)(b * SS) * 1536 + h * 64;
    const __half* kh = qh + 512;
    const __half* vh = qh + 1024;

    auto kv_prefetch = [&](int kt) {
        const uint32_t st = sbase + (uint32_t)((kt & 1) * 36864);
#pragma unroll
        for (int i = 0; i < 8; i++) {
            const int id = tid + (i & 3) * 256;
            const int r = id >> 3, c = id & 7;
            if (i < 4)
                cpa16(st + (uint32_t)(r*144 + c*16),
                      &kh[(long long)(kt*128 + r) * 1536 + c*8]);
            else
                cpa16(st + 18432u + (uint32_t)(r*144 + c*16),
                      &vh[(long long)(kt*128 + r) * 1536 + c*8]);
        }
    };

    kv_prefetch(0); CP_COMMIT();

    {
        __half* Qs = (__half*)(dsm + 73728);
#pragma unroll
        for (int i = 0; i < 4; i++) {
            const int id = tid + i * 256;
            const int r = id >> 3, c8 = (id & 7) * 8;
            *(float4*)&Qs[r * 72 + c8] =
                *(const float4*)&qh[(long long)(q0 + r) * 1536 + c8];
        }
        __syncthreads();
    }
    uint32_t qa[4][4];
    {
        const __half* Qs = (const __half*)(dsm + 73728);
#pragma unroll
        for (int ks = 0; ks < 4; ks++) {
            const int r0 = (qr + g) * 72, r1 = (qr + g + 8) * 72;
            qa[ks][0] = *(const uint32_t*)&Qs[r0 + ks*16 + 2*tg];
            qa[ks][1] = *(const uint32_t*)&Qs[r1 + ks*16 + 2*tg];
            qa[ks][2] = *(const uint32_t*)&Qs[r0 + ks*16 + 2*tg + 8];
            qa[ks][3] = *(const uint32_t*)&Qs[r1 + ks*16 + 2*tg + 8];
        }
    }

    float mrun[2] = {-INFINITY, -INFINITY};
    float lrun[2] = {0.f, 0.f};
    float oacc[8][4];
#pragma unroll
    for (int n = 0; n < 8; n++)
#pragma unroll
        for (int c = 0; c < 4; c++) oacc[n][c] = 0.f;

    const __half* Bz = biasmh + (long long)z * SSS + (long long)(q0 + qr) * SS;

    for (int kt = 0; kt < 4; kt++) {
        CP_WAIT(0);
        __syncthreads();

#pragma unroll
        for (int p = 0; p < 8; p++) {
            const int c = p * 32 + lane;
            const int r = c >> 4, cc8 = (c & 15) * 8;
            cpa16(wr_u32 + (uint32_t)((r * 136 + cc8) * 2),
                  &Bz[(long long)r * SS + kt * 128 + cc8]);
        }
        CP_COMMIT();
        if (kt + 1 < 4) kv_prefetch(kt + 1);
        CP_COMMIT();

        const __half* KsS = (const __half*)(dsm + (kt & 1) * 36864);
        const uint32_t Vb = sbase + (uint32_t)((kt & 1) * 36864 + 18432);

        float sacc[16][4];
#pragma unroll
        for (int n = 0; n < 16; n++)
#pragma unroll
            for (int c = 0; c < 4; c++) sacc[n][c] = 0.f;
#pragma unroll
        for (int ks = 0; ks < 4; ks++) {
#pragma unroll
            for (int n = 0; n < 16; n++) {
                const int rn = (n*8 + g) * 72;
                const uint32_t b0 = *(const uint32_t*)&KsS[rn + ks*16 + 2*tg];
                const uint32_t b1 = *(const uint32_t*)&KsS[rn + ks*16 + 2*tg + 8];
                mma16(sacc[n], qa[ks], b0, b1);
            }
        }

        CP_WAIT(1);
        __syncwarp();
        float tmax0 = -INFINITY, tmax1 = -INFINITY;
#pragma unroll
        for (int n = 0; n < 16; n++) {
            const float2 bv0 = __half22float2(*(__half2*)&wrh[ g      * 136 + n*8 + 2*tg]);
            const float2 bv1 = __half22float2(*(__half2*)&wrh[(g + 8) * 136 + n*8 + 2*tg]);
            sacc[n][0] = sacc[n][0]*0.125f + bv0.x;
            sacc[n][1] = sacc[n][1]*0.125f + bv0.y;
            sacc[n][2] = sacc[n][2]*0.125f + bv1.x;
            sacc[n][3] = sacc[n][3]*0.125f + bv1.y;
            tmax0 = fmaxf(tmax0, fmaxf(sacc[n][0], sacc[n][1]));
            tmax1 = fmaxf(tmax1, fmaxf(sacc[n][2], sacc[n][3]));
        }
        tmax0 = fmaxf(tmax0, __shfl_xor_sync(0xffffffffu, tmax0, 1));
        tmax0 = fmaxf(tmax0, __shfl_xor_sync(0xffffffffu, tmax0, 2));
        tmax1 = fmaxf(tmax1, __shfl_xor_sync(0xffffffffu, tmax1, 1));
        tmax1 = fmaxf(tmax1, __shfl_xor_sync(0xffffffffu, tmax1, 2));

        const float mnew0 = fmaxf(mrun[0], tmax0);
        const float mnew1 = fmaxf(mrun[1], tmax1);
        const float scl0 = __expf(mrun[0] - mnew0);
        const float scl1 = __expf(mrun[1] - mnew1);
        float ts0 = 0.f, ts1 = 0.f;
#pragma unroll
        for (int n = 0; n < 16; n++) {
            sacc[n][0] = __expf(sacc[n][0] - mnew0);
            sacc[n][1] = __expf(sacc[n][1] - mnew0);
            sacc[n][2] = __expf(sacc[n][2] - mnew1);
            sacc[n][3] = __expf(sacc[n][3] - mnew1);
            ts0 += sacc[n][0] + sacc[n][1];
            ts1 += sacc[n][2] + sacc[n][3];
        }
        ts0 += __shfl_xor_sync(0xffffffffu, ts0, 1);
        ts0 += __shfl_xor_sync(0xffffffffu, ts0, 2);
        ts1 += __shfl_xor_sync(0xffffffffu, ts1, 1);
        ts1 += __shfl_xor_sync(0xffffffffu, ts1, 2);
        lrun[0] = lrun[0] * scl0 + ts0;
        lrun[1] = lrun[1] * scl1 + ts1;
        mrun[0] = mnew0; mrun[1] = mnew1;
#pragma unroll
        for (int n = 0; n < 8; n++) {
            oacc[n][0] *= scl0; oacc[n][1] *= scl0;
            oacc[n][2] *= scl1; oacc[n][3] *= scl1;
        }

        __syncwarp();
#pragma unroll
        for (int n = 0; n < 16; n++) {
            *(__half2*)&wrh[ g      * 136 + n*8 + 2*tg] = __floats2half2_rn(sacc[n][0], sacc[n][1]);
            *(__half2*)&wrh[(g + 8) * 136 + n*8 + 2*tg] = __floats2half2_rn(sacc[n][2], sacc[n][3]);
        }
        __syncwarp();
#pragma unroll
        for (int ks = 0; ks < 8; ks++) {
            uint32_t pa[4];
            pa[0] = *(const uint32_t*)&wrh[ g      * 136 + ks*16 + 2*tg];
            pa[1] = *(const uint32_t*)&wrh[(g + 8) * 136 + ks*16 + 2*tg];
            pa[2] = *(const uint32_t*)&wrh[ g      * 136 + ks*16 + 2*tg + 8];
            pa[3] = *(const uint32_t*)&wrh[(g + 8) * 136 + ks*16 + 2*tg + 8];
            const uint32_t vr = Vb + (uint32_t)((ks*16 + vrow) * 144);
#pragma unroll
            for (int n = 0; n < 8; n++) {
                uint32_t b0, b1;
                LDSM2T(b0, b1, vr + (uint32_t)(n * 16));
                mma16(oacc[n], pa, b0, b1);
            }
        }
    }

    const float inv0 = 1.f / lrun[0];
    const float inv1 = 1.f / lrun[1];
    const int t0 = b * SS + q0 + qr;
#pragma unroll
    for (int n = 0; n < 8; n++) {
        const int col = h * 64 + n * 8 + 2 * tg;
        *(__half2*)&ctxh[(long long)(t0 + g    ) * EE + col] =
            __floats2half2_rn(oacc[n][0] * inv0, oacc[n][1] * inv0);
        *(__half2*)&ctxh[(long long)(t0 + g + 8) * EE + col] =
            __floats2half2_rn(oacc[n][2] * inv1, oacc[n][3] * inv1);
    }
}

// ---------------------------------------------------------------------------
__global__ void convw4_k(const float* __restrict__ s0, const float* __restrict__ s1,
                         const float* __restrict__ s2, const float* __restrict__ s3,
                         __half* __restrict__ dst)
{
    const int i = blockIdx.x * blockDim.x + threadIdx.x;
    float v;
    if      (i < N_IP)                  v = s0[i];
    else if (i < N_IP + N_OW)           v = s1[i - N_IP];
    else if (i < N_IP + N_OW + N_F1)    v = s2[i - N_IP - N_OW];
    else                                v = s3[i - N_IP - N_OW - N_F1];
    dst[i] = __float2half_rn(v);
}

__global__ void embed_k(const int* __restrict__ seq, const float* __restrict__ emb,
                        __half* __restrict__ xh)
{
    int i = blockIdx.x * blockDim.x + threadIdx.x;
    int e = i & (EE-1);
    int t = i >> 9;
    xh[i] = __float2half_rn(emb[seq[t]*EE + e] * 22.627416997969522f);
}

// biasm (half), 4 k-values per thread: int4 squares load, L1-hot dist gathers,
// 8B vectorized stores.
__global__ void bias_k(const int* __restrict__ squares, const int* __restrict__ seq,
                       const float* __restrict__ dist, __half* __restrict__ bias)
{
    const long long i = (long long)blockIdx.x * blockDim.x + threadIdx.x; // < NZ*SSS/4
    const int kb = (int)(i & 127);          // k block of 4 (SS/4 = 128)
    long long r = i >> 7;
    const int q = (int)(r & (SS-1)); r >>= 9;
    const int h = (int)(r & (HH-1));
    const int b = (int)(r >> 3);
    const int4 sq = *(const int4*)&squares[((long long)(b*SS + q) << 9) + kb*4];
    const int* seqb = seq + b*SS + kb*4;
    float v0 = dist[sq.x*HH + h] + (seqb[0] == 0 ? -60000.f : 0.f);
    float v1 = dist[sq.y*HH + h] + (seqb[1] == 0 ? -60000.f : 0.f);
    float v2 = dist[sq.z*HH + h] + (seqb[2] == 0 ? -60000.f : 0.f);
    float v3 = dist[sq.w*HH + h] + (seqb[3] == 0 ? -60000.f : 0.f);
    __half2* out = (__half2*)&bias[i * 4];
    out[0] = __floats2half2_rn(v0, v1);
    out[1] = __floats2half2_rn(v2, v3);
}

// ---------------------------------------------------------------------------
__device__ __forceinline__ void block_ln_stats(float v, float& mean, float& var)
{
    float s = v, q = v*v;
#pragma unroll
    for (int o = 16; o > 0; o >>= 1) {
        s += __shfl_xor_sync(0xffffffffu, s, o);
        q += __shfl_xor_sync(0xffffffffu, q, o);
    }
    __shared__ float shs[16], shq[16];
    const int wid = threadIdx.x >> 5, lane = threadIdx.x & 31;
    if (lane == 0) { shs[wid] = s; shq[wid] = q; }
    __syncthreads();
    if (threadIdx.x < 32) {
        float ss = (lane < 16) ? shs[lane] : 0.f;
        float qq = (lane < 16) ? shq[lane] : 0.f;
#pragma unroll
        for (int o = 8; o > 0; o >>= 1) {
            ss += __shfl_xor_sync(0xffffffffu, ss, o);
            qq += __shfl_xor_sync(0xffffffffu, qq, o);
        }
        if (lane == 0) { shs[0] = ss; shq[0] = qq; }
    }
    __syncthreads();
    mean = shs[0] * (1.f/EE);
    var  = shq[0] * (1.f/EE) - mean*mean;
}

// x = LN(x + sum_p part[p] + bias)  — split-K reduction fused into LN
template<int P>
__global__ void add_ln_red_k(__half* __restrict__ xh, const float* __restrict__ part,
                             const float* __restrict__ bias,
                             const float* __restrict__ w, const float* __restrict__ b)
{
    const long long base = (long long)blockIdx.x * EE;
    const int t = threadIdx.x;
    float v = __half2float(xh[base + t]) + bias[t];
#pragma unroll
    for (int p = 0; p < P; p++)
        v += part[(long long)p * (TOK*EE) + base + t];
    float mean, var;
    block_ln_stats(v, mean, var);
    xh[base + t] = __float2half_rn((v - mean) * rsqrtf(var + 1e-5f) * w[t] + b[t]);
}

__global__ void ln_final_k(const __half* __restrict__ xh, const float* __restrict__ w,
                           const float* __restrict__ b, float* __restrict__ out)
{
    const int row = blockIdx.x;
    const int bi = row >> 9, si = row & (SS-1);
    const int t = threadIdx.x;
    float v = __half2float(xh[(long long)row*EE + t]);
    float mean, var;
    block_ln_stats(v, mean, var);
    out[((long long)si*BB + bi)*EE + t] = (v - mean) * rsqrtf(var + 1e-5f) * w[t] + b[t];
}

__global__ void mask_k(const int* __restrict__ seq, float* __restrict__ out)
{
    int i = blockIdx.x * blockDim.x + threadIdx.x;
    out[i] = (seq[i] == 0) ? 1.f : 0.f;
}

// ---------------------------------------------------------------------------
extern "C" void kernel_launch(void* const* d_in, const int* in_sizes, int n_in,
                              void* d_out, int out_size)
{
    const int*   seq     = (const int*)  d_in[0];
    const int*   squares = (const int*)  d_in[1];
    const float* tok_emb = (const float*)d_in[2];
    const float* dist    = (const float*)d_in[3];
    const float* ipw     = (const float*)d_in[4];
    const float* ipb     = (const float*)d_in[5];
    const float* ow      = (const float*)d_in[6];
    const float* ob      = (const float*)d_in[7];
    const float* f1w     = (const float*)d_in[8];
    const float* f1b     = (const float*)d_in[9];
    const float* f2w     = (const float*)d_in[10];
    const float* f2b     = (const float*)d_in[11];
    const float* l1w     = (const float*)d_in[12];
    const float* l1b     = (const float*)d_in[13];
    const float* l2w     = (const float*)d_in[14];
    const float* l2b     = (const float*)d_in[15];
    const float* lfw     = (const float*)d_in[16];
    const float* lfb     = (const float*)d_in[17];
    float* out = (float*)d_out;

    __half *xh,*qkvh,*bmh,*ctxh,*ffh,*wh;
    float *part;
    cudaGetSymbolAddress((void**)&xh,   g_xh);
    cudaGetSymbolAddress((void**)&qkvh, g_qkvh);
    cudaGetSymbolAddress((void**)&bmh,  g_biasmh);
    cudaGetSymbolAddress((void**)&ctxh, g_ctxh);
    cudaGetSymbolAddress((void**)&ffh,  g_ffh);
    cudaGetSymbolAddress((void**)&part, g_part);
    cudaGetSymbolAddress((void**)&wh,   g_wh);

    const int GEMM_SMEM  = 4 * 20480;     // 81920
    const int FLASH_SMEM = 108544;
    cudaFuncSetAttribute(hgemm<__half,0>, cudaFuncAttributeMaxDynamicSharedMemorySize, GEMM_SMEM);
    cudaFuncSetAttribute(hgemm<__half,1>, cudaFuncAttributeMaxDynamicSharedMemorySize, GEMM_SMEM);
    cudaFuncSetAttribute(hgemm<float,3>,  cudaFuncAttributeMaxDynamicSharedMemorySize, GEMM_SMEM);
    cudaFuncSetAttribute(flash_h,         cudaFuncAttributeMaxDynamicSharedMemorySize, FLASH_SMEM);

    __half* iph = wh;
    __half* owh = iph + N_IP;
    __half* f1h = owh + N_OW;
    __half* f2h = f1h + N_F1;
    convw4_k<<<(N_IP+N_OW+N_F1+N_F2)/256, 256>>>(ipw, ow, f1w, f2w, wh);

    embed_k<<<(TOK*EE)/256, 256>>>(seq, tok_emb, xh);
    bias_k<<<(int)(((long long)NZ*SSS/4)/256), 256>>>(squares, seq, dist, bmh);

    const long long PSTR = (long long)TOK*EE;

    for (int l = 0; l < LL; l++) {
        // qkv = x @ in_proj_w^T + b      [8192,1536] K=512
        hgemm<__half,0><<<dim3(12,64,1), 512, GEMM_SMEM>>>(
            xh, iph + (long long)l*3*EE*EE, ipb + l*3*EE, qkvh, EE, EE, EE, 3*EE, 0);

        // fused attention: ctx = softmax(0.125*QK^T + biasm) @ V
        flash_h<<<dim3(4, NZ), 256, FLASH_SMEM>>>(qkvh, bmh, ctxh);

        // attn partials: ctx @ out_w^T, split-K=2 (K=256 each)
        hgemm<float,3><<<dim3(4,64,2), 512, GEMM_SMEM>>>(
            ctxh, owh + (long long)l*EE*EE, nullptr, part, 256, EE, EE, EE, PSTR);

        // x = LN(x + p0 + p1 + ob)
        add_ln_red_k<2><<<TOK, EE>>>(xh, part, ob + l*EE, l1w + l*EE, l1b + l*EE);

        // h = gelu(x @ ff1_w^T + b)      [8192,2048] K=512
        hgemm<__half,1><<<dim3(16,64,1), 512, GEMM_SMEM>>>(
            xh, f1h + (long long)l*FFD*EE, f1b + l*FFD, ffh, EE, EE, EE, FFD, 0);

        // ff partials: h @ ff2_w^T, split-K=4 (K=512 each)
        hgemm<float,3><<<dim3(4,64,4), 512, GEMM_SMEM>>>(
            ffh, f2h + (long long)l*EE*FFD, nullptr, part, 512, FFD, FFD, EE, PSTR);

        // x = LN(x + p0+p1+p2+p3 + f2b)
        add_ln_red_k<4><<<TOK, EE>>>(xh, part, f2b + l*EE, l2w + l*EE, l2b + l*EE);
    }

    ln_final_k<<<TOK, EE>>>(xh, lfw, lfb, out);

    if (out_size >= TOK*EE + TOK)
        mask_k<<<TOK/256, 256>>>(seq, out + (long long)TOK*EE);
}